// round 9
// baseline (speedup 1.0000x reference)
#include <cuda_runtime.h>
#include <cuda_fp16.h>
#include <math.h>

#define D    128
#define DOUT 40
#define NMAX 100000
#define EMAX 1600000

typedef unsigned long long ull;

static inline int cdiv(int a, int b) { return (a + b - 1) / b; }

// ---------------- scratch (static device globals; no allocation) ----------------
__device__ __align__(16) __half g_xw [(size_t)NMAX * D];    // fp16 gather operand
__device__ __align__(16) float  g_h  [(size_t)NMAX * D];    // fp32 hidden activations
__device__ __align__(16) __half g_xw2[(size_t)NMAX * DOUT]; // fp16 final-layer operand
__device__ float g_deg [NMAX];
__device__ float g_dinv[NMAX];
__device__ int   g_idx [2 * EMAX];
__device__ int   g_is64;
// CSR
__device__ int   g_cnt [NMAX];
__device__ int   g_rowptr[NMAX + 1];
__device__ int   g_fill[NMAX];
__device__ int   g_bsum[256];
__device__ int   g_boff[256];
__device__ int   g_esrc [EMAX];
__device__ float g_enorm[EMAX];
// BN stats, double-buffered (layer 0 -> idx 0, layer 1 -> idx 1)
__device__ __align__(16) float g_bnsum  [2 * 128];
__device__ __align__(16) float g_bnsumsq[2 * 128];

// ---------------- packed f32x2 helpers ----------------
__device__ __forceinline__ ull fma2(ull a, ull b, ull c) {
    ull d;
    asm("fma.rn.f32x2 %0, %1, %2, %3;" : "=l"(d) : "l"(a), "l"(b), "l"(c));
    return d;
}
__device__ __forceinline__ ull splat2(float x) {
    ull d;
    asm("mov.b64 %0, {%1, %1};" : "=l"(d) : "f"(x));
    return d;
}

// ---------------- index dtype detect ----------------
__global__ void detect_kernel(const unsigned* __restrict__ w, int twoE) {
    if (threadIdx.x == 0 && blockIdx.x == 0) {
        int nchk = twoE < 256 ? twoE : 256;
        int is64 = 1;
        for (int i = 0; i < nchk; i++)
            if (w[2 * i + 1] != 0u) { is64 = 0; break; }
        g_is64 = is64;
    }
}

// ---------------- convert + degree/histogram (fused) ----------------
__global__ void convert_deg_kernel(const void* __restrict__ ei,
                                   const float* __restrict__ ew, int E) {
    int i = blockIdx.x * blockDim.x + threadIdx.x;
    int twoE = 2 * E;
    if (i < twoE) {
        int v;
        if (g_is64) v = (int)((const long long*)ei)[i];
        else        v = ((const int*)ei)[i];
        g_idx[i] = v;
        if (i >= E) {
            atomicAdd(&g_deg[v], ew[i - E]);
            atomicAdd(&g_cnt[v], 1);
        }
    }
}

// ---------------- exclusive scan of g_cnt -> g_rowptr (3-pass) ----------------
__global__ void scan1(int n) {
    __shared__ int sm[512];
    int i = blockIdx.x * 512 + threadIdx.x;
    int v = (i < n) ? g_cnt[i] : 0;
    sm[threadIdx.x] = v;
    __syncthreads();
    #pragma unroll
    for (int o = 1; o < 512; o <<= 1) {
        int t = (threadIdx.x >= o) ? sm[threadIdx.x - o] : 0;
        __syncthreads();
        sm[threadIdx.x] += t;
        __syncthreads();
    }
    if (i < n) g_rowptr[i] = sm[threadIdx.x] - v;
    if (threadIdx.x == 511) g_bsum[blockIdx.x] = sm[511];
}

__global__ void scan2(int nb) {
    __shared__ int sm[256];
    int v = (threadIdx.x < nb) ? g_bsum[threadIdx.x] : 0;
    sm[threadIdx.x] = v;
    __syncthreads();
    #pragma unroll
    for (int o = 1; o < 256; o <<= 1) {
        int t = (threadIdx.x >= o) ? sm[threadIdx.x - o] : 0;
        __syncthreads();
        sm[threadIdx.x] += t;
        __syncthreads();
    }
    if (threadIdx.x < nb) g_boff[threadIdx.x] = sm[threadIdx.x] - v;
}

__global__ void scan3(int n, int E) {
    int i = blockIdx.x * blockDim.x + threadIdx.x;
    if (i < n) {
        g_rowptr[i] += g_boff[i >> 9];
        g_dinv[i] = rsqrtf(g_deg[i] + 1.0f);
    }
    if (i == 0) g_rowptr[n] = E;
}

// ---------------- CSR fill ----------------
__global__ void fill_kernel(const float* __restrict__ ew, int E) {
    int e = blockIdx.x * blockDim.x + threadIdx.x;
    if (e < E) {
        int s = g_idx[e];
        int d = g_idx[E + e];
        int pos = g_rowptr[d] + atomicAdd(&g_fill[d], 1);
        g_esrc[pos]  = s;
        g_enorm[pos] = g_dinv[s] * ew[e] * g_dinv[d];
    }
}

// ---------------- GEMM 128x128: fp32 in, optional BN prologue, fp16 out ----------
#define GEMM_SMEM ((128 * 128 + 128 * 132 + 256) * 4)

template <bool FUSE_BN>
__global__ void __launch_bounds__(256) gemm128(const float* __restrict__ A,
                                               const float* __restrict__ W,
                                               __half* __restrict__ C, int n,
                                               const float* __restrict__ g,
                                               const float* __restrict__ be,
                                               int statIdx, float fn) {
    extern __shared__ float smem[];
    float* sW  = smem;                          // [128][128]
    float* sX  = smem + 128 * 128;              // [128][132] padded
    float* sSc = smem + 128 * 128 + 128 * 132;  // [128]
    float* sSh = sSc + 128;                     // [128]

    int tid = threadIdx.x;
    int row0 = blockIdx.x * 128;

    if (FUSE_BN) {
        if (tid < 128) {
            float mean = g_bnsum[statIdx * 128 + tid] / fn;
            float var  = g_bnsumsq[statIdx * 128 + tid] / fn - mean * mean;
            float sc   = g[tid] * rsqrtf(var + 1e-5f);
            sSc[tid] = sc;
            sSh[tid] = be[tid] - mean * sc;
        }
        __syncthreads();
    }

    const float4* W4  = (const float4*)W;
    float4*       sW4 = (float4*)sW;
    #pragma unroll
    for (int i = tid; i < 4096; i += 256) sW4[i] = W4[i];

    const float4* A4 = (const float4*)A + (size_t)row0 * 32;
    float4* sX4 = (float4*)sX;
    #pragma unroll
    for (int i = tid; i < 4096; i += 256) {
        int r = i >> 5, c4 = i & 31;
        float4 v = make_float4(0.f, 0.f, 0.f, 0.f);
        if (row0 + r < n) v = A4[i];
        if (FUSE_BN) {
            float4 sc = ((const float4*)sSc)[c4];
            float4 sh = ((const float4*)sSh)[c4];
            v.x = fmaxf(fmaf(v.x, sc.x, sh.x), 0.f);
            v.y = fmaxf(fmaf(v.y, sc.y, sh.y), 0.f);
            v.z = fmaxf(fmaf(v.z, sc.z, sh.z), 0.f);
            v.w = fmaxf(fmaf(v.w, sc.w, sh.w), 0.f);
        }
        sX4[r * 33 + c4] = v;
    }
    __syncthreads();

    int tx = tid & 15, ty = tid >> 4;
    ull acc[8][4];
    #pragma unroll
    for (int j = 0; j < 8; j++)
        #pragma unroll
        for (int p = 0; p < 4; p++) acc[j][p] = splat2(0.f);

    const ulonglong2* sW2 = (const ulonglong2*)sW;
    #pragma unroll 2
    for (int k = 0; k < 128; k++) {
        ulonglong2 wa = sW2[k * 32 + 2 * tx];
        ulonglong2 wb = sW2[k * 32 + 2 * tx + 1];
        #pragma unroll
        for (int j = 0; j < 8; j++) {
            int row = (j < 4) ? (ty * 4 + j) : (64 + ty * 4 + (j - 4));
            ull xi = splat2(sX[row * 132 + k]);
            acc[j][0] = fma2(xi, wa.x, acc[j][0]);
            acc[j][1] = fma2(xi, wa.y, acc[j][1]);
            acc[j][2] = fma2(xi, wb.x, acc[j][2]);
            acc[j][3] = fma2(xi, wb.y, acc[j][3]);
        }
    }

    #pragma unroll
    for (int j = 0; j < 8; j++) {
        int r = row0 + ((j < 4) ? (ty * 4 + j) : (64 + ty * 4 + (j - 4)));
        if (r < n) {
            uint4 o;
            union { ull u; float2 f; } cv;
            __half2 hh;
            cv.u = acc[j][0]; hh = __floats2half2_rn(cv.f.x, cv.f.y);
            o.x = *reinterpret_cast<unsigned*>(&hh);
            cv.u = acc[j][1]; hh = __floats2half2_rn(cv.f.x, cv.f.y);
            o.y = *reinterpret_cast<unsigned*>(&hh);
            cv.u = acc[j][2]; hh = __floats2half2_rn(cv.f.x, cv.f.y);
            o.z = *reinterpret_cast<unsigned*>(&hh);
            cv.u = acc[j][3]; hh = __floats2half2_rn(cv.f.x, cv.f.y);
            o.w = *reinterpret_cast<unsigned*>(&hh);
            ((uint4*)(C + (size_t)r * D))[tx] = o;
        }
    }
}

// ---------------- GEMM 128->40 with BN prologue (fp32 in, fp16 out) -------------
__global__ void gemm40(const float* __restrict__ A, const float* __restrict__ W,
                       __half* __restrict__ C, int n,
                       const float* __restrict__ g, const float* __restrict__ be,
                       int statIdx, float fn) {
    __shared__ float sW[128 * 40];
    __shared__ float sX[32 * 132];
    __shared__ float sSc[128], sSh[128];

    int tid = threadIdx.x;
    int row0 = blockIdx.x * 32;

    if (tid < 128) {
        float mean = g_bnsum[statIdx * 128 + tid] / fn;
        float var  = g_bnsumsq[statIdx * 128 + tid] / fn - mean * mean;
        float sc   = g[tid] * rsqrtf(var + 1e-5f);
        sSc[tid] = sc;
        sSh[tid] = be[tid] - mean * sc;
    }
    __syncthreads();

    const float4* W4  = (const float4*)W;
    float4*       sW4 = (float4*)sW;
    #pragma unroll
    for (int i = tid; i < 1280; i += 256) sW4[i] = W4[i];

    const float4* A4 = (const float4*)A + (size_t)row0 * 32;
    float4* sX4 = (float4*)sX;
    #pragma unroll
    for (int i = tid; i < 1024; i += 256) {
        int r = i >> 5, c4 = i & 31;
        float4 v = make_float4(0.f, 0.f, 0.f, 0.f);
        if (row0 + r < n) {
            v = A4[i];
            float4 sc = ((const float4*)sSc)[c4];
            float4 sh = ((const float4*)sSh)[c4];
            v.x = fmaxf(fmaf(v.x, sc.x, sh.x), 0.f);
            v.y = fmaxf(fmaf(v.y, sc.y, sh.y), 0.f);
            v.z = fmaxf(fmaf(v.z, sc.z, sh.z), 0.f);
            v.w = fmaxf(fmaf(v.w, sc.w, sh.w), 0.f);
        }
        sX4[r * 33 + c4] = v;
    }
    __syncthreads();

    int tx = tid & 7, rt = tid >> 3;
    float acc[5] = {0.f, 0.f, 0.f, 0.f, 0.f};
    #pragma unroll 4
    for (int k = 0; k < 128; k++) {
        float xv = sX[rt * 132 + k];
        #pragma unroll
        for (int j = 0; j < 5; j++)
            acc[j] = fmaf(xv, sW[k * 40 + tx * 5 + j], acc[j]);
    }
    int row = row0 + rt;
    if (row < n) {
        #pragma unroll
        for (int j = 0; j < 5; j++)
            C[(size_t)row * 40 + tx * 5 + j] = __float2half_rn(acc[j]);
    }
}

// ---------------- CSR gather (fp16 in) + self-loop + bias + BN stats, fp32 h out --
__global__ void gather128_bn(const __half* __restrict__ xw, const float* __restrict__ b,
                             float* __restrict__ h, int n, int statIdx) {
    __shared__ float sbs[128], sbss[128];
    int tid = threadIdx.x;
    if (tid < 128) { sbs[tid] = 0.f; sbss[tid] = 0.f; }
    __syncthreads();

    int lane   = tid & 31;
    int warp   = (blockIdx.x * blockDim.x + tid) >> 5;
    int nwarps = (gridDim.x * blockDim.x) >> 5;

    float4 ps  = make_float4(0.f, 0.f, 0.f, 0.f);
    float4 pss = make_float4(0.f, 0.f, 0.f, 0.f);
    float4 bb  = ((const float4*)b)[lane];

    for (int v = warp; v < n; v += nwarps) {
        int beg = g_rowptr[v], end = g_rowptr[v + 1];
        float4 acc = make_float4(0.f, 0.f, 0.f, 0.f);
        for (int i = beg; i < end; i++) {
            int   s = g_esrc[i];
            float w = g_enorm[i];
            uint2 rv = ((const uint2*)(xw + (size_t)s * D))[lane];
            float2 f0 = __half22float2(*reinterpret_cast<__half2*>(&rv.x));
            float2 f1 = __half22float2(*reinterpret_cast<__half2*>(&rv.y));
            acc.x = fmaf(f0.x, w, acc.x);
            acc.y = fmaf(f0.y, w, acc.y);
            acc.z = fmaf(f1.x, w, acc.z);
            acc.w = fmaf(f1.y, w, acc.w);
        }
        float di  = g_dinv[v];
        float di2 = di * di;
        uint2 rv = ((const uint2*)(xw + (size_t)v * D))[lane];
        float2 f0 = __half22float2(*reinterpret_cast<__half2*>(&rv.x));
        float2 f1 = __half22float2(*reinterpret_cast<__half2*>(&rv.y));
        acc.x = fmaf(f0.x, di2, acc.x) + bb.x;
        acc.y = fmaf(f0.y, di2, acc.y) + bb.y;
        acc.z = fmaf(f1.x, di2, acc.z) + bb.z;
        acc.w = fmaf(f1.y, di2, acc.w) + bb.w;
        ((float4*)(h + (size_t)v * D))[lane] = acc;
        ps.x += acc.x; ps.y += acc.y; ps.z += acc.z; ps.w += acc.w;
        pss.x = fmaf(acc.x, acc.x, pss.x);
        pss.y = fmaf(acc.y, acc.y, pss.y);
        pss.z = fmaf(acc.z, acc.z, pss.z);
        pss.w = fmaf(acc.w, acc.w, pss.w);
    }

    atomicAdd(&sbs[lane * 4 + 0], ps.x);
    atomicAdd(&sbs[lane * 4 + 1], ps.y);
    atomicAdd(&sbs[lane * 4 + 2], ps.z);
    atomicAdd(&sbs[lane * 4 + 3], ps.w);
    atomicAdd(&sbss[lane * 4 + 0], pss.x);
    atomicAdd(&sbss[lane * 4 + 1], pss.y);
    atomicAdd(&sbss[lane * 4 + 2], pss.z);
    atomicAdd(&sbss[lane * 4 + 3], pss.w);
    __syncthreads();
    if (tid < 128) {
        atomicAdd(&g_bnsum[statIdx * 128 + tid],   sbs[tid]);
        atomicAdd(&g_bnsumsq[statIdx * 128 + tid], sbss[tid]);
    }
}

// ---------------- CSR gather (D=40, fp16) + self-loop + bias + log_softmax --------
__global__ void gather40_softmax(const __half* __restrict__ xw2,
                                 const float* __restrict__ b2, float* __restrict__ out,
                                 int n) {
    int lane   = threadIdx.x & 31;
    int warp   = (blockIdx.x * blockDim.x + threadIdx.x) >> 5;
    int nwarps = (gridDim.x * blockDim.x) >> 5;

    for (int v = warp; v < n; v += nwarps) {
        int beg = g_rowptr[v], end = g_rowptr[v + 1];
        float4 acc = make_float4(0.f, 0.f, 0.f, 0.f);
        if (lane < 10) {
            for (int i = beg; i < end; i++) {
                int   s = g_esrc[i];
                float w = g_enorm[i];
                uint2 rv = ((const uint2*)(xw2 + (size_t)s * DOUT))[lane];
                float2 f0 = __half22float2(*reinterpret_cast<__half2*>(&rv.x));
                float2 f1 = __half22float2(*reinterpret_cast<__half2*>(&rv.y));
                acc.x = fmaf(f0.x, w, acc.x);
                acc.y = fmaf(f0.y, w, acc.y);
                acc.z = fmaf(f1.x, w, acc.z);
                acc.w = fmaf(f1.y, w, acc.w);
            }
            float di  = g_dinv[v];
            float di2 = di * di;
            uint2 rv = ((const uint2*)(xw2 + (size_t)v * DOUT))[lane];
            float2 f0 = __half22float2(*reinterpret_cast<__half2*>(&rv.x));
            float2 f1 = __half22float2(*reinterpret_cast<__half2*>(&rv.y));
            float4 bb = ((const float4*)b2)[lane];
            acc.x = fmaf(f0.x, di2, acc.x) + bb.x;
            acc.y = fmaf(f0.y, di2, acc.y) + bb.y;
            acc.z = fmaf(f1.x, di2, acc.z) + bb.z;
            acc.w = fmaf(f1.y, di2, acc.w) + bb.w;
        }
        float m = (lane < 10)
                ? fmaxf(fmaxf(acc.x, acc.y), fmaxf(acc.z, acc.w)) : -1e30f;
        #pragma unroll
        for (int o = 16; o; o >>= 1) m = fmaxf(m, __shfl_xor_sync(0xffffffffu, m, o));
        float s = (lane < 10)
                ? (expf(acc.x - m) + expf(acc.y - m) + expf(acc.z - m) + expf(acc.w - m))
                : 0.f;
        #pragma unroll
        for (int o = 16; o; o >>= 1) s += __shfl_xor_sync(0xffffffffu, s, o);
        float lse = m + logf(s);
        if (lane < 10)
            ((float4*)(out + (size_t)v * DOUT))[lane] =
                make_float4(acc.x - lse, acc.y - lse, acc.z - lse, acc.w - lse);
    }
}

// ---------------- launch ----------------
extern "C" void kernel_launch(void* const* d_in, const int* in_sizes, int n_in,
                              void* d_out, int out_size) {
    const float* x   = (const float*)d_in[0];
    const void*  ei  = d_in[1];
    const float* ew  = (const float*)d_in[2];
    const float* W0  = (const float*)d_in[3];
    const float* b0  = (const float*)d_in[4];
    const float* g0  = (const float*)d_in[5];
    const float* be0 = (const float*)d_in[6];
    const float* W1  = (const float*)d_in[7];
    const float* b1  = (const float*)d_in[8];
    const float* g1  = (const float*)d_in[9];
    const float* be1 = (const float*)d_in[10];
    const float* W2  = (const float*)d_in[11];
    const float* b2  = (const float*)d_in[12];

    int n = in_sizes[0] / D;
    int E = in_sizes[2];
    int twoE = 2 * E;
    float fn = (float)n;

    cudaFuncSetAttribute(gemm128<false>, cudaFuncAttributeMaxDynamicSharedMemorySize, GEMM_SMEM);
    cudaFuncSetAttribute(gemm128<true>,  cudaFuncAttributeMaxDynamicSharedMemorySize, GEMM_SMEM);

    void *p_deg, *p_cnt, *p_fill, *p_bns, *p_bnss, *p_xw, *p_h, *p_xw2;
    cudaGetSymbolAddress(&p_deg,  g_deg);
    cudaGetSymbolAddress(&p_cnt,  g_cnt);
    cudaGetSymbolAddress(&p_fill, g_fill);
    cudaGetSymbolAddress(&p_bns,  g_bnsum);
    cudaGetSymbolAddress(&p_bnss, g_bnsumsq);
    cudaGetSymbolAddress(&p_xw,   g_xw);
    cudaGetSymbolAddress(&p_h,    g_h);
    cudaGetSymbolAddress(&p_xw2,  g_xw2);
    __half* xw  = (__half*)p_xw;
    float*  h   = (float*)p_h;
    __half* xw2 = (__half*)p_xw2;

    const int T = 256;
    int nb_scan = cdiv(n, 512);
    int gather_blocks = 1184;

    // fork/join: CSR build + stat zeroing (s2) overlapped with layer-0 GEMM (s0).
    cudaStream_t s2;
    cudaEvent_t evF, evJ;
    cudaStreamCreateWithFlags(&s2, cudaStreamNonBlocking);
    cudaEventCreateWithFlags(&evF, cudaEventDisableTiming);
    cudaEventCreateWithFlags(&evJ, cudaEventDisableTiming);

    cudaEventRecord(evF, 0);
    cudaStreamWaitEvent(s2, evF, 0);

    // ---- branch A (s2): zero + convert + CSR build ----
    cudaMemsetAsync(p_deg,  0, (size_t)n * sizeof(float), s2);
    cudaMemsetAsync(p_cnt,  0, (size_t)n * sizeof(int), s2);
    cudaMemsetAsync(p_fill, 0, (size_t)n * sizeof(int), s2);
    cudaMemsetAsync(p_bns,  0, 256 * sizeof(float), s2);
    cudaMemsetAsync(p_bnss, 0, 256 * sizeof(float), s2);
    detect_kernel<<<1, 32, 0, s2>>>((const unsigned*)ei, twoE);
    convert_deg_kernel<<<cdiv(twoE, T), T, 0, s2>>>(ei, ew, E);
    scan1<<<nb_scan, 512, 0, s2>>>(n);
    scan2<<<1, 256, 0, s2>>>(nb_scan);
    scan3<<<cdiv(n, T), T, 0, s2>>>(n, E);
    fill_kernel<<<cdiv(E, T), T, 0, s2>>>(ew, E);
    cudaEventRecord(evJ, s2);

    // ---- branch B (stream 0): layer-0 GEMM ----
    gemm128<false><<<cdiv(n, 128), T, GEMM_SMEM>>>(x, W0, xw, n,
                                                   (const float*)0, (const float*)0, 0, fn);

    // join
    cudaStreamWaitEvent(0, evJ, 0);

    // ---- layer 0 aggregate (stats -> buffer 0) ----
    gather128_bn<<<gather_blocks, T>>>(xw, b0, h, n, 0);

    // ---- layer 1 (BN from buffer 0 in prologue) ----
    gemm128<true><<<cdiv(n, 128), T, GEMM_SMEM>>>(h, W1, xw, n, g0, be0, 0, fn);
    gather128_bn<<<gather_blocks, T>>>(xw, b1, h, n, 1);

    // ---- layer 2 (BN from buffer 1) + log_softmax ----
    gemm40<<<cdiv(n, 32), T>>>(h, W2, xw2, n, g1, be1, 1, fn);
    gather40_softmax<<<gather_blocks, T>>>(xw2, b2, (float*)d_out, n);

    cudaEventDestroy(evF);
    cudaEventDestroy(evJ);
    cudaStreamDestroy(s2);
}

// round 10
// speedup vs baseline: 1.0630x; 1.0630x over previous
#include <cuda_runtime.h>
#include <cuda_fp16.h>
#include <math.h>

#define D    128
#define DOUT 40
#define NMAX 100000
#define EMAX 1600000

typedef unsigned long long ull;

static inline int cdiv(int a, int b) { return (a + b - 1) / b; }

// ---------------- scratch (static device globals; no allocation) ----------------
__device__ __align__(16) __half g_xw [(size_t)NMAX * D];    // fp16 gather operand
__device__ __align__(16) float  g_h  [(size_t)NMAX * D];    // fp32 hidden activations
__device__ __align__(16) __half g_xw2[(size_t)NMAX * DOUT]; // fp16 final-layer operand
__device__ float g_deg [NMAX];
__device__ float g_dinv[NMAX];
__device__ int   g_idx [2 * EMAX];
__device__ int   g_is64;
// CSR
__device__ int   g_cnt [NMAX];
__device__ int   g_rowptr[NMAX + 1];
__device__ int   g_fill[NMAX];
__device__ int   g_bsum[256];
__device__ int   g_boff[256];
__device__ int   g_esrc [EMAX];
__device__ float g_enorm[EMAX];
// BN
__device__ __align__(16) float g_bnsum  [128];
__device__ __align__(16) float g_bnsumsq[128];
__device__ __align__(16) float g_scale  [128];
__device__ __align__(16) float g_shift  [128];

// ---------------- packed f32x2 helpers ----------------
__device__ __forceinline__ ull fma2(ull a, ull b, ull c) {
    ull d;
    asm("fma.rn.f32x2 %0, %1, %2, %3;" : "=l"(d) : "l"(a), "l"(b), "l"(c));
    return d;
}
__device__ __forceinline__ ull splat2(float x) {
    ull d;
    asm("mov.b64 %0, {%1, %1};" : "=l"(d) : "f"(x));
    return d;
}

// ---------------- index dtype detect ----------------
__global__ void detect_kernel(const unsigned* __restrict__ w, int twoE) {
    if (threadIdx.x == 0 && blockIdx.x == 0) {
        int nchk = twoE < 256 ? twoE : 256;
        int is64 = 1;
        for (int i = 0; i < nchk; i++)
            if (w[2 * i + 1] != 0u) { is64 = 0; break; }
        g_is64 = is64;
    }
}

// ---------------- convert + degree/histogram (fused) ----------------
__global__ void convert_deg_kernel(const void* __restrict__ ei,
                                   const float* __restrict__ ew, int E) {
    int i = blockIdx.x * blockDim.x + threadIdx.x;
    int twoE = 2 * E;
    if (i < twoE) {
        int v;
        if (g_is64) v = (int)((const long long*)ei)[i];
        else        v = ((const int*)ei)[i];
        g_idx[i] = v;
        if (i >= E) {
            atomicAdd(&g_deg[v], ew[i - E]);
            atomicAdd(&g_cnt[v], 1);
        }
    }
}

// ---------------- exclusive scan of g_cnt -> g_rowptr (3-pass) ----------------
__global__ void scan1(int n) {
    __shared__ int sm[512];
    int i = blockIdx.x * 512 + threadIdx.x;
    int v = (i < n) ? g_cnt[i] : 0;
    sm[threadIdx.x] = v;
    __syncthreads();
    #pragma unroll
    for (int o = 1; o < 512; o <<= 1) {
        int t = (threadIdx.x >= o) ? sm[threadIdx.x - o] : 0;
        __syncthreads();
        sm[threadIdx.x] += t;
        __syncthreads();
    }
    if (i < n) g_rowptr[i] = sm[threadIdx.x] - v;
    if (threadIdx.x == 511) g_bsum[blockIdx.x] = sm[511];
}

__global__ void scan2(int nb) {
    __shared__ int sm[256];
    int v = (threadIdx.x < nb) ? g_bsum[threadIdx.x] : 0;
    sm[threadIdx.x] = v;
    __syncthreads();
    #pragma unroll
    for (int o = 1; o < 256; o <<= 1) {
        int t = (threadIdx.x >= o) ? sm[threadIdx.x - o] : 0;
        __syncthreads();
        sm[threadIdx.x] += t;
        __syncthreads();
    }
    if (threadIdx.x < nb) g_boff[threadIdx.x] = sm[threadIdx.x] - v;
}

__global__ void scan3(int n, int E) {
    int i = blockIdx.x * blockDim.x + threadIdx.x;
    if (i < n) {
        g_rowptr[i] += g_boff[i >> 9];
        g_dinv[i] = rsqrtf(g_deg[i] + 1.0f);
    }
    if (i == 0) g_rowptr[n] = E;
}

// ---------------- CSR fill ----------------
__global__ void fill_kernel(const float* __restrict__ ew, int E) {
    int e = blockIdx.x * blockDim.x + threadIdx.x;
    if (e < E) {
        int s = g_idx[e];
        int d = g_idx[E + e];
        int pos = g_rowptr[d] + atomicAdd(&g_fill[d], 1);
        g_esrc[pos]  = s;
        g_enorm[pos] = g_dinv[s] * ew[e] * g_dinv[d];
    }
}

// ---------------- fused BN+ReLU on load ----------------
__device__ __forceinline__ float4 bnrelu4(float4 v, int c4) {
    float4 sc = ((const float4*)g_scale)[c4];
    float4 sh = ((const float4*)g_shift)[c4];
    v.x = fmaxf(fmaf(v.x, sc.x, sh.x), 0.0f);
    v.y = fmaxf(fmaf(v.y, sc.y, sh.y), 0.0f);
    v.z = fmaxf(fmaf(v.z, sc.z, sh.z), 0.0f);
    v.w = fmaxf(fmaf(v.w, sc.w, sh.w), 0.0f);
    return v;
}

// ---------------- GEMM 128x128: fp32 in (opt BN+ReLU), fp16 out -----------------
#define GEMM_SMEM ((128 * 128 + 128 * 132) * 4)

template <bool FUSE_BN>
__global__ void __launch_bounds__(256) gemm128(const float* __restrict__ A,
                                               const float* __restrict__ W,
                                               __half* __restrict__ C, int n) {
    extern __shared__ float smem[];
    float* sW = smem;                 // [128][128]
    float* sX = smem + 128 * 128;     // [128][132] padded

    int tid = threadIdx.x;
    int row0 = blockIdx.x * 128;

    const float4* W4  = (const float4*)W;
    float4*       sW4 = (float4*)sW;
    #pragma unroll
    for (int i = tid; i < 4096; i += 256) sW4[i] = W4[i];

    const float4* A4 = (const float4*)A + (size_t)row0 * 32;
    float4* sX4 = (float4*)sX;
    #pragma unroll
    for (int i = tid; i < 4096; i += 256) {
        int r = i >> 5, c4 = i & 31;
        float4 v = make_float4(0.f, 0.f, 0.f, 0.f);
        if (row0 + r < n) v = A4[i];
        if (FUSE_BN) v = bnrelu4(v, c4);
        sX4[r * 33 + c4] = v;
    }
    __syncthreads();

    int tx = tid & 15, ty = tid >> 4;
    ull acc[8][4];
    #pragma unroll
    for (int j = 0; j < 8; j++)
        #pragma unroll
        for (int p = 0; p < 4; p++) acc[j][p] = splat2(0.f);

    const ulonglong2* sW2 = (const ulonglong2*)sW;
    #pragma unroll 2
    for (int k = 0; k < 128; k++) {
        ulonglong2 wa = sW2[k * 32 + 2 * tx];
        ulonglong2 wb = sW2[k * 32 + 2 * tx + 1];
        #pragma unroll
        for (int j = 0; j < 8; j++) {
            int row = (j < 4) ? (ty * 4 + j) : (64 + ty * 4 + (j - 4));
            ull xi = splat2(sX[row * 132 + k]);
            acc[j][0] = fma2(xi, wa.x, acc[j][0]);
            acc[j][1] = fma2(xi, wa.y, acc[j][1]);
            acc[j][2] = fma2(xi, wb.x, acc[j][2]);
            acc[j][3] = fma2(xi, wb.y, acc[j][3]);
        }
    }

    #pragma unroll
    for (int j = 0; j < 8; j++) {
        int r = row0 + ((j < 4) ? (ty * 4 + j) : (64 + ty * 4 + (j - 4)));
        if (r < n) {
            uint4 o;
            union { ull u; float2 f; } cv;
            __half2 hh;
            cv.u = acc[j][0]; hh = __floats2half2_rn(cv.f.x, cv.f.y);
            o.x = *reinterpret_cast<unsigned*>(&hh);
            cv.u = acc[j][1]; hh = __floats2half2_rn(cv.f.x, cv.f.y);
            o.y = *reinterpret_cast<unsigned*>(&hh);
            cv.u = acc[j][2]; hh = __floats2half2_rn(cv.f.x, cv.f.y);
            o.z = *reinterpret_cast<unsigned*>(&hh);
            cv.u = acc[j][3]; hh = __floats2half2_rn(cv.f.x, cv.f.y);
            o.w = *reinterpret_cast<unsigned*>(&hh);
            ((uint4*)(C + (size_t)r * D))[tx] = o;
        }
    }
}

// ---------------- GEMM 128->40: fp32 in (BN+ReLU), fp16 out ----------------
__global__ void gemm40(const float* __restrict__ A, const float* __restrict__ W,
                       __half* __restrict__ C, int n) {
    __shared__ float sW[128 * 40];
    __shared__ float sX[32 * 132];

    int tid = threadIdx.x;
    int row0 = blockIdx.x * 32;

    const float4* W4  = (const float4*)W;
    float4*       sW4 = (float4*)sW;
    #pragma unroll
    for (int i = tid; i < 1280; i += 256) sW4[i] = W4[i];

    const float4* A4 = (const float4*)A + (size_t)row0 * 32;
    float4* sX4 = (float4*)sX;
    #pragma unroll
    for (int i = tid; i < 1024; i += 256) {
        int r = i >> 5, c4 = i & 31;
        float4 v = make_float4(0.f, 0.f, 0.f, 0.f);
        if (row0 + r < n) v = A4[i];
        v = bnrelu4(v, c4);
        sX4[r * 33 + c4] = v;
    }
    __syncthreads();

    int tx = tid & 7, rt = tid >> 3;
    float acc[5] = {0.f, 0.f, 0.f, 0.f, 0.f};
    #pragma unroll 4
    for (int k = 0; k < 128; k++) {
        float xv = sX[rt * 132 + k];
        #pragma unroll
        for (int j = 0; j < 5; j++)
            acc[j] = fmaf(xv, sW[k * 40 + tx * 5 + j], acc[j]);
    }
    int row = row0 + rt;
    if (row < n) {
        #pragma unroll
        for (int j = 0; j < 5; j++)
            C[(size_t)row * 40 + tx * 5 + j] = __float2half_rn(acc[j]);
    }
}

// ---------------- CSR gather (fp16 in, 2-way unrolled) + BN stats, fp32 h out ----
__global__ void gather128_bn(const __half* __restrict__ xw, const float* __restrict__ b,
                             float* __restrict__ h, int n) {
    __shared__ float sbs[128], sbss[128];
    int tid = threadIdx.x;
    if (tid < 128) { sbs[tid] = 0.f; sbss[tid] = 0.f; }
    __syncthreads();

    int lane   = tid & 31;
    int warp   = (blockIdx.x * blockDim.x + tid) >> 5;
    int nwarps = (gridDim.x * blockDim.x) >> 5;

    float4 ps  = make_float4(0.f, 0.f, 0.f, 0.f);
    float4 pss = make_float4(0.f, 0.f, 0.f, 0.f);
    float4 bb  = ((const float4*)b)[lane];

    for (int v = warp; v < n; v += nwarps) {
        int beg = g_rowptr[v], end = g_rowptr[v + 1];
        float4 acc  = make_float4(0.f, 0.f, 0.f, 0.f);
        float4 acc2 = make_float4(0.f, 0.f, 0.f, 0.f);
        int i = beg;
        // 2-way unroll: two independent gather chains -> 2x outstanding L2 loads
        for (; i + 2 <= end; i += 2) {
            int   s0 = g_esrc[i],     s1 = g_esrc[i + 1];
            float w0 = g_enorm[i],    w1 = g_enorm[i + 1];
            uint2 r0 = ((const uint2*)(xw + (size_t)s0 * D))[lane];
            uint2 r1 = ((const uint2*)(xw + (size_t)s1 * D))[lane];
            float2 a0 = __half22float2(*reinterpret_cast<__half2*>(&r0.x));
            float2 a1 = __half22float2(*reinterpret_cast<__half2*>(&r0.y));
            float2 b0f = __half22float2(*reinterpret_cast<__half2*>(&r1.x));
            float2 b1f = __half22float2(*reinterpret_cast<__half2*>(&r1.y));
            acc.x  = fmaf(a0.x,  w0, acc.x);
            acc.y  = fmaf(a0.y,  w0, acc.y);
            acc.z  = fmaf(a1.x,  w0, acc.z);
            acc.w  = fmaf(a1.y,  w0, acc.w);
            acc2.x = fmaf(b0f.x, w1, acc2.x);
            acc2.y = fmaf(b0f.y, w1, acc2.y);
            acc2.z = fmaf(b1f.x, w1, acc2.z);
            acc2.w = fmaf(b1f.y, w1, acc2.w);
        }
        if (i < end) {
            int   s0 = g_esrc[i];
            float w0 = g_enorm[i];
            uint2 r0 = ((const uint2*)(xw + (size_t)s0 * D))[lane];
            float2 a0 = __half22float2(*reinterpret_cast<__half2*>(&r0.x));
            float2 a1 = __half22float2(*reinterpret_cast<__half2*>(&r0.y));
            acc.x = fmaf(a0.x, w0, acc.x);
            acc.y = fmaf(a0.y, w0, acc.y);
            acc.z = fmaf(a1.x, w0, acc.z);
            acc.w = fmaf(a1.y, w0, acc.w);
        }
        acc.x += acc2.x; acc.y += acc2.y; acc.z += acc2.z; acc.w += acc2.w;

        float di  = g_dinv[v];
        float di2 = di * di;
        uint2 rv = ((const uint2*)(xw + (size_t)v * D))[lane];
        float2 f0 = __half22float2(*reinterpret_cast<__half2*>(&rv.x));
        float2 f1 = __half22float2(*reinterpret_cast<__half2*>(&rv.y));
        acc.x = fmaf(f0.x, di2, acc.x) + bb.x;
        acc.y = fmaf(f0.y, di2, acc.y) + bb.y;
        acc.z = fmaf(f1.x, di2, acc.z) + bb.z;
        acc.w = fmaf(f1.y, di2, acc.w) + bb.w;
        ((float4*)(h + (size_t)v * D))[lane] = acc;
        ps.x += acc.x; ps.y += acc.y; ps.z += acc.z; ps.w += acc.w;
        pss.x = fmaf(acc.x, acc.x, pss.x);
        pss.y = fmaf(acc.y, acc.y, pss.y);
        pss.z = fmaf(acc.z, acc.z, pss.z);
        pss.w = fmaf(acc.w, acc.w, pss.w);
    }

    atomicAdd(&sbs[lane * 4 + 0], ps.x);
    atomicAdd(&sbs[lane * 4 + 1], ps.y);
    atomicAdd(&sbs[lane * 4 + 2], ps.z);
    atomicAdd(&sbs[lane * 4 + 3], ps.w);
    atomicAdd(&sbss[lane * 4 + 0], pss.x);
    atomicAdd(&sbss[lane * 4 + 1], pss.y);
    atomicAdd(&sbss[lane * 4 + 2], pss.z);
    atomicAdd(&sbss[lane * 4 + 3], pss.w);
    __syncthreads();
    if (tid < 128) {
        atomicAdd(&g_bnsum[tid],   sbs[tid]);
        atomicAdd(&g_bnsumsq[tid], sbss[tid]);
    }
}

__global__ void bn_final(const float* __restrict__ g, const float* __restrict__ be,
                         float fn) {
    int c = threadIdx.x;
    float mean = g_bnsum[c] / fn;
    float var  = g_bnsumsq[c] / fn - mean * mean;
    float sc   = g[c] * rsqrtf(var + 1e-5f);
    g_scale[c] = sc;
    g_shift[c] = be[c] - mean * sc;
    g_bnsum[c] = 0.f;          // reset for next layer (replaces memsets)
    g_bnsumsq[c] = 0.f;
}

// ---------------- CSR gather (D=40, fp16, 2-way unrolled) + log_softmax ----------
__global__ void gather40_softmax(const __half* __restrict__ xw2,
                                 const float* __restrict__ b2, float* __restrict__ out,
                                 int n) {
    int lane   = threadIdx.x & 31;
    int warp   = (blockIdx.x * blockDim.x + threadIdx.x) >> 5;
    int nwarps = (gridDim.x * blockDim.x) >> 5;

    for (int v = warp; v < n; v += nwarps) {
        int beg = g_rowptr[v], end = g_rowptr[v + 1];
        float4 acc  = make_float4(0.f, 0.f, 0.f, 0.f);
        float4 acc2 = make_float4(0.f, 0.f, 0.f, 0.f);
        if (lane < 10) {
            int i = beg;
            for (; i + 2 <= end; i += 2) {
                int   s0 = g_esrc[i],  s1 = g_esrc[i + 1];
                float w0 = g_enorm[i], w1 = g_enorm[i + 1];
                uint2 r0 = ((const uint2*)(xw2 + (size_t)s0 * DOUT))[lane];
                uint2 r1 = ((const uint2*)(xw2 + (size_t)s1 * DOUT))[lane];
                float2 a0 = __half22float2(*reinterpret_cast<__half2*>(&r0.x));
                float2 a1 = __half22float2(*reinterpret_cast<__half2*>(&r0.y));
                float2 c0 = __half22float2(*reinterpret_cast<__half2*>(&r1.x));
                float2 c1 = __half22float2(*reinterpret_cast<__half2*>(&r1.y));
                acc.x  = fmaf(a0.x, w0, acc.x);
                acc.y  = fmaf(a0.y, w0, acc.y);
                acc.z  = fmaf(a1.x, w0, acc.z);
                acc.w  = fmaf(a1.y, w0, acc.w);
                acc2.x = fmaf(c0.x, w1, acc2.x);
                acc2.y = fmaf(c0.y, w1, acc2.y);
                acc2.z = fmaf(c1.x, w1, acc2.z);
                acc2.w = fmaf(c1.y, w1, acc2.w);
            }
            if (i < end) {
                int   s0 = g_esrc[i];
                float w0 = g_enorm[i];
                uint2 r0 = ((const uint2*)(xw2 + (size_t)s0 * DOUT))[lane];
                float2 a0 = __half22float2(*reinterpret_cast<__half2*>(&r0.x));
                float2 a1 = __half22float2(*reinterpret_cast<__half2*>(&r0.y));
                acc.x = fmaf(a0.x, w0, acc.x);
                acc.y = fmaf(a0.y, w0, acc.y);
                acc.z = fmaf(a1.x, w0, acc.z);
                acc.w = fmaf(a1.y, w0, acc.w);
            }
            acc.x += acc2.x; acc.y += acc2.y; acc.z += acc2.z; acc.w += acc2.w;

            float di  = g_dinv[v];
            float di2 = di * di;
            uint2 rv = ((const uint2*)(xw2 + (size_t)v * DOUT))[lane];
            float2 f0 = __half22float2(*reinterpret_cast<__half2*>(&rv.x));
            float2 f1 = __half22float2(*reinterpret_cast<__half2*>(&rv.y));
            float4 bb = ((const float4*)b2)[lane];
            acc.x = fmaf(f0.x, di2, acc.x) + bb.x;
            acc.y = fmaf(f0.y, di2, acc.y) + bb.y;
            acc.z = fmaf(f1.x, di2, acc.z) + bb.z;
            acc.w = fmaf(f1.y, di2, acc.w) + bb.w;
        }
        float m = (lane < 10)
                ? fmaxf(fmaxf(acc.x, acc.y), fmaxf(acc.z, acc.w)) : -1e30f;
        #pragma unroll
        for (int o = 16; o; o >>= 1) m = fmaxf(m, __shfl_xor_sync(0xffffffffu, m, o));
        float s = (lane < 10)
                ? (expf(acc.x - m) + expf(acc.y - m) + expf(acc.z - m) + expf(acc.w - m))
                : 0.f;
        #pragma unroll
        for (int o = 16; o; o >>= 1) s += __shfl_xor_sync(0xffffffffu, s, o);
        float lse = m + logf(s);
        if (lane < 10)
            ((float4*)(out + (size_t)v * DOUT))[lane] =
                make_float4(acc.x - lse, acc.y - lse, acc.z - lse, acc.w - lse);
    }
}

// ---------------- launch ----------------
extern "C" void kernel_launch(void* const* d_in, const int* in_sizes, int n_in,
                              void* d_out, int out_size) {
    const float* x   = (const float*)d_in[0];
    const void*  ei  = d_in[1];
    const float* ew  = (const float*)d_in[2];
    const float* W0  = (const float*)d_in[3];
    const float* b0  = (const float*)d_in[4];
    const float* g0  = (const float*)d_in[5];
    const float* be0 = (const float*)d_in[6];
    const float* W1  = (const float*)d_in[7];
    const float* b1  = (const float*)d_in[8];
    const float* g1  = (const float*)d_in[9];
    const float* be1 = (const float*)d_in[10];
    const float* W2  = (const float*)d_in[11];
    const float* b2  = (const float*)d_in[12];

    int n = in_sizes[0] / D;
    int E = in_sizes[2];
    int twoE = 2 * E;

    cudaFuncSetAttribute(gemm128<false>, cudaFuncAttributeMaxDynamicSharedMemorySize, GEMM_SMEM);
    cudaFuncSetAttribute(gemm128<true>,  cudaFuncAttributeMaxDynamicSharedMemorySize, GEMM_SMEM);

    void *p_deg, *p_cnt, *p_fill, *p_bns, *p_bnss, *p_xw, *p_h, *p_xw2;
    cudaGetSymbolAddress(&p_deg,  g_deg);
    cudaGetSymbolAddress(&p_cnt,  g_cnt);
    cudaGetSymbolAddress(&p_fill, g_fill);
    cudaGetSymbolAddress(&p_bns,  g_bnsum);
    cudaGetSymbolAddress(&p_bnss, g_bnsumsq);
    cudaGetSymbolAddress(&p_xw,   g_xw);
    cudaGetSymbolAddress(&p_h,    g_h);
    cudaGetSymbolAddress(&p_xw2,  g_xw2);
    __half* xw  = (__half*)p_xw;
    float*  h   = (float*)p_h;
    __half* xw2 = (__half*)p_xw2;

    const int T = 256;
    int nb_scan = cdiv(n, 512);
    int gather_blocks = 1184;

    // fork/join: CSR build (s2) overlapped with layer-0 GEMM (s0).
    cudaStream_t s2;
    cudaEvent_t evF, evJ;
    cudaStreamCreateWithFlags(&s2, cudaStreamNonBlocking);
    cudaEventCreateWithFlags(&evF, cudaEventDisableTiming);
    cudaEventCreateWithFlags(&evJ, cudaEventDisableTiming);

    cudaEventRecord(evF, 0);
    cudaStreamWaitEvent(s2, evF, 0);

    // ---- branch A (s2): zero + convert + CSR build ----
    cudaMemsetAsync(p_deg,  0, (size_t)n * sizeof(float), s2);
    cudaMemsetAsync(p_cnt,  0, (size_t)n * sizeof(int), s2);
    cudaMemsetAsync(p_fill, 0, (size_t)n * sizeof(int), s2);
    cudaMemsetAsync(p_bns,  0, 128 * sizeof(float), s2);
    cudaMemsetAsync(p_bnss, 0, 128 * sizeof(float), s2);
    detect_kernel<<<1, 32, 0, s2>>>((const unsigned*)ei, twoE);
    convert_deg_kernel<<<cdiv(twoE, T), T, 0, s2>>>(ei, ew, E);
    scan1<<<nb_scan, 512, 0, s2>>>(n);
    scan2<<<1, 256, 0, s2>>>(nb_scan);
    scan3<<<cdiv(n, T), T, 0, s2>>>(n, E);
    fill_kernel<<<cdiv(E, T), T, 0, s2>>>(ew, E);
    cudaEventRecord(evJ, s2);

    // ---- branch B (stream 0): layer-0 GEMM ----
    gemm128<false><<<cdiv(n, 128), T, GEMM_SMEM>>>(x, W0, xw, n);

    // join
    cudaStreamWaitEvent(0, evJ, 0);

    // ---- layer 0 aggregate ----
    gather128_bn<<<gather_blocks, T>>>(xw, b0, h, n);
    bn_final<<<1, 128>>>(g0, be0, (float)n);   // also resets stats

    // ---- layer 1 ----
    gemm128<true><<<cdiv(n, 128), T, GEMM_SMEM>>>(h, W1, xw, n);
    gather128_bn<<<gather_blocks, T>>>(xw, b1, h, n);
    bn_final<<<1, 128>>>(g1, be1, (float)n);

    // ---- layer 2 + log_softmax ----
    gemm40<<<cdiv(n, 32), T>>>(h, W2, xw2, n);
    gather40_softmax<<<gather_blocks, T>>>(xw2, b2, (float*)d_out, n);

    cudaEventDestroy(evF);
    cudaEventDestroy(evJ);
    cudaStreamDestroy(s2);
}

// round 11
// speedup vs baseline: 1.3914x; 1.3089x over previous
#include <cuda_runtime.h>
#include <cuda_fp16.h>
#include <mma.h>
#include <math.h>

using namespace nvcuda;

#define D    128
#define DOUT 40
#define NMAX 100000
#define EMAX 1600000

typedef unsigned long long ull;

static inline int cdiv(int a, int b) { return (a + b - 1) / b; }

// ---------------- scratch (static device globals; no allocation) ----------------
__device__ __align__(16) __half g_xw [(size_t)NMAX * D];    // fp16 gather operand
__device__ __align__(16) float  g_h  [(size_t)NMAX * D];    // fp32 hidden activations
__device__ __align__(16) __half g_xw2[(size_t)NMAX * DOUT]; // fp16 final-layer operand
__device__ float g_deg [NMAX];
__device__ float g_dinv[NMAX];
__device__ int   g_idx [2 * EMAX];
__device__ int   g_is64;
// CSR
__device__ int   g_cnt [NMAX];
__device__ int   g_rowptr[NMAX + 1];
__device__ int   g_fill[NMAX];
__device__ int   g_bsum[256];
__device__ int   g_boff[256];
__device__ int   g_esrc [EMAX];
__device__ float g_enorm[EMAX];
// BN
__device__ __align__(16) float g_bnsum  [128];
__device__ __align__(16) float g_bnsumsq[128];
__device__ __align__(16) float g_scale  [128];
__device__ __align__(16) float g_shift  [128];

// ---------------- index dtype detect ----------------
__global__ void detect_kernel(const unsigned* __restrict__ w, int twoE) {
    if (threadIdx.x == 0 && blockIdx.x == 0) {
        int nchk = twoE < 256 ? twoE : 256;
        int is64 = 1;
        for (int i = 0; i < nchk; i++)
            if (w[2 * i + 1] != 0u) { is64 = 0; break; }
        g_is64 = is64;
    }
}

// ---------------- convert + degree/histogram (fused) ----------------
__global__ void convert_deg_kernel(const void* __restrict__ ei,
                                   const float* __restrict__ ew, int E) {
    int i = blockIdx.x * blockDim.x + threadIdx.x;
    int twoE = 2 * E;
    if (i < twoE) {
        int v;
        if (g_is64) v = (int)((const long long*)ei)[i];
        else        v = ((const int*)ei)[i];
        g_idx[i] = v;
        if (i >= E) {
            atomicAdd(&g_deg[v], ew[i - E]);
            atomicAdd(&g_cnt[v], 1);
        }
    }
}

// ---------------- exclusive scan of g_cnt -> g_rowptr (3-pass) ----------------
__global__ void scan1(int n) {
    __shared__ int sm[512];
    int i = blockIdx.x * 512 + threadIdx.x;
    int v = (i < n) ? g_cnt[i] : 0;
    sm[threadIdx.x] = v;
    __syncthreads();
    #pragma unroll
    for (int o = 1; o < 512; o <<= 1) {
        int t = (threadIdx.x >= o) ? sm[threadIdx.x - o] : 0;
        __syncthreads();
        sm[threadIdx.x] += t;
        __syncthreads();
    }
    if (i < n) g_rowptr[i] = sm[threadIdx.x] - v;
    if (threadIdx.x == 511) g_bsum[blockIdx.x] = sm[511];
}

__global__ void scan2(int nb) {
    __shared__ int sm[256];
    int v = (threadIdx.x < nb) ? g_bsum[threadIdx.x] : 0;
    sm[threadIdx.x] = v;
    __syncthreads();
    #pragma unroll
    for (int o = 1; o < 256; o <<= 1) {
        int t = (threadIdx.x >= o) ? sm[threadIdx.x - o] : 0;
        __syncthreads();
        sm[threadIdx.x] += t;
        __syncthreads();
    }
    if (threadIdx.x < nb) g_boff[threadIdx.x] = sm[threadIdx.x] - v;
}

__global__ void scan3(int n, int E) {
    int i = blockIdx.x * blockDim.x + threadIdx.x;
    if (i < n) {
        g_rowptr[i] += g_boff[i >> 9];
        g_dinv[i] = rsqrtf(g_deg[i] + 1.0f);
    }
    if (i == 0) g_rowptr[n] = E;
}

// ---------------- CSR fill ----------------
__global__ void fill_kernel(const float* __restrict__ ew, int E) {
    int e = blockIdx.x * blockDim.x + threadIdx.x;
    if (e < E) {
        int s = g_idx[e];
        int d = g_idx[E + e];
        int pos = g_rowptr[d] + atomicAdd(&g_fill[d], 1);
        g_esrc[pos]  = s;
        g_enorm[pos] = g_dinv[s] * ew[e] * g_dinv[d];
    }
}

// ---------------- fused BN+ReLU on load ----------------
__device__ __forceinline__ float4 bnrelu4(float4 v, int c4) {
    float4 sc = ((const float4*)g_scale)[c4];
    float4 sh = ((const float4*)g_shift)[c4];
    v.x = fmaxf(fmaf(v.x, sc.x, sh.x), 0.0f);
    v.y = fmaxf(fmaf(v.y, sc.y, sh.y), 0.0f);
    v.z = fmaxf(fmaf(v.z, sc.z, sh.z), 0.0f);
    v.w = fmaxf(fmaf(v.w, sc.w, sh.w), 0.0f);
    return v;
}

// ---------------- tensor-core GEMM 128x128: fp32 in (opt BN+ReLU), fp16 out ------
// Block 256 thr (8 warps, 4x2), 128x128 tile, wmma 16x16x16 f16 in / f32 accum.
// SMEM: phase 1 = A[128][136]h + B[128][136]h ; phase 2 (reuse) = C[128][136]f
#define SKH 136
#define GEMM_SMEM (128 * SKH * 4)   // 69632 B (== 2 * 128*136*2)

template <bool FUSE_BN>
__global__ void __launch_bounds__(256) gemm128t(const float* __restrict__ A,
                                                const float* __restrict__ W,
                                                __half* __restrict__ C, int n) {
    extern __shared__ char smem[];
    __half* sA = (__half*)smem;              // [128][SKH]
    __half* sB = sA + 128 * SKH;             // [128][SKH]
    float*  sC = (float*)smem;               // [128][SKH] (reused after compute)

    int tid = threadIdx.x;
    int row0 = blockIdx.x * 128;

    // W[k][n] fp32 -> sB fp16
    const float4* W4 = (const float4*)W;
    #pragma unroll
    for (int i = tid; i < 4096; i += 256) {
        int r = i >> 5, c4 = i & 31;
        float4 v = W4[i];
        __half2* dst = (__half2*)(sB + r * SKH + c4 * 4);
        dst[0] = __floats2half2_rn(v.x, v.y);
        dst[1] = __floats2half2_rn(v.z, v.w);
    }

    // A rows fp32 (opt BN+ReLU) -> sA fp16
    const float4* A4 = (const float4*)A + (size_t)row0 * 32;
    #pragma unroll
    for (int i = tid; i < 4096; i += 256) {
        int r = i >> 5, c4 = i & 31;
        float4 v = make_float4(0.f, 0.f, 0.f, 0.f);
        if (row0 + r < n) v = A4[i];
        if (FUSE_BN) v = bnrelu4(v, c4);
        __half2* dst = (__half2*)(sA + r * SKH + c4 * 4);
        dst[0] = __floats2half2_rn(v.x, v.y);
        dst[1] = __floats2half2_rn(v.z, v.w);
    }
    __syncthreads();

    int warp = tid >> 5;
    int wr = warp & 3;        // 4 row-groups of 32
    int wc = warp >> 2;       // 2 col-groups of 64

    wmma::fragment<wmma::accumulator, 16, 16, 16, float> acc[2][4];
    #pragma unroll
    for (int i = 0; i < 2; i++)
        #pragma unroll
        for (int j = 0; j < 4; j++) wmma::fill_fragment(acc[i][j], 0.0f);

    #pragma unroll
    for (int ks = 0; ks < 8; ks++) {
        wmma::fragment<wmma::matrix_a, 16, 16, 16, __half, wmma::row_major> af[2];
        wmma::load_matrix_sync(af[0], sA + (wr * 32 +  0) * SKH + ks * 16, SKH);
        wmma::load_matrix_sync(af[1], sA + (wr * 32 + 16) * SKH + ks * 16, SKH);
        wmma::fragment<wmma::matrix_b, 16, 16, 16, __half, wmma::row_major> bf[4];
        #pragma unroll
        for (int j = 0; j < 4; j++)
            wmma::load_matrix_sync(bf[j], sB + (ks * 16) * SKH + wc * 64 + j * 16, SKH);
        #pragma unroll
        for (int i = 0; i < 2; i++)
            #pragma unroll
            for (int j = 0; j < 4; j++)
                wmma::mma_sync(acc[i][j], af[i], bf[j], acc[i][j]);
    }
    __syncthreads();   // done reading sA/sB

    // stage accumulators to SMEM fp32
    #pragma unroll
    for (int i = 0; i < 2; i++)
        #pragma unroll
        for (int j = 0; j < 4; j++)
            wmma::store_matrix_sync(sC + (wr * 32 + i * 16) * SKH + wc * 64 + j * 16,
                                    acc[i][j], SKH, wmma::mem_row_major);
    __syncthreads();

    // convert to fp16, write out
    #pragma unroll
    for (int i = tid; i < 4096; i += 256) {
        int r = i >> 5, c4 = i & 31;
        if (row0 + r < n) {
            float4 v = *(const float4*)(sC + r * SKH + c4 * 4);
            uint2 o;
            __half2 hh;
            hh = __floats2half2_rn(v.x, v.y);
            o.x = *reinterpret_cast<unsigned*>(&hh);
            hh = __floats2half2_rn(v.z, v.w);
            o.y = *reinterpret_cast<unsigned*>(&hh);
            ((uint2*)(C + (size_t)(row0 + r) * D))[c4] = o;
        }
    }
}

// ---------------- GEMM 128->40: fp32 in (BN+ReLU), fp16 out ----------------
__global__ void gemm40(const float* __restrict__ A, const float* __restrict__ W,
                       __half* __restrict__ C, int n) {
    __shared__ float sW[128 * 40];
    __shared__ float sX[32 * 132];

    int tid = threadIdx.x;
    int row0 = blockIdx.x * 32;

    const float4* W4  = (const float4*)W;
    float4*       sW4 = (float4*)sW;
    #pragma unroll
    for (int i = tid; i < 1280; i += 256) sW4[i] = W4[i];

    const float4* A4 = (const float4*)A + (size_t)row0 * 32;
    float4* sX4 = (float4*)sX;
    #pragma unroll
    for (int i = tid; i < 1024; i += 256) {
        int r = i >> 5, c4 = i & 31;
        float4 v = make_float4(0.f, 0.f, 0.f, 0.f);
        if (row0 + r < n) v = A4[i];
        v = bnrelu4(v, c4);
        sX4[r * 33 + c4] = v;
    }
    __syncthreads();

    int tx = tid & 7, rt = tid >> 3;
    float acc[5] = {0.f, 0.f, 0.f, 0.f, 0.f};
    #pragma unroll 4
    for (int k = 0; k < 128; k++) {
        float xv = sX[rt * 132 + k];
        #pragma unroll
        for (int j = 0; j < 5; j++)
            acc[j] = fmaf(xv, sW[k * 40 + tx * 5 + j], acc[j]);
    }
    int row = row0 + rt;
    if (row < n) {
        #pragma unroll
        for (int j = 0; j < 5; j++)
            C[(size_t)row * 40 + tx * 5 + j] = __float2half_rn(acc[j]);
    }
}

// ---------------- CSR gather (fp16 in, 2-way unrolled) + BN stats, fp32 h out ----
__global__ void gather128_bn(const __half* __restrict__ xw, const float* __restrict__ b,
                             float* __restrict__ h, int n) {
    __shared__ float sbs[128], sbss[128];
    int tid = threadIdx.x;
    if (tid < 128) { sbs[tid] = 0.f; sbss[tid] = 0.f; }
    __syncthreads();

    int lane   = tid & 31;
    int warp   = (blockIdx.x * blockDim.x + tid) >> 5;
    int nwarps = (gridDim.x * blockDim.x) >> 5;

    float4 ps  = make_float4(0.f, 0.f, 0.f, 0.f);
    float4 pss = make_float4(0.f, 0.f, 0.f, 0.f);
    float4 bb  = ((const float4*)b)[lane];

    for (int v = warp; v < n; v += nwarps) {
        int beg = g_rowptr[v], end = g_rowptr[v + 1];
        float4 acc  = make_float4(0.f, 0.f, 0.f, 0.f);
        float4 acc2 = make_float4(0.f, 0.f, 0.f, 0.f);
        int i = beg;
        for (; i + 2 <= end; i += 2) {
            int   s0 = g_esrc[i],     s1 = g_esrc[i + 1];
            float w0 = g_enorm[i],    w1 = g_enorm[i + 1];
            uint2 r0 = ((const uint2*)(xw + (size_t)s0 * D))[lane];
            uint2 r1 = ((const uint2*)(xw + (size_t)s1 * D))[lane];
            float2 a0 = __half22float2(*reinterpret_cast<__half2*>(&r0.x));
            float2 a1 = __half22float2(*reinterpret_cast<__half2*>(&r0.y));
            float2 b0f = __half22float2(*reinterpret_cast<__half2*>(&r1.x));
            float2 b1f = __half22float2(*reinterpret_cast<__half2*>(&r1.y));
            acc.x  = fmaf(a0.x,  w0, acc.x);
            acc.y  = fmaf(a0.y,  w0, acc.y);
            acc.z  = fmaf(a1.x,  w0, acc.z);
            acc.w  = fmaf(a1.y,  w0, acc.w);
            acc2.x = fmaf(b0f.x, w1, acc2.x);
            acc2.y = fmaf(b0f.y, w1, acc2.y);
            acc2.z = fmaf(b1f.x, w1, acc2.z);
            acc2.w = fmaf(b1f.y, w1, acc2.w);
        }
        if (i < end) {
            int   s0 = g_esrc[i];
            float w0 = g_enorm[i];
            uint2 r0 = ((const uint2*)(xw + (size_t)s0 * D))[lane];
            float2 a0 = __half22float2(*reinterpret_cast<__half2*>(&r0.x));
            float2 a1 = __half22float2(*reinterpret_cast<__half2*>(&r0.y));
            acc.x = fmaf(a0.x, w0, acc.x);
            acc.y = fmaf(a0.y, w0, acc.y);
            acc.z = fmaf(a1.x, w0, acc.z);
            acc.w = fmaf(a1.y, w0, acc.w);
        }
        acc.x += acc2.x; acc.y += acc2.y; acc.z += acc2.z; acc.w += acc2.w;

        float di  = g_dinv[v];
        float di2 = di * di;
        uint2 rv = ((const uint2*)(xw + (size_t)v * D))[lane];
        float2 f0 = __half22float2(*reinterpret_cast<__half2*>(&rv.x));
        float2 f1 = __half22float2(*reinterpret_cast<__half2*>(&rv.y));
        acc.x = fmaf(f0.x, di2, acc.x) + bb.x;
        acc.y = fmaf(f0.y, di2, acc.y) + bb.y;
        acc.z = fmaf(f1.x, di2, acc.z) + bb.z;
        acc.w = fmaf(f1.y, di2, acc.w) + bb.w;
        ((float4*)(h + (size_t)v * D))[lane] = acc;
        ps.x += acc.x; ps.y += acc.y; ps.z += acc.z; ps.w += acc.w;
        pss.x = fmaf(acc.x, acc.x, pss.x);
        pss.y = fmaf(acc.y, acc.y, pss.y);
        pss.z = fmaf(acc.z, acc.z, pss.z);
        pss.w = fmaf(acc.w, acc.w, pss.w);
    }

    atomicAdd(&sbs[lane * 4 + 0], ps.x);
    atomicAdd(&sbs[lane * 4 + 1], ps.y);
    atomicAdd(&sbs[lane * 4 + 2], ps.z);
    atomicAdd(&sbs[lane * 4 + 3], ps.w);
    atomicAdd(&sbss[lane * 4 + 0], pss.x);
    atomicAdd(&sbss[lane * 4 + 1], pss.y);
    atomicAdd(&sbss[lane * 4 + 2], pss.z);
    atomicAdd(&sbss[lane * 4 + 3], pss.w);
    __syncthreads();
    if (tid < 128) {
        atomicAdd(&g_bnsum[tid],   sbs[tid]);
        atomicAdd(&g_bnsumsq[tid], sbss[tid]);
    }
}

__global__ void bn_final(const float* __restrict__ g, const float* __restrict__ be,
                         float fn) {
    int c = threadIdx.x;
    float mean = g_bnsum[c] / fn;
    float var  = g_bnsumsq[c] / fn - mean * mean;
    float sc   = g[c] * rsqrtf(var + 1e-5f);
    g_scale[c] = sc;
    g_shift[c] = be[c] - mean * sc;
    g_bnsum[c] = 0.f;
    g_bnsumsq[c] = 0.f;
}

// ---------------- CSR gather (D=40, fp16, 2-way unrolled) + log_softmax ----------
__global__ void gather40_softmax(const __half* __restrict__ xw2,
                                 const float* __restrict__ b2, float* __restrict__ out,
                                 int n) {
    int lane   = threadIdx.x & 31;
    int warp   = (blockIdx.x * blockDim.x + threadIdx.x) >> 5;
    int nwarps = (gridDim.x * blockDim.x) >> 5;

    for (int v = warp; v < n; v += nwarps) {
        int beg = g_rowptr[v], end = g_rowptr[v + 1];
        float4 acc  = make_float4(0.f, 0.f, 0.f, 0.f);
        float4 acc2 = make_float4(0.f, 0.f, 0.f, 0.f);
        if (lane < 10) {
            int i = beg;
            for (; i + 2 <= end; i += 2) {
                int   s0 = g_esrc[i],  s1 = g_esrc[i + 1];
                float w0 = g_enorm[i], w1 = g_enorm[i + 1];
                uint2 r0 = ((const uint2*)(xw2 + (size_t)s0 * DOUT))[lane];
                uint2 r1 = ((const uint2*)(xw2 + (size_t)s1 * DOUT))[lane];
                float2 a0 = __half22float2(*reinterpret_cast<__half2*>(&r0.x));
                float2 a1 = __half22float2(*reinterpret_cast<__half2*>(&r0.y));
                float2 c0 = __half22float2(*reinterpret_cast<__half2*>(&r1.x));
                float2 c1 = __half22float2(*reinterpret_cast<__half2*>(&r1.y));
                acc.x  = fmaf(a0.x, w0, acc.x);
                acc.y  = fmaf(a0.y, w0, acc.y);
                acc.z  = fmaf(a1.x, w0, acc.z);
                acc.w  = fmaf(a1.y, w0, acc.w);
                acc2.x = fmaf(c0.x, w1, acc2.x);
                acc2.y = fmaf(c0.y, w1, acc2.y);
                acc2.z = fmaf(c1.x, w1, acc2.z);
                acc2.w = fmaf(c1.y, w1, acc2.w);
            }
            if (i < end) {
                int   s0 = g_esrc[i];
                float w0 = g_enorm[i];
                uint2 r0 = ((const uint2*)(xw2 + (size_t)s0 * DOUT))[lane];
                float2 a0 = __half22float2(*reinterpret_cast<__half2*>(&r0.x));
                float2 a1 = __half22float2(*reinterpret_cast<__half2*>(&r0.y));
                acc.x = fmaf(a0.x, w0, acc.x);
                acc.y = fmaf(a0.y, w0, acc.y);
                acc.z = fmaf(a1.x, w0, acc.z);
                acc.w = fmaf(a1.y, w0, acc.w);
            }
            acc.x += acc2.x; acc.y += acc2.y; acc.z += acc2.z; acc.w += acc2.w;

            float di  = g_dinv[v];
            float di2 = di * di;
            uint2 rv = ((const uint2*)(xw2 + (size_t)v * DOUT))[lane];
            float2 f0 = __half22float2(*reinterpret_cast<__half2*>(&rv.x));
            float2 f1 = __half22float2(*reinterpret_cast<__half2*>(&rv.y));
            float4 bb = ((const float4*)b2)[lane];
            acc.x = fmaf(f0.x, di2, acc.x) + bb.x;
            acc.y = fmaf(f0.y, di2, acc.y) + bb.y;
            acc.z = fmaf(f1.x, di2, acc.z) + bb.z;
            acc.w = fmaf(f1.y, di2, acc.w) + bb.w;
        }
        float m = (lane < 10)
                ? fmaxf(fmaxf(acc.x, acc.y), fmaxf(acc.z, acc.w)) : -1e30f;
        #pragma unroll
        for (int o = 16; o; o >>= 1) m = fmaxf(m, __shfl_xor_sync(0xffffffffu, m, o));
        float s = (lane < 10)
                ? (expf(acc.x - m) + expf(acc.y - m) + expf(acc.z - m) + expf(acc.w - m))
                : 0.f;
        #pragma unroll
        for (int o = 16; o; o >>= 1) s += __shfl_xor_sync(0xffffffffu, s, o);
        float lse = m + logf(s);
        if (lane < 10)
            ((float4*)(out + (size_t)v * DOUT))[lane] =
                make_float4(acc.x - lse, acc.y - lse, acc.z - lse, acc.w - lse);
    }
}

// ---------------- launch ----------------
extern "C" void kernel_launch(void* const* d_in, const int* in_sizes, int n_in,
                              void* d_out, int out_size) {
    const float* x   = (const float*)d_in[0];
    const void*  ei  = d_in[1];
    const float* ew  = (const float*)d_in[2];
    const float* W0  = (const float*)d_in[3];
    const float* b0  = (const float*)d_in[4];
    const float* g0  = (const float*)d_in[5];
    const float* be0 = (const float*)d_in[6];
    const float* W1  = (const float*)d_in[7];
    const float* b1  = (const float*)d_in[8];
    const float* g1  = (const float*)d_in[9];
    const float* be1 = (const float*)d_in[10];
    const float* W2  = (const float*)d_in[11];
    const float* b2  = (const float*)d_in[12];

    int n = in_sizes[0] / D;
    int E = in_sizes[2];
    int twoE = 2 * E;

    cudaFuncSetAttribute(gemm128t<false>, cudaFuncAttributeMaxDynamicSharedMemorySize, GEMM_SMEM);
    cudaFuncSetAttribute(gemm128t<true>,  cudaFuncAttributeMaxDynamicSharedMemorySize, GEMM_SMEM);

    void *p_deg, *p_cnt, *p_fill, *p_bns, *p_bnss, *p_xw, *p_h, *p_xw2;
    cudaGetSymbolAddress(&p_deg,  g_deg);
    cudaGetSymbolAddress(&p_cnt,  g_cnt);
    cudaGetSymbolAddress(&p_fill, g_fill);
    cudaGetSymbolAddress(&p_bns,  g_bnsum);
    cudaGetSymbolAddress(&p_bnss, g_bnsumsq);
    cudaGetSymbolAddress(&p_xw,   g_xw);
    cudaGetSymbolAddress(&p_h,    g_h);
    cudaGetSymbolAddress(&p_xw2,  g_xw2);
    __half* xw  = (__half*)p_xw;
    float*  h   = (float*)p_h;
    __half* xw2 = (__half*)p_xw2;

    const int T = 256;
    int nb_scan = cdiv(n, 512);
    int gather_blocks = 1184;

    // fork/join: CSR build (s2) overlapped with layer-0 GEMM (s0).
    cudaStream_t s2;
    cudaEvent_t evF, evJ;
    cudaStreamCreateWithFlags(&s2, cudaStreamNonBlocking);
    cudaEventCreateWithFlags(&evF, cudaEventDisableTiming);
    cudaEventCreateWithFlags(&evJ, cudaEventDisableTiming);

    cudaEventRecord(evF, 0);
    cudaStreamWaitEvent(s2, evF, 0);

    // ---- branch A (s2): zero + convert + CSR build ----
    cudaMemsetAsync(p_deg,  0, (size_t)n * sizeof(float), s2);
    cudaMemsetAsync(p_cnt,  0, (size_t)n * sizeof(int), s2);
    cudaMemsetAsync(p_fill, 0, (size_t)n * sizeof(int), s2);
    cudaMemsetAsync(p_bns,  0, 128 * sizeof(float), s2);
    cudaMemsetAsync(p_bnss, 0, 128 * sizeof(float), s2);
    detect_kernel<<<1, 32, 0, s2>>>((const unsigned*)ei, twoE);
    convert_deg_kernel<<<cdiv(twoE, T), T, 0, s2>>>(ei, ew, E);
    scan1<<<nb_scan, 512, 0, s2>>>(n);
    scan2<<<1, 256, 0, s2>>>(nb_scan);
    scan3<<<cdiv(n, T), T, 0, s2>>>(n, E);
    fill_kernel<<<cdiv(E, T), T, 0, s2>>>(ew, E);
    cudaEventRecord(evJ, s2);

    // ---- branch B (stream 0): layer-0 GEMM (tensor cores) ----
    gemm128t<false><<<cdiv(n, 128), T, GEMM_SMEM>>>(x, W0, xw, n);

    // join
    cudaStreamWaitEvent(0, evJ, 0);

    // ---- layer 0 aggregate ----
    gather128_bn<<<gather_blocks, T>>>(xw, b0, h, n);
    bn_final<<<1, 128>>>(g0, be0, (float)n);

    // ---- layer 1 ----
    gemm128t<true><<<cdiv(n, 128), T, GEMM_SMEM>>>(h, W1, xw, n);
    gather128_bn<<<gather_blocks, T>>>(xw, b1, h, n);
    bn_final<<<1, 128>>>(g1, be1, (float)n);

    // ---- layer 2 + log_softmax ----
    gemm40<<<cdiv(n, 32), T>>>(h, W2, xw2, n);
    gather40_softmax<<<gather_blocks, T>>>(xw2, b2, (float*)d_out, n);

    cudaEventDestroy(evF);
    cudaEventDestroy(evJ);
    cudaStreamDestroy(s2);
}

// round 12
// speedup vs baseline: 1.5692x; 1.1278x over previous
#include <cuda_runtime.h>
#include <cuda_fp16.h>
#include <mma.h>
#include <math.h>

using namespace nvcuda;

#define D    128
#define DOUT 40
#define NMAX 100000
#define EMAX 1600000

typedef unsigned long long ull;

static inline int cdiv(int a, int b) { return (a + b - 1) / b; }

// ---------------- scratch (static device globals; no allocation) ----------------
__device__ __align__(16) __half g_xw [(size_t)NMAX * D];    // fp16 gather operand
__device__ __align__(16) __half g_h  [(size_t)NMAX * D];    // fp16 hidden activations
__device__ __align__(16) __half g_xw2[(size_t)NMAX * DOUT]; // fp16 final-layer operand
__device__ float g_deg [NMAX];
__device__ float g_dinv[NMAX];
__device__ int   g_idx [2 * EMAX];
__device__ int   g_is64;
// CSR
__device__ int   g_cnt [NMAX];
__device__ int   g_rowptr[NMAX + 1];
__device__ int   g_fill[NMAX];
__device__ int   g_bsum[256];
__device__ int   g_boff[256];
__device__ int   g_esrc [EMAX];
__device__ float g_enorm[EMAX];
// BN
__device__ __align__(16) float g_bnsum  [128];
__device__ __align__(16) float g_bnsumsq[128];
__device__ __align__(16) float g_scale  [128];
__device__ __align__(16) float g_shift  [128];

// ---------------- index dtype detect ----------------
__global__ void detect_kernel(const unsigned* __restrict__ w, int twoE) {
    if (threadIdx.x == 0 && blockIdx.x == 0) {
        int nchk = twoE < 256 ? twoE : 256;
        int is64 = 1;
        for (int i = 0; i < nchk; i++)
            if (w[2 * i + 1] != 0u) { is64 = 0; break; }
        g_is64 = is64;
    }
}

// ---------------- convert + degree/histogram (fused) ----------------
__global__ void convert_deg_kernel(const void* __restrict__ ei,
                                   const float* __restrict__ ew, int E) {
    int i = blockIdx.x * blockDim.x + threadIdx.x;
    int twoE = 2 * E;
    if (i < twoE) {
        int v;
        if (g_is64) v = (int)((const long long*)ei)[i];
        else        v = ((const int*)ei)[i];
        g_idx[i] = v;
        if (i >= E) {
            atomicAdd(&g_deg[v], ew[i - E]);
            atomicAdd(&g_cnt[v], 1);
        }
    }
}

// ---------------- exclusive scan of g_cnt -> g_rowptr (3-pass) ----------------
__global__ void scan1(int n) {
    __shared__ int sm[512];
    int i = blockIdx.x * 512 + threadIdx.x;
    int v = (i < n) ? g_cnt[i] : 0;
    sm[threadIdx.x] = v;
    __syncthreads();
    #pragma unroll
    for (int o = 1; o < 512; o <<= 1) {
        int t = (threadIdx.x >= o) ? sm[threadIdx.x - o] : 0;
        __syncthreads();
        sm[threadIdx.x] += t;
        __syncthreads();
    }
    if (i < n) g_rowptr[i] = sm[threadIdx.x] - v;
    if (threadIdx.x == 511) g_bsum[blockIdx.x] = sm[511];
}

__global__ void scan2(int nb) {
    __shared__ int sm[256];
    int v = (threadIdx.x < nb) ? g_bsum[threadIdx.x] : 0;
    sm[threadIdx.x] = v;
    __syncthreads();
    #pragma unroll
    for (int o = 1; o < 256; o <<= 1) {
        int t = (threadIdx.x >= o) ? sm[threadIdx.x - o] : 0;
        __syncthreads();
        sm[threadIdx.x] += t;
        __syncthreads();
    }
    if (threadIdx.x < nb) g_boff[threadIdx.x] = sm[threadIdx.x] - v;
}

__global__ void scan3(int n, int E) {
    int i = blockIdx.x * blockDim.x + threadIdx.x;
    if (i < n) {
        g_rowptr[i] += g_boff[i >> 9];
        g_dinv[i] = rsqrtf(g_deg[i] + 1.0f);
    }
    if (i == 0) g_rowptr[n] = E;
}

// ---------------- CSR fill ----------------
__global__ void fill_kernel(const float* __restrict__ ew, int E) {
    int e = blockIdx.x * blockDim.x + threadIdx.x;
    if (e < E) {
        int s = g_idx[e];
        int d = g_idx[E + e];
        int pos = g_rowptr[d] + atomicAdd(&g_fill[d], 1);
        g_esrc[pos]  = s;
        g_enorm[pos] = g_dinv[s] * ew[e] * g_dinv[d];
    }
}

// ---------------- fused BN+ReLU on load ----------------
__device__ __forceinline__ float4 bnrelu4(float4 v, int c4) {
    float4 sc = ((const float4*)g_scale)[c4];
    float4 sh = ((const float4*)g_shift)[c4];
    v.x = fmaxf(fmaf(v.x, sc.x, sh.x), 0.0f);
    v.y = fmaxf(fmaf(v.y, sc.y, sh.y), 0.0f);
    v.z = fmaxf(fmaf(v.z, sc.z, sh.z), 0.0f);
    v.w = fmaxf(fmaf(v.w, sc.w, sh.w), 0.0f);
    return v;
}

// ---------------- tensor-core GEMM 128x128 ----------------
// Layer 0: fp32 A in. Layer 1: fp16 A in + BN+ReLU. fp16 out.
#define SKH 136
#define GEMM_SMEM (128 * SKH * 4)   // 69632 B

template <bool FUSE_BN>
__global__ void __launch_bounds__(256) gemm128t(const float* __restrict__ Af,
                                                const __half* __restrict__ Ah,
                                                const float* __restrict__ W,
                                                __half* __restrict__ C, int n) {
    extern __shared__ char smem[];
    __half* sA = (__half*)smem;              // [128][SKH]
    __half* sB = sA + 128 * SKH;             // [128][SKH]
    float*  sC = (float*)smem;               // [128][SKH] (reused)

    int tid = threadIdx.x;
    int row0 = blockIdx.x * 128;

    // W[k][n] fp32 -> sB fp16
    const float4* W4 = (const float4*)W;
    #pragma unroll
    for (int i = tid; i < 4096; i += 256) {
        int r = i >> 5, c4 = i & 31;
        float4 v = W4[i];
        __half2* dst = (__half2*)(sB + r * SKH + c4 * 4);
        dst[0] = __floats2half2_rn(v.x, v.y);
        dst[1] = __floats2half2_rn(v.z, v.w);
    }

    // A rows -> sA fp16 (fp32 source for layer 0; fp16 + BN+ReLU for layer 1)
    if (FUSE_BN) {
        const uint2* A2 = (const uint2*)(Ah + (size_t)row0 * D);
        #pragma unroll
        for (int i = tid; i < 4096; i += 256) {
            int r = i >> 5, c4 = i & 31;
            float4 v = make_float4(0.f, 0.f, 0.f, 0.f);
            if (row0 + r < n) {
                uint2 rv = A2[i];
                float2 f0 = __half22float2(*reinterpret_cast<__half2*>(&rv.x));
                float2 f1 = __half22float2(*reinterpret_cast<__half2*>(&rv.y));
                v = bnrelu4(make_float4(f0.x, f0.y, f1.x, f1.y), c4);
            }
            __half2* dst = (__half2*)(sA + r * SKH + c4 * 4);
            dst[0] = __floats2half2_rn(v.x, v.y);
            dst[1] = __floats2half2_rn(v.z, v.w);
        }
    } else {
        const float4* A4 = (const float4*)Af + (size_t)row0 * 32;
        #pragma unroll
        for (int i = tid; i < 4096; i += 256) {
            int r = i >> 5, c4 = i & 31;
            float4 v = make_float4(0.f, 0.f, 0.f, 0.f);
            if (row0 + r < n) v = A4[i];
            __half2* dst = (__half2*)(sA + r * SKH + c4 * 4);
            dst[0] = __floats2half2_rn(v.x, v.y);
            dst[1] = __floats2half2_rn(v.z, v.w);
        }
    }
    __syncthreads();

    int warp = tid >> 5;
    int wr = warp & 3;
    int wc = warp >> 2;

    wmma::fragment<wmma::accumulator, 16, 16, 16, float> acc[2][4];
    #pragma unroll
    for (int i = 0; i < 2; i++)
        #pragma unroll
        for (int j = 0; j < 4; j++) wmma::fill_fragment(acc[i][j], 0.0f);

    #pragma unroll
    for (int ks = 0; ks < 8; ks++) {
        wmma::fragment<wmma::matrix_a, 16, 16, 16, __half, wmma::row_major> af[2];
        wmma::load_matrix_sync(af[0], sA + (wr * 32 +  0) * SKH + ks * 16, SKH);
        wmma::load_matrix_sync(af[1], sA + (wr * 32 + 16) * SKH + ks * 16, SKH);
        wmma::fragment<wmma::matrix_b, 16, 16, 16, __half, wmma::row_major> bf[4];
        #pragma unroll
        for (int j = 0; j < 4; j++)
            wmma::load_matrix_sync(bf[j], sB + (ks * 16) * SKH + wc * 64 + j * 16, SKH);
        #pragma unroll
        for (int i = 0; i < 2; i++)
            #pragma unroll
            for (int j = 0; j < 4; j++)
                wmma::mma_sync(acc[i][j], af[i], bf[j], acc[i][j]);
    }
    __syncthreads();

    #pragma unroll
    for (int i = 0; i < 2; i++)
        #pragma unroll
        for (int j = 0; j < 4; j++)
            wmma::store_matrix_sync(sC + (wr * 32 + i * 16) * SKH + wc * 64 + j * 16,
                                    acc[i][j], SKH, wmma::mem_row_major);
    __syncthreads();

    #pragma unroll
    for (int i = tid; i < 4096; i += 256) {
        int r = i >> 5, c4 = i & 31;
        if (row0 + r < n) {
            float4 v = *(const float4*)(sC + r * SKH + c4 * 4);
            uint2 o;
            __half2 hh;
            hh = __floats2half2_rn(v.x, v.y);
            o.x = *reinterpret_cast<unsigned*>(&hh);
            hh = __floats2half2_rn(v.z, v.w);
            o.y = *reinterpret_cast<unsigned*>(&hh);
            ((uint2*)(C + (size_t)(row0 + r) * D))[c4] = o;
        }
    }
}

// ---------------- tensor-core GEMM 128->40 (fp16 in + BN+ReLU, fp16 out) ---------
// 128-row tile, W2 padded to 48 cols. 8 warps: each 16 rows x 48 cols (1x3 frags).
#define SB40 48
#define GEMM40_SMEM (128 * SKH * 2 + 128 * SB40 * 2)   // 34816 + 12288 = 47104 B

__global__ void __launch_bounds__(256) gemm40t(const __half* __restrict__ A,
                                               const float* __restrict__ W,
                                               __half* __restrict__ C, int n) {
    extern __shared__ char smem[];
    __half* sA = (__half*)smem;              // [128][SKH]
    __half* sB = sA + 128 * SKH;             // [128][SB40]
    float*  sC = (float*)smem;               // [128][SB40] fp32 staging (24KB < 34KB)

    int tid = threadIdx.x;
    int row0 = blockIdx.x * 128;

    // W2[k][0..39] fp32 -> sB fp16, cols 40..47 zero
    #pragma unroll
    for (int i = tid; i < 128 * SB40; i += 256) {
        int r = i / SB40, c = i % SB40;
        float v = (c < DOUT) ? W[r * DOUT + c] : 0.f;
        sB[r * SB40 + c] = __float2half_rn(v);
    }

    // A rows fp16 + BN+ReLU -> sA fp16
    const uint2* A2 = (const uint2*)(A + (size_t)row0 * D);
    #pragma unroll
    for (int i = tid; i < 4096; i += 256) {
        int r = i >> 5, c4 = i & 31;
        float4 v = make_float4(0.f, 0.f, 0.f, 0.f);
        if (row0 + r < n) {
            uint2 rv = A2[i];
            float2 f0 = __half22float2(*reinterpret_cast<__half2*>(&rv.x));
            float2 f1 = __half22float2(*reinterpret_cast<__half2*>(&rv.y));
            v = bnrelu4(make_float4(f0.x, f0.y, f1.x, f1.y), c4);
        }
        __half2* dst = (__half2*)(sA + r * SKH + c4 * 4);
        dst[0] = __floats2half2_rn(v.x, v.y);
        dst[1] = __floats2half2_rn(v.z, v.w);
    }
    __syncthreads();

    int warp = tid >> 5;   // 0..7, 16 rows each

    wmma::fragment<wmma::accumulator, 16, 16, 16, float> acc[3];
    #pragma unroll
    for (int j = 0; j < 3; j++) wmma::fill_fragment(acc[j], 0.0f);

    #pragma unroll
    for (int ks = 0; ks < 8; ks++) {
        wmma::fragment<wmma::matrix_a, 16, 16, 16, __half, wmma::row_major> af;
        wmma::load_matrix_sync(af, sA + (warp * 16) * SKH + ks * 16, SKH);
        #pragma unroll
        for (int j = 0; j < 3; j++) {
            wmma::fragment<wmma::matrix_b, 16, 16, 16, __half, wmma::row_major> bf;
            wmma::load_matrix_sync(bf, sB + (ks * 16) * SB40 + j * 16, SB40);
            wmma::mma_sync(acc[j], af, bf, acc[j]);
        }
    }
    __syncthreads();

    #pragma unroll
    for (int j = 0; j < 3; j++)
        wmma::store_matrix_sync(sC + (warp * 16) * SB40 + j * 16, acc[j],
                                SB40, wmma::mem_row_major);
    __syncthreads();

    // emit cols 0..39 fp16 (20 uints per row)
    #pragma unroll
    for (int i = tid; i < 128 * 20; i += 256) {
        int r = i / 20, cu = i % 20;           // cu indexes pairs of cols
        if (row0 + r < n) {
            float2 v = *(const float2*)(sC + r * SB40 + cu * 2);
            __half2 hh = __floats2half2_rn(v.x, v.y);
            ((unsigned*)(C + (size_t)(row0 + r) * DOUT))[cu] =
                *reinterpret_cast<unsigned*>(&hh);
        }
    }
}

// ---------------- CSR gather (fp16 in, 2-way unrolled) + BN stats, fp16 h out ----
__global__ void gather128_bn(const __half* __restrict__ xw, const float* __restrict__ b,
                             __half* __restrict__ h, int n) {
    __shared__ float sbs[128], sbss[128];
    int tid = threadIdx.x;
    if (tid < 128) { sbs[tid] = 0.f; sbss[tid] = 0.f; }
    __syncthreads();

    int lane   = tid & 31;
    int warp   = (blockIdx.x * blockDim.x + tid) >> 5;
    int nwarps = (gridDim.x * blockDim.x) >> 5;

    float4 ps  = make_float4(0.f, 0.f, 0.f, 0.f);
    float4 pss = make_float4(0.f, 0.f, 0.f, 0.f);
    float4 bb  = ((const float4*)b)[lane];

    for (int v = warp; v < n; v += nwarps) {
        int beg = g_rowptr[v], end = g_rowptr[v + 1];
        float4 acc  = make_float4(0.f, 0.f, 0.f, 0.f);
        float4 acc2 = make_float4(0.f, 0.f, 0.f, 0.f);
        int i = beg;
        for (; i + 2 <= end; i += 2) {
            int   s0 = g_esrc[i],     s1 = g_esrc[i + 1];
            float w0 = g_enorm[i],    w1 = g_enorm[i + 1];
            uint2 r0 = ((const uint2*)(xw + (size_t)s0 * D))[lane];
            uint2 r1 = ((const uint2*)(xw + (size_t)s1 * D))[lane];
            float2 a0 = __half22float2(*reinterpret_cast<__half2*>(&r0.x));
            float2 a1 = __half22float2(*reinterpret_cast<__half2*>(&r0.y));
            float2 b0f = __half22float2(*reinterpret_cast<__half2*>(&r1.x));
            float2 b1f = __half22float2(*reinterpret_cast<__half2*>(&r1.y));
            acc.x  = fmaf(a0.x,  w0, acc.x);
            acc.y  = fmaf(a0.y,  w0, acc.y);
            acc.z  = fmaf(a1.x,  w0, acc.z);
            acc.w  = fmaf(a1.y,  w0, acc.w);
            acc2.x = fmaf(b0f.x, w1, acc2.x);
            acc2.y = fmaf(b0f.y, w1, acc2.y);
            acc2.z = fmaf(b1f.x, w1, acc2.z);
            acc2.w = fmaf(b1f.y, w1, acc2.w);
        }
        if (i < end) {
            int   s0 = g_esrc[i];
            float w0 = g_enorm[i];
            uint2 r0 = ((const uint2*)(xw + (size_t)s0 * D))[lane];
            float2 a0 = __half22float2(*reinterpret_cast<__half2*>(&r0.x));
            float2 a1 = __half22float2(*reinterpret_cast<__half2*>(&r0.y));
            acc.x = fmaf(a0.x, w0, acc.x);
            acc.y = fmaf(a0.y, w0, acc.y);
            acc.z = fmaf(a1.x, w0, acc.z);
            acc.w = fmaf(a1.y, w0, acc.w);
        }
        acc.x += acc2.x; acc.y += acc2.y; acc.z += acc2.z; acc.w += acc2.w;

        float di  = g_dinv[v];
        float di2 = di * di;
        uint2 rv = ((const uint2*)(xw + (size_t)v * D))[lane];
        float2 f0 = __half22float2(*reinterpret_cast<__half2*>(&rv.x));
        float2 f1 = __half22float2(*reinterpret_cast<__half2*>(&rv.y));
        acc.x = fmaf(f0.x, di2, acc.x) + bb.x;
        acc.y = fmaf(f0.y, di2, acc.y) + bb.y;
        acc.z = fmaf(f1.x, di2, acc.z) + bb.z;
        acc.w = fmaf(f1.y, di2, acc.w) + bb.w;

        uint2 o;
        __half2 hh;
        hh = __floats2half2_rn(acc.x, acc.y);
        o.x = *reinterpret_cast<unsigned*>(&hh);
        hh = __floats2half2_rn(acc.z, acc.w);
        o.y = *reinterpret_cast<unsigned*>(&hh);
        ((uint2*)(h + (size_t)v * D))[lane] = o;

        ps.x += acc.x; ps.y += acc.y; ps.z += acc.z; ps.w += acc.w;
        pss.x = fmaf(acc.x, acc.x, pss.x);
        pss.y = fmaf(acc.y, acc.y, pss.y);
        pss.z = fmaf(acc.z, acc.z, pss.z);
        pss.w = fmaf(acc.w, acc.w, pss.w);
    }

    atomicAdd(&sbs[lane * 4 + 0], ps.x);
    atomicAdd(&sbs[lane * 4 + 1], ps.y);
    atomicAdd(&sbs[lane * 4 + 2], ps.z);
    atomicAdd(&sbs[lane * 4 + 3], ps.w);
    atomicAdd(&sbss[lane * 4 + 0], pss.x);
    atomicAdd(&sbss[lane * 4 + 1], pss.y);
    atomicAdd(&sbss[lane * 4 + 2], pss.z);
    atomicAdd(&sbss[lane * 4 + 3], pss.w);
    __syncthreads();
    if (tid < 128) {
        atomicAdd(&g_bnsum[tid],   sbs[tid]);
        atomicAdd(&g_bnsumsq[tid], sbss[tid]);
    }
}

__global__ void bn_final(const float* __restrict__ g, const float* __restrict__ be,
                         float fn) {
    int c = threadIdx.x;
    float mean = g_bnsum[c] / fn;
    float var  = g_bnsumsq[c] / fn - mean * mean;
    float sc   = g[c] * rsqrtf(var + 1e-5f);
    g_scale[c] = sc;
    g_shift[c] = be[c] - mean * sc;
    g_bnsum[c] = 0.f;
    g_bnsumsq[c] = 0.f;
}

// ---------------- CSR gather (D=40, fp16, 2-way unrolled) + log_softmax ----------
__global__ void gather40_softmax(const __half* __restrict__ xw2,
                                 const float* __restrict__ b2, float* __restrict__ out,
                                 int n) {
    int lane   = threadIdx.x & 31;
    int warp   = (blockIdx.x * blockDim.x + threadIdx.x) >> 5;
    int nwarps = (gridDim.x * blockDim.x) >> 5;

    for (int v = warp; v < n; v += nwarps) {
        int beg = g_rowptr[v], end = g_rowptr[v + 1];
        float4 acc  = make_float4(0.f, 0.f, 0.f, 0.f);
        float4 acc2 = make_float4(0.f, 0.f, 0.f, 0.f);
        if (lane < 10) {
            int i = beg;
            for (; i + 2 <= end; i += 2) {
                int   s0 = g_esrc[i],  s1 = g_esrc[i + 1];
                float w0 = g_enorm[i], w1 = g_enorm[i + 1];
                uint2 r0 = ((const uint2*)(xw2 + (size_t)s0 * DOUT))[lane];
                uint2 r1 = ((const uint2*)(xw2 + (size_t)s1 * DOUT))[lane];
                float2 a0 = __half22float2(*reinterpret_cast<__half2*>(&r0.x));
                float2 a1 = __half22float2(*reinterpret_cast<__half2*>(&r0.y));
                float2 c0 = __half22float2(*reinterpret_cast<__half2*>(&r1.x));
                float2 c1 = __half22float2(*reinterpret_cast<__half2*>(&r1.y));
                acc.x  = fmaf(a0.x, w0, acc.x);
                acc.y  = fmaf(a0.y, w0, acc.y);
                acc.z  = fmaf(a1.x, w0, acc.z);
                acc.w  = fmaf(a1.y, w0, acc.w);
                acc2.x = fmaf(c0.x, w1, acc2.x);
                acc2.y = fmaf(c0.y, w1, acc2.y);
                acc2.z = fmaf(c1.x, w1, acc2.z);
                acc2.w = fmaf(c1.y, w1, acc2.w);
            }
            if (i < end) {
                int   s0 = g_esrc[i];
                float w0 = g_enorm[i];
                uint2 r0 = ((const uint2*)(xw2 + (size_t)s0 * DOUT))[lane];
                float2 a0 = __half22float2(*reinterpret_cast<__half2*>(&r0.x));
                float2 a1 = __half22float2(*reinterpret_cast<__half2*>(&r0.y));
                acc.x = fmaf(a0.x, w0, acc.x);
                acc.y = fmaf(a0.y, w0, acc.y);
                acc.z = fmaf(a1.x, w0, acc.z);
                acc.w = fmaf(a1.y, w0, acc.w);
            }
            acc.x += acc2.x; acc.y += acc2.y; acc.z += acc2.z; acc.w += acc2.w;

            float di  = g_dinv[v];
            float di2 = di * di;
            uint2 rv = ((const uint2*)(xw2 + (size_t)v * DOUT))[lane];
            float2 f0 = __half22float2(*reinterpret_cast<__half2*>(&rv.x));
            float2 f1 = __half22float2(*reinterpret_cast<__half2*>(&rv.y));
            float4 bb = ((const float4*)b2)[lane];
            acc.x = fmaf(f0.x, di2, acc.x) + bb.x;
            acc.y = fmaf(f0.y, di2, acc.y) + bb.y;
            acc.z = fmaf(f1.x, di2, acc.z) + bb.z;
            acc.w = fmaf(f1.y, di2, acc.w) + bb.w;
        }
        float m = (lane < 10)
                ? fmaxf(fmaxf(acc.x, acc.y), fmaxf(acc.z, acc.w)) : -1e30f;
        #pragma unroll
        for (int o = 16; o; o >>= 1) m = fmaxf(m, __shfl_xor_sync(0xffffffffu, m, o));
        float s = (lane < 10)
                ? (expf(acc.x - m) + expf(acc.y - m) + expf(acc.z - m) + expf(acc.w - m))
                : 0.f;
        #pragma unroll
        for (int o = 16; o; o >>= 1) s += __shfl_xor_sync(0xffffffffu, s, o);
        float lse = m + logf(s);
        if (lane < 10)
            ((float4*)(out + (size_t)v * DOUT))[lane] =
                make_float4(acc.x - lse, acc.y - lse, acc.z - lse, acc.w - lse);
    }
}

// ---------------- launch ----------------
extern "C" void kernel_launch(void* const* d_in, const int* in_sizes, int n_in,
                              void* d_out, int out_size) {
    const float* x   = (const float*)d_in[0];
    const void*  ei  = d_in[1];
    const float* ew  = (const float*)d_in[2];
    const float* W0  = (const float*)d_in[3];
    const float* b0  = (const float*)d_in[4];
    const float* g0  = (const float*)d_in[5];
    const float* be0 = (const float*)d_in[6];
    const float* W1  = (const float*)d_in[7];
    const float* b1  = (const float*)d_in[8];
    const float* g1  = (const float*)d_in[9];
    const float* be1 = (const float*)d_in[10];
    const float* W2  = (const float*)d_in[11];
    const float* b2  = (const float*)d_in[12];

    int n = in_sizes[0] / D;
    int E = in_sizes[2];
    int twoE = 2 * E;

    cudaFuncSetAttribute(gemm128t<false>, cudaFuncAttributeMaxDynamicSharedMemorySize, GEMM_SMEM);
    cudaFuncSetAttribute(gemm128t<true>,  cudaFuncAttributeMaxDynamicSharedMemorySize, GEMM_SMEM);
    cudaFuncSetAttribute(gemm40t, cudaFuncAttributeMaxDynamicSharedMemorySize, GEMM40_SMEM);

    void *p_deg, *p_cnt, *p_fill, *p_bns, *p_bnss, *p_xw, *p_h, *p_xw2;
    cudaGetSymbolAddress(&p_deg,  g_deg);
    cudaGetSymbolAddress(&p_cnt,  g_cnt);
    cudaGetSymbolAddress(&p_fill, g_fill);
    cudaGetSymbolAddress(&p_bns,  g_bnsum);
    cudaGetSymbolAddress(&p_bnss, g_bnsumsq);
    cudaGetSymbolAddress(&p_xw,   g_xw);
    cudaGetSymbolAddress(&p_h,    g_h);
    cudaGetSymbolAddress(&p_xw2,  g_xw2);
    __half* xw  = (__half*)p_xw;
    __half* h   = (__half*)p_h;
    __half* xw2 = (__half*)p_xw2;

    const int T = 256;
    int nb_scan = cdiv(n, 512);
    int gather_blocks = 1184;

    // fork/join: CSR build (s2) overlapped with layer-0 GEMM (s0).
    cudaStream_t s2;
    cudaEvent_t evF, evJ;
    cudaStreamCreateWithFlags(&s2, cudaStreamNonBlocking);
    cudaEventCreateWithFlags(&evF, cudaEventDisableTiming);
    cudaEventCreateWithFlags(&evJ, cudaEventDisableTiming);

    cudaEventRecord(evF, 0);
    cudaStreamWaitEvent(s2, evF, 0);

    // ---- branch A (s2): zero + convert + CSR build ----
    cudaMemsetAsync(p_deg,  0, (size_t)n * sizeof(float), s2);
    cudaMemsetAsync(p_cnt,  0, (size_t)n * sizeof(int), s2);
    cudaMemsetAsync(p_fill, 0, (size_t)n * sizeof(int), s2);
    cudaMemsetAsync(p_bns,  0, 128 * sizeof(float), s2);
    cudaMemsetAsync(p_bnss, 0, 128 * sizeof(float), s2);
    detect_kernel<<<1, 32, 0, s2>>>((const unsigned*)ei, twoE);
    convert_deg_kernel<<<cdiv(twoE, T), T, 0, s2>>>(ei, ew, E);
    scan1<<<nb_scan, 512, 0, s2>>>(n);
    scan2<<<1, 256, 0, s2>>>(nb_scan);
    scan3<<<cdiv(n, T), T, 0, s2>>>(n, E);
    fill_kernel<<<cdiv(E, T), T, 0, s2>>>(ew, E);
    cudaEventRecord(evJ, s2);

    // ---- branch B (stream 0): layer-0 GEMM (tensor cores) ----
    gemm128t<false><<<cdiv(n, 128), T, GEMM_SMEM>>>(x, (const __half*)0, W0, xw, n);

    // join
    cudaStreamWaitEvent(0, evJ, 0);

    // ---- layer 0 aggregate ----
    gather128_bn<<<gather_blocks, T>>>(xw, b0, h, n);
    bn_final<<<1, 128>>>(g0, be0, (float)n);

    // ---- layer 1 ----
    gemm128t<true><<<cdiv(n, 128), T, GEMM_SMEM>>>((const float*)0, h, W1, xw, n);
    gather128_bn<<<gather_blocks, T>>>(xw, b1, h, n);
    bn_final<<<1, 128>>>(g1, be1, (float)n);

    // ---- layer 2 + log_softmax ----
    gemm40t<<<cdiv(n, 128), T, GEMM40_SMEM>>>(h, W2, xw2, n);
    gather40_softmax<<<gather_blocks, T>>>(xw2, b2, (float*)d_out, n);

    cudaEventDestroy(evF);
    cudaEventDestroy(evJ);
    cudaStreamDestroy(s2);
}

// round 13
// speedup vs baseline: 1.5794x; 1.0065x over previous
#include <cuda_runtime.h>
#include <cuda_fp16.h>
#include <mma.h>
#include <math.h>

using namespace nvcuda;

#define D    128
#define DOUT 40
#define NMAX 100000
#define EMAX 1600000

typedef unsigned long long ull;

static inline int cdiv(int a, int b) { return (a + b - 1) / b; }

// ---------------- scratch (static device globals; no allocation) ----------------
__device__ __align__(16) __half g_xw [(size_t)NMAX * D];    // fp16 gather operand
__device__ __align__(16) __half g_h  [(size_t)NMAX * D];    // fp16 hidden activations
__device__ __align__(16) __half g_xw2[(size_t)NMAX * DOUT]; // fp16 final-layer operand
__device__ float g_deg [NMAX];
__device__ float g_dinv[NMAX];
__device__ int   g_idx [2 * EMAX];
__device__ int   g_is64;
// CSR
__device__ int   g_cnt [NMAX];
__device__ int   g_rowptr[NMAX + 1];
__device__ int   g_fill[NMAX];
__device__ int   g_bsum[256];
__device__ int   g_boff[256];
__device__ __align__(8) int2 g_edge[EMAX];   // (src, norm-bits) interleaved
// BN
__device__ __align__(16) float g_bnsum  [128];
__device__ __align__(16) float g_bnsumsq[128];
__device__ __align__(16) float g_scale  [128];
__device__ __align__(16) float g_shift  [128];
__device__ int g_done;

// ---------------- index dtype detect ----------------
__global__ void detect_kernel(const unsigned* __restrict__ w, int twoE) {
    if (threadIdx.x == 0 && blockIdx.x == 0) {
        int nchk = twoE < 256 ? twoE : 256;
        int is64 = 1;
        for (int i = 0; i < nchk; i++)
            if (w[2 * i + 1] != 0u) { is64 = 0; break; }
        g_is64 = is64;
    }
}

// ---------------- convert + degree/histogram (fused) ----------------
__global__ void convert_deg_kernel(const void* __restrict__ ei,
                                   const float* __restrict__ ew, int E) {
    int i = blockIdx.x * blockDim.x + threadIdx.x;
    int twoE = 2 * E;
    if (i < twoE) {
        int v;
        if (g_is64) v = (int)((const long long*)ei)[i];
        else        v = ((const int*)ei)[i];
        g_idx[i] = v;
        if (i >= E) {
            atomicAdd(&g_deg[v], ew[i - E]);
            atomicAdd(&g_cnt[v], 1);
        }
    }
}

// ---------------- exclusive scan of g_cnt -> g_rowptr (3-pass) ----------------
__global__ void scan1(int n) {
    __shared__ int sm[512];
    int i = blockIdx.x * 512 + threadIdx.x;
    int v = (i < n) ? g_cnt[i] : 0;
    sm[threadIdx.x] = v;
    __syncthreads();
    #pragma unroll
    for (int o = 1; o < 512; o <<= 1) {
        int t = (threadIdx.x >= o) ? sm[threadIdx.x - o] : 0;
        __syncthreads();
        sm[threadIdx.x] += t;
        __syncthreads();
    }
    if (i < n) g_rowptr[i] = sm[threadIdx.x] - v;
    if (threadIdx.x == 511) g_bsum[blockIdx.x] = sm[511];
}

__global__ void scan2(int nb) {
    __shared__ int sm[256];
    int v = (threadIdx.x < nb) ? g_bsum[threadIdx.x] : 0;
    sm[threadIdx.x] = v;
    __syncthreads();
    #pragma unroll
    for (int o = 1; o < 256; o <<= 1) {
        int t = (threadIdx.x >= o) ? sm[threadIdx.x - o] : 0;
        __syncthreads();
        sm[threadIdx.x] += t;
        __syncthreads();
    }
    if (threadIdx.x < nb) g_boff[threadIdx.x] = sm[threadIdx.x] - v;
}

__global__ void scan3(int n, int E) {
    int i = blockIdx.x * blockDim.x + threadIdx.x;
    if (i < n) {
        g_rowptr[i] += g_boff[i >> 9];
        g_dinv[i] = rsqrtf(g_deg[i] + 1.0f);
    }
    if (i == 0) g_rowptr[n] = E;
}

// ---------------- CSR fill (interleaved src+norm) ----------------
__global__ void fill_kernel(const float* __restrict__ ew, int E) {
    int e = blockIdx.x * blockDim.x + threadIdx.x;
    if (e < E) {
        int s = g_idx[e];
        int d = g_idx[E + e];
        int pos = g_rowptr[d] + atomicAdd(&g_fill[d], 1);
        float nm = g_dinv[s] * ew[e] * g_dinv[d];
        g_edge[pos] = make_int2(s, __float_as_int(nm));
    }
}

// ---------------- fused BN+ReLU on load ----------------
__device__ __forceinline__ float4 bnrelu4(float4 v, int c4) {
    float4 sc = ((const float4*)g_scale)[c4];
    float4 sh = ((const float4*)g_shift)[c4];
    v.x = fmaxf(fmaf(v.x, sc.x, sh.x), 0.0f);
    v.y = fmaxf(fmaf(v.y, sc.y, sh.y), 0.0f);
    v.z = fmaxf(fmaf(v.z, sc.z, sh.z), 0.0f);
    v.w = fmaxf(fmaf(v.w, sc.w, sh.w), 0.0f);
    return v;
}

// ---------------- tensor-core GEMM 128x128 ----------------
#define SKH 136
#define GEMM_SMEM (128 * SKH * 4)   // 69632 B

template <bool FUSE_BN>
__global__ void __launch_bounds__(256) gemm128t(const float* __restrict__ Af,
                                                const __half* __restrict__ Ah,
                                                const float* __restrict__ W,
                                                __half* __restrict__ C, int n) {
    extern __shared__ char smem[];
    __half* sA = (__half*)smem;              // [128][SKH]
    __half* sB = sA + 128 * SKH;             // [128][SKH]
    float*  sC = (float*)smem;               // [128][SKH] (reused)

    int tid = threadIdx.x;
    int row0 = blockIdx.x * 128;

    const float4* W4 = (const float4*)W;
    #pragma unroll
    for (int i = tid; i < 4096; i += 256) {
        int r = i >> 5, c4 = i & 31;
        float4 v = W4[i];
        __half2* dst = (__half2*)(sB + r * SKH + c4 * 4);
        dst[0] = __floats2half2_rn(v.x, v.y);
        dst[1] = __floats2half2_rn(v.z, v.w);
    }

    if (FUSE_BN) {
        const uint2* A2 = (const uint2*)(Ah + (size_t)row0 * D);
        #pragma unroll
        for (int i = tid; i < 4096; i += 256) {
            int r = i >> 5, c4 = i & 31;
            float4 v = make_float4(0.f, 0.f, 0.f, 0.f);
            if (row0 + r < n) {
                uint2 rv = A2[i];
                float2 f0 = __half22float2(*reinterpret_cast<__half2*>(&rv.x));
                float2 f1 = __half22float2(*reinterpret_cast<__half2*>(&rv.y));
                v = bnrelu4(make_float4(f0.x, f0.y, f1.x, f1.y), c4);
            }
            __half2* dst = (__half2*)(sA + r * SKH + c4 * 4);
            dst[0] = __floats2half2_rn(v.x, v.y);
            dst[1] = __floats2half2_rn(v.z, v.w);
        }
    } else {
        const float4* A4 = (const float4*)Af + (size_t)row0 * 32;
        #pragma unroll
        for (int i = tid; i < 4096; i += 256) {
            int r = i >> 5, c4 = i & 31;
            float4 v = make_float4(0.f, 0.f, 0.f, 0.f);
            if (row0 + r < n) v = A4[i];
            __half2* dst = (__half2*)(sA + r * SKH + c4 * 4);
            dst[0] = __floats2half2_rn(v.x, v.y);
            dst[1] = __floats2half2_rn(v.z, v.w);
        }
    }
    __syncthreads();

    int warp = tid >> 5;
    int wr = warp & 3;
    int wc = warp >> 2;

    wmma::fragment<wmma::accumulator, 16, 16, 16, float> acc[2][4];
    #pragma unroll
    for (int i = 0; i < 2; i++)
        #pragma unroll
        for (int j = 0; j < 4; j++) wmma::fill_fragment(acc[i][j], 0.0f);

    #pragma unroll
    for (int ks = 0; ks < 8; ks++) {
        wmma::fragment<wmma::matrix_a, 16, 16, 16, __half, wmma::row_major> af[2];
        wmma::load_matrix_sync(af[0], sA + (wr * 32 +  0) * SKH + ks * 16, SKH);
        wmma::load_matrix_sync(af[1], sA + (wr * 32 + 16) * SKH + ks * 16, SKH);
        wmma::fragment<wmma::matrix_b, 16, 16, 16, __half, wmma::row_major> bf[4];
        #pragma unroll
        for (int j = 0; j < 4; j++)
            wmma::load_matrix_sync(bf[j], sB + (ks * 16) * SKH + wc * 64 + j * 16, SKH);
        #pragma unroll
        for (int i = 0; i < 2; i++)
            #pragma unroll
            for (int j = 0; j < 4; j++)
                wmma::mma_sync(acc[i][j], af[i], bf[j], acc[i][j]);
    }
    __syncthreads();

    #pragma unroll
    for (int i = 0; i < 2; i++)
        #pragma unroll
        for (int j = 0; j < 4; j++)
            wmma::store_matrix_sync(sC + (wr * 32 + i * 16) * SKH + wc * 64 + j * 16,
                                    acc[i][j], SKH, wmma::mem_row_major);
    __syncthreads();

    #pragma unroll
    for (int i = tid; i < 4096; i += 256) {
        int r = i >> 5, c4 = i & 31;
        if (row0 + r < n) {
            float4 v = *(const float4*)(sC + r * SKH + c4 * 4);
            uint2 o;
            __half2 hh;
            hh = __floats2half2_rn(v.x, v.y);
            o.x = *reinterpret_cast<unsigned*>(&hh);
            hh = __floats2half2_rn(v.z, v.w);
            o.y = *reinterpret_cast<unsigned*>(&hh);
            ((uint2*)(C + (size_t)(row0 + r) * D))[c4] = o;
        }
    }
}

// ---------------- tensor-core GEMM 128->40 (fp16 in + BN+ReLU, fp16 out) ---------
#define SB40 48
#define GEMM40_SMEM (128 * SKH * 2 + 128 * SB40 * 2)

__global__ void __launch_bounds__(256) gemm40t(const __half* __restrict__ A,
                                               const float* __restrict__ W,
                                               __half* __restrict__ C, int n) {
    extern __shared__ char smem[];
    __half* sA = (__half*)smem;              // [128][SKH]
    __half* sB = sA + 128 * SKH;             // [128][SB40]
    float*  sC = (float*)smem;               // [128][SB40] staging

    int tid = threadIdx.x;
    int row0 = blockIdx.x * 128;

    #pragma unroll
    for (int i = tid; i < 128 * SB40; i += 256) {
        int r = i / SB40, c = i % SB40;
        float v = (c < DOUT) ? W[r * DOUT + c] : 0.f;
        sB[r * SB40 + c] = __float2half_rn(v);
    }

    const uint2* A2 = (const uint2*)(A + (size_t)row0 * D);
    #pragma unroll
    for (int i = tid; i < 4096; i += 256) {
        int r = i >> 5, c4 = i & 31;
        float4 v = make_float4(0.f, 0.f, 0.f, 0.f);
        if (row0 + r < n) {
            uint2 rv = A2[i];
            float2 f0 = __half22float2(*reinterpret_cast<__half2*>(&rv.x));
            float2 f1 = __half22float2(*reinterpret_cast<__half2*>(&rv.y));
            v = bnrelu4(make_float4(f0.x, f0.y, f1.x, f1.y), c4);
        }
        __half2* dst = (__half2*)(sA + r * SKH + c4 * 4);
        dst[0] = __floats2half2_rn(v.x, v.y);
        dst[1] = __floats2half2_rn(v.z, v.w);
    }
    __syncthreads();

    int warp = tid >> 5;

    wmma::fragment<wmma::accumulator, 16, 16, 16, float> acc[3];
    #pragma unroll
    for (int j = 0; j < 3; j++) wmma::fill_fragment(acc[j], 0.0f);

    #pragma unroll
    for (int ks = 0; ks < 8; ks++) {
        wmma::fragment<wmma::matrix_a, 16, 16, 16, __half, wmma::row_major> af;
        wmma::load_matrix_sync(af, sA + (warp * 16) * SKH + ks * 16, SKH);
        #pragma unroll
        for (int j = 0; j < 3; j++) {
            wmma::fragment<wmma::matrix_b, 16, 16, 16, __half, wmma::row_major> bf;
            wmma::load_matrix_sync(bf, sB + (ks * 16) * SB40 + j * 16, SB40);
            wmma::mma_sync(acc[j], af, bf, acc[j]);
        }
    }
    __syncthreads();

    #pragma unroll
    for (int j = 0; j < 3; j++)
        wmma::store_matrix_sync(sC + (warp * 16) * SB40 + j * 16, acc[j],
                                SB40, wmma::mem_row_major);
    __syncthreads();

    #pragma unroll
    for (int i = tid; i < 128 * 20; i += 256) {
        int r = i / 20, cu = i % 20;
        if (row0 + r < n) {
            float2 v = *(const float2*)(sC + r * SB40 + cu * 2);
            __half2 hh = __floats2half2_rn(v.x, v.y);
            ((unsigned*)(C + (size_t)(row0 + r) * DOUT))[cu] =
                *reinterpret_cast<unsigned*>(&hh);
        }
    }
}

// ---------------- CSR gather + BN stats + fused finalize (last block) ------------
__global__ void gather128_bn(const __half* __restrict__ xw, const float* __restrict__ b,
                             __half* __restrict__ h, int n,
                             const float* __restrict__ g, const float* __restrict__ be,
                             float fn) {
    __shared__ float sbs[128], sbss[128];
    __shared__ int sIsLast;
    int tid = threadIdx.x;
    if (tid < 128) { sbs[tid] = 0.f; sbss[tid] = 0.f; }
    __syncthreads();

    int lane   = tid & 31;
    int warp   = (blockIdx.x * blockDim.x + tid) >> 5;
    int nwarps = (gridDim.x * blockDim.x) >> 5;

    float4 ps  = make_float4(0.f, 0.f, 0.f, 0.f);
    float4 pss = make_float4(0.f, 0.f, 0.f, 0.f);
    float4 bb  = ((const float4*)b)[lane];

    for (int v = warp; v < n; v += nwarps) {
        int beg = g_rowptr[v], end = g_rowptr[v + 1];
        float4 acc  = make_float4(0.f, 0.f, 0.f, 0.f);
        float4 acc2 = make_float4(0.f, 0.f, 0.f, 0.f);
        int i = beg;
        for (; i + 2 <= end; i += 2) {
            int2 e0 = g_edge[i], e1 = g_edge[i + 1];
            float w0 = __int_as_float(e0.y), w1 = __int_as_float(e1.y);
            uint2 r0 = ((const uint2*)(xw + (size_t)e0.x * D))[lane];
            uint2 r1 = ((const uint2*)(xw + (size_t)e1.x * D))[lane];
            float2 a0 = __half22float2(*reinterpret_cast<__half2*>(&r0.x));
            float2 a1 = __half22float2(*reinterpret_cast<__half2*>(&r0.y));
            float2 b0f = __half22float2(*reinterpret_cast<__half2*>(&r1.x));
            float2 b1f = __half22float2(*reinterpret_cast<__half2*>(&r1.y));
            acc.x  = fmaf(a0.x,  w0, acc.x);
            acc.y  = fmaf(a0.y,  w0, acc.y);
            acc.z  = fmaf(a1.x,  w0, acc.z);
            acc.w  = fmaf(a1.y,  w0, acc.w);
            acc2.x = fmaf(b0f.x, w1, acc2.x);
            acc2.y = fmaf(b0f.y, w1, acc2.y);
            acc2.z = fmaf(b1f.x, w1, acc2.z);
            acc2.w = fmaf(b1f.y, w1, acc2.w);
        }
        if (i < end) {
            int2 e0 = g_edge[i];
            float w0 = __int_as_float(e0.y);
            uint2 r0 = ((const uint2*)(xw + (size_t)e0.x * D))[lane];
            float2 a0 = __half22float2(*reinterpret_cast<__half2*>(&r0.x));
            float2 a1 = __half22float2(*reinterpret_cast<__half2*>(&r0.y));
            acc.x = fmaf(a0.x, w0, acc.x);
            acc.y = fmaf(a0.y, w0, acc.y);
            acc.z = fmaf(a1.x, w0, acc.z);
            acc.w = fmaf(a1.y, w0, acc.w);
        }
        acc.x += acc2.x; acc.y += acc2.y; acc.z += acc2.z; acc.w += acc2.w;

        float di  = g_dinv[v];
        float di2 = di * di;
        uint2 rv = ((const uint2*)(xw + (size_t)v * D))[lane];
        float2 f0 = __half22float2(*reinterpret_cast<__half2*>(&rv.x));
        float2 f1 = __half22float2(*reinterpret_cast<__half2*>(&rv.y));
        acc.x = fmaf(f0.x, di2, acc.x) + bb.x;
        acc.y = fmaf(f0.y, di2, acc.y) + bb.y;
        acc.z = fmaf(f1.x, di2, acc.z) + bb.z;
        acc.w = fmaf(f1.y, di2, acc.w) + bb.w;

        uint2 o;
        __half2 hh;
        hh = __floats2half2_rn(acc.x, acc.y);
        o.x = *reinterpret_cast<unsigned*>(&hh);
        hh = __floats2half2_rn(acc.z, acc.w);
        o.y = *reinterpret_cast<unsigned*>(&hh);
        ((uint2*)(h + (size_t)v * D))[lane] = o;

        ps.x += acc.x; ps.y += acc.y; ps.z += acc.z; ps.w += acc.w;
        pss.x = fmaf(acc.x, acc.x, pss.x);
        pss.y = fmaf(acc.y, acc.y, pss.y);
        pss.z = fmaf(acc.z, acc.z, pss.z);
        pss.w = fmaf(acc.w, acc.w, pss.w);
    }

    atomicAdd(&sbs[lane * 4 + 0], ps.x);
    atomicAdd(&sbs[lane * 4 + 1], ps.y);
    atomicAdd(&sbs[lane * 4 + 2], ps.z);
    atomicAdd(&sbs[lane * 4 + 3], ps.w);
    atomicAdd(&sbss[lane * 4 + 0], pss.x);
    atomicAdd(&sbss[lane * 4 + 1], pss.y);
    atomicAdd(&sbss[lane * 4 + 2], pss.z);
    atomicAdd(&sbss[lane * 4 + 3], pss.w);
    __syncthreads();
    if (tid < 128) {
        atomicAdd(&g_bnsum[tid],   sbs[tid]);
        atomicAdd(&g_bnsumsq[tid], sbss[tid]);
    }

    // last-block finalize: compute scale/shift, reset stats + counter
    __threadfence();
    if (tid == 0) {
        int prev = atomicAdd(&g_done, 1);
        sIsLast = (prev == gridDim.x - 1);
    }
    __syncthreads();
    if (sIsLast && tid < 128) {
        float mean = g_bnsum[tid] / fn;
        float var  = g_bnsumsq[tid] / fn - mean * mean;
        float sc   = g[tid] * rsqrtf(var + 1e-5f);
        g_scale[tid] = sc;
        g_shift[tid] = be[tid] - mean * sc;
        g_bnsum[tid] = 0.f;
        g_bnsumsq[tid] = 0.f;
        if (tid == 0) g_done = 0;
    }
}

// ---------------- CSR gather (D=40, fp16, 2-way unrolled) + log_softmax ----------
__global__ void gather40_softmax(const __half* __restrict__ xw2,
                                 const float* __restrict__ b2, float* __restrict__ out,
                                 int n) {
    int lane   = threadIdx.x & 31;
    int warp   = (blockIdx.x * blockDim.x + threadIdx.x) >> 5;
    int nwarps = (gridDim.x * blockDim.x) >> 5;

    for (int v = warp; v < n; v += nwarps) {
        int beg = g_rowptr[v], end = g_rowptr[v + 1];
        float4 acc  = make_float4(0.f, 0.f, 0.f, 0.f);
        float4 acc2 = make_float4(0.f, 0.f, 0.f, 0.f);
        if (lane < 10) {
            int i = beg;
            for (; i + 2 <= end; i += 2) {
                int2 e0 = g_edge[i], e1 = g_edge[i + 1];
                float w0 = __int_as_float(e0.y), w1 = __int_as_float(e1.y);
                uint2 r0 = ((const uint2*)(xw2 + (size_t)e0.x * DOUT))[lane];
                uint2 r1 = ((const uint2*)(xw2 + (size_t)e1.x * DOUT))[lane];
                float2 a0 = __half22float2(*reinterpret_cast<__half2*>(&r0.x));
                float2 a1 = __half22float2(*reinterpret_cast<__half2*>(&r0.y));
                float2 c0 = __half22float2(*reinterpret_cast<__half2*>(&r1.x));
                float2 c1 = __half22float2(*reinterpret_cast<__half2*>(&r1.y));
                acc.x  = fmaf(a0.x, w0, acc.x);
                acc.y  = fmaf(a0.y, w0, acc.y);
                acc.z  = fmaf(a1.x, w0, acc.z);
                acc.w  = fmaf(a1.y, w0, acc.w);
                acc2.x = fmaf(c0.x, w1, acc2.x);
                acc2.y = fmaf(c0.y, w1, acc2.y);
                acc2.z = fmaf(c1.x, w1, acc2.z);
                acc2.w = fmaf(c1.y, w1, acc2.w);
            }
            if (i < end) {
                int2 e0 = g_edge[i];
                float w0 = __int_as_float(e0.y);
                uint2 r0 = ((const uint2*)(xw2 + (size_t)e0.x * DOUT))[lane];
                float2 a0 = __half22float2(*reinterpret_cast<__half2*>(&r0.x));
                float2 a1 = __half22float2(*reinterpret_cast<__half2*>(&r0.y));
                acc.x = fmaf(a0.x, w0, acc.x);
                acc.y = fmaf(a0.y, w0, acc.y);
                acc.z = fmaf(a1.x, w0, acc.z);
                acc.w = fmaf(a1.y, w0, acc.w);
            }
            acc.x += acc2.x; acc.y += acc2.y; acc.z += acc2.z; acc.w += acc2.w;

            float di  = g_dinv[v];
            float di2 = di * di;
            uint2 rv = ((const uint2*)(xw2 + (size_t)v * DOUT))[lane];
            float2 f0 = __half22float2(*reinterpret_cast<__half2*>(&rv.x));
            float2 f1 = __half22float2(*reinterpret_cast<__half2*>(&rv.y));
            float4 bb = ((const float4*)b2)[lane];
            acc.x = fmaf(f0.x, di2, acc.x) + bb.x;
            acc.y = fmaf(f0.y, di2, acc.y) + bb.y;
            acc.z = fmaf(f1.x, di2, acc.z) + bb.z;
            acc.w = fmaf(f1.y, di2, acc.w) + bb.w;
        }
        float m = (lane < 10)
                ? fmaxf(fmaxf(acc.x, acc.y), fmaxf(acc.z, acc.w)) : -1e30f;
        #pragma unroll
        for (int o = 16; o; o >>= 1) m = fmaxf(m, __shfl_xor_sync(0xffffffffu, m, o));
        float s = (lane < 10)
                ? (expf(acc.x - m) + expf(acc.y - m) + expf(acc.z - m) + expf(acc.w - m))
                : 0.f;
        #pragma unroll
        for (int o = 16; o; o >>= 1) s += __shfl_xor_sync(0xffffffffu, s, o);
        float lse = m + logf(s);
        if (lane < 10)
            ((float4*)(out + (size_t)v * DOUT))[lane] =
                make_float4(acc.x - lse, acc.y - lse, acc.z - lse, acc.w - lse);
    }
}

// ---------------- launch ----------------
extern "C" void kernel_launch(void* const* d_in, const int* in_sizes, int n_in,
                              void* d_out, int out_size) {
    const float* x   = (const float*)d_in[0];
    const void*  ei  = d_in[1];
    const float* ew  = (const float*)d_in[2];
    const float* W0  = (const float*)d_in[3];
    const float* b0  = (const float*)d_in[4];
    const float* g0  = (const float*)d_in[5];
    const float* be0 = (const float*)d_in[6];
    const float* W1  = (const float*)d_in[7];
    const float* b1  = (const float*)d_in[8];
    const float* g1  = (const float*)d_in[9];
    const float* be1 = (const float*)d_in[10];
    const float* W2  = (const float*)d_in[11];
    const float* b2  = (const float*)d_in[12];

    int n = in_sizes[0] / D;
    int E = in_sizes[2];
    int twoE = 2 * E;
    float fn = (float)n;

    cudaFuncSetAttribute(gemm128t<false>, cudaFuncAttributeMaxDynamicSharedMemorySize, GEMM_SMEM);
    cudaFuncSetAttribute(gemm128t<true>,  cudaFuncAttributeMaxDynamicSharedMemorySize, GEMM_SMEM);
    cudaFuncSetAttribute(gemm40t, cudaFuncAttributeMaxDynamicSharedMemorySize, GEMM40_SMEM);

    void *p_deg, *p_cnt, *p_fill, *p_bns, *p_bnss, *p_done, *p_xw, *p_h, *p_xw2;
    cudaGetSymbolAddress(&p_deg,  g_deg);
    cudaGetSymbolAddress(&p_cnt,  g_cnt);
    cudaGetSymbolAddress(&p_fill, g_fill);
    cudaGetSymbolAddress(&p_bns,  g_bnsum);
    cudaGetSymbolAddress(&p_bnss, g_bnsumsq);
    cudaGetSymbolAddress(&p_done, g_done);
    cudaGetSymbolAddress(&p_xw,   g_xw);
    cudaGetSymbolAddress(&p_h,    g_h);
    cudaGetSymbolAddress(&p_xw2,  g_xw2);
    __half* xw  = (__half*)p_xw;
    __half* h   = (__half*)p_h;
    __half* xw2 = (__half*)p_xw2;

    const int T = 256;
    int nb_scan = cdiv(n, 512);
    int gather_blocks = 1184;

    cudaStream_t s2;
    cudaEvent_t evF, evJ;
    cudaStreamCreateWithFlags(&s2, cudaStreamNonBlocking);
    cudaEventCreateWithFlags(&evF, cudaEventDisableTiming);
    cudaEventCreateWithFlags(&evJ, cudaEventDisableTiming);

    cudaEventRecord(evF, 0);
    cudaStreamWaitEvent(s2, evF, 0);

    // ---- branch A (s2): zero + convert + CSR build ----
    cudaMemsetAsync(p_deg,  0, (size_t)n * sizeof(float), s2);
    cudaMemsetAsync(p_cnt,  0, (size_t)n * sizeof(int), s2);
    cudaMemsetAsync(p_fill, 0, (size_t)n * sizeof(int), s2);
    cudaMemsetAsync(p_bns,  0, 128 * sizeof(float), s2);
    cudaMemsetAsync(p_bnss, 0, 128 * sizeof(float), s2);
    cudaMemsetAsync(p_done, 0, sizeof(int), s2);
    detect_kernel<<<1, 32, 0, s2>>>((const unsigned*)ei, twoE);
    convert_deg_kernel<<<cdiv(twoE, T), T, 0, s2>>>(ei, ew, E);
    scan1<<<nb_scan, 512, 0, s2>>>(n);
    scan2<<<1, 256, 0, s2>>>(nb_scan);
    scan3<<<cdiv(n, T), T, 0, s2>>>(n, E);
    fill_kernel<<<cdiv(E, T), T, 0, s2>>>(ew, E);
    cudaEventRecord(evJ, s2);

    // ---- branch B (stream 0): layer-0 GEMM (tensor cores) ----
    gemm128t<false><<<cdiv(n, 128), T, GEMM_SMEM>>>(x, (const __half*)0, W0, xw, n);

    cudaStreamWaitEvent(0, evJ, 0);

    // ---- layer 0 aggregate (BN finalize fused into last block) ----
    gather128_bn<<<gather_blocks, T>>>(xw, b0, h, n, g0, be0, fn);

    // ---- layer 1 ----
    gemm128t<true><<<cdiv(n, 128), T, GEMM_SMEM>>>((const float*)0, h, W1, xw, n);
    gather128_bn<<<gather_blocks, T>>>(xw, b1, h, n, g1, be1, fn);

    // ---- layer 2 + log_softmax ----
    gemm40t<<<cdiv(n, 128), T, GEMM40_SMEM>>>(h, W2, xw2, n);
    gather40_softmax<<<gather_blocks, T>>>(xw2, b2, (float*)d_out, n);

    cudaEventDestroy(evF);
    cudaEventDestroy(evJ);
    cudaStreamDestroy(s2);
}

// round 14
// speedup vs baseline: 1.6888x; 1.0693x over previous
#include <cuda_runtime.h>
#include <cuda_fp16.h>
#include <mma.h>
#include <math.h>

using namespace nvcuda;

#define D    128
#define DOUT 40
#define NMAX 100000
#define EMAX 1600000

typedef unsigned long long ull;

static inline int cdiv(int a, int b) { return (a + b - 1) / b; }

// ---------------- scratch (static device globals; no allocation) ----------------
__device__ __align__(16) __half g_xw [(size_t)NMAX * D];    // fp16 gather operand
__device__ __align__(16) __half g_h  [(size_t)NMAX * D];    // fp16 hidden activations
__device__ __align__(16) __half g_xw2[(size_t)NMAX * DOUT]; // fp16 final-layer operand
__device__ float g_deg [NMAX];
__device__ float g_dinv[NMAX];
__device__ int   g_idx [2 * EMAX];
__device__ int   g_is64;
// CSR
__device__ int   g_cnt [NMAX];
__device__ int   g_rowptr[NMAX + 1];
__device__ int   g_fill[NMAX];
__device__ int   g_bsum[256];
__device__ int   g_boff[256];
__device__ int   g_scan_done;
__device__ __align__(8) int2 g_edge[EMAX];   // (src, norm-bits) interleaved
// BN
__device__ __align__(16) float g_bnsum  [128];
__device__ __align__(16) float g_bnsumsq[128];
__device__ __align__(16) float g_scale  [128];
__device__ __align__(16) float g_shift  [128];
__device__ int g_done;

// ---------------- index dtype detect ----------------
__global__ void detect_kernel(const unsigned* __restrict__ w, int twoE) {
    if (threadIdx.x == 0 && blockIdx.x == 0) {
        int nchk = twoE < 256 ? twoE : 256;
        int is64 = 1;
        for (int i = 0; i < nchk; i++)
            if (w[2 * i + 1] != 0u) { is64 = 0; break; }
        g_is64 = is64;
    }
}

// ---------------- convert + degree/histogram (fused) ----------------
__global__ void convert_deg_kernel(const void* __restrict__ ei,
                                   const float* __restrict__ ew, int E) {
    int i = blockIdx.x * blockDim.x + threadIdx.x;
    int twoE = 2 * E;
    if (i < twoE) {
        int v;
        if (g_is64) v = (int)((const long long*)ei)[i];
        else        v = ((const int*)ei)[i];
        g_idx[i] = v;
        if (i >= E) {
            atomicAdd(&g_deg[v], ew[i - E]);
            atomicAdd(&g_cnt[v], 1);
        }
    }
}

// ---------------- scan1: per-block scan + last-block scans block sums -----------
__global__ void scan1(int n, int nb) {
    __shared__ int sm[512];
    __shared__ int sIsLast;
    int i = blockIdx.x * 512 + threadIdx.x;
    int v = (i < n) ? g_cnt[i] : 0;
    sm[threadIdx.x] = v;
    __syncthreads();
    #pragma unroll
    for (int o = 1; o < 512; o <<= 1) {
        int t = (threadIdx.x >= o) ? sm[threadIdx.x - o] : 0;
        __syncthreads();
        sm[threadIdx.x] += t;
        __syncthreads();
    }
    if (i < n) g_rowptr[i] = sm[threadIdx.x] - v;
    if (threadIdx.x == 511) g_bsum[blockIdx.x] = sm[511];

    // last-block: scan g_bsum -> g_boff
    __threadfence();
    if (threadIdx.x == 0) {
        int prev = atomicAdd(&g_scan_done, 1);
        sIsLast = (prev == gridDim.x - 1);
    }
    __syncthreads();
    if (sIsLast) {
        int bv = (threadIdx.x < nb) ? g_bsum[threadIdx.x] : 0;
        sm[threadIdx.x] = bv;
        __syncthreads();
        #pragma unroll
        for (int o = 1; o < 512; o <<= 1) {
            int t = (threadIdx.x >= o) ? sm[threadIdx.x - o] : 0;
            __syncthreads();
            sm[threadIdx.x] += t;
            __syncthreads();
        }
        if (threadIdx.x < nb) g_boff[threadIdx.x] = sm[threadIdx.x] - bv;
        if (threadIdx.x == 0) g_scan_done = 0;
    }
}

__global__ void scan3(int n, int E) {
    int i = blockIdx.x * blockDim.x + threadIdx.x;
    if (i < n) {
        g_rowptr[i] += g_boff[i >> 9];
        g_dinv[i] = rsqrtf(g_deg[i] + 1.0f);
    }
    if (i == 0) g_rowptr[n] = E;
}

// ---------------- CSR fill (interleaved src+norm) ----------------
__global__ void fill_kernel(const float* __restrict__ ew, int E) {
    int e = blockIdx.x * blockDim.x + threadIdx.x;
    if (e < E) {
        int s = g_idx[e];
        int d = g_idx[E + e];
        int pos = g_rowptr[d] + atomicAdd(&g_fill[d], 1);
        float nm = g_dinv[s] * ew[e] * g_dinv[d];
        g_edge[pos] = make_int2(s, __float_as_int(nm));
    }
}

// ---------------- fused BN+ReLU on load ----------------
__device__ __forceinline__ float4 bnrelu4(float4 v, int c4) {
    float4 sc = ((const float4*)g_scale)[c4];
    float4 sh = ((const float4*)g_shift)[c4];
    v.x = fmaxf(fmaf(v.x, sc.x, sh.x), 0.0f);
    v.y = fmaxf(fmaf(v.y, sc.y, sh.y), 0.0f);
    v.z = fmaxf(fmaf(v.z, sc.z, sh.z), 0.0f);
    v.w = fmaxf(fmaf(v.w, sc.w, sh.w), 0.0f);
    return v;
}

// ---------------- tensor-core GEMM 128x128 ----------------
#define SKH 136
#define GEMM_SMEM (128 * SKH * 4)   // 69632 B

template <bool FUSE_BN>
__global__ void __launch_bounds__(256) gemm128t(const float* __restrict__ Af,
                                                const __half* __restrict__ Ah,
                                                const float* __restrict__ W,
                                                __half* __restrict__ C, int n) {
    extern __shared__ char smem[];
    __half* sA = (__half*)smem;              // [128][SKH]
    __half* sB = sA + 128 * SKH;             // [128][SKH]
    float*  sC = (float*)smem;               // [128][SKH] (reused)

    int tid = threadIdx.x;
    int row0 = blockIdx.x * 128;

    const float4* W4 = (const float4*)W;
    #pragma unroll
    for (int i = tid; i < 4096; i += 256) {
        int r = i >> 5, c4 = i & 31;
        float4 v = W4[i];
        __half2* dst = (__half2*)(sB + r * SKH + c4 * 4);
        dst[0] = __floats2half2_rn(v.x, v.y);
        dst[1] = __floats2half2_rn(v.z, v.w);
    }

    if (FUSE_BN) {
        const uint2* A2 = (const uint2*)(Ah + (size_t)row0 * D);
        #pragma unroll
        for (int i = tid; i < 4096; i += 256) {
            int r = i >> 5, c4 = i & 31;
            float4 v = make_float4(0.f, 0.f, 0.f, 0.f);
            if (row0 + r < n) {
                uint2 rv = A2[i];
                float2 f0 = __half22float2(*reinterpret_cast<__half2*>(&rv.x));
                float2 f1 = __half22float2(*reinterpret_cast<__half2*>(&rv.y));
                v = bnrelu4(make_float4(f0.x, f0.y, f1.x, f1.y), c4);
            }
            __half2* dst = (__half2*)(sA + r * SKH + c4 * 4);
            dst[0] = __floats2half2_rn(v.x, v.y);
            dst[1] = __floats2half2_rn(v.z, v.w);
        }
    } else {
        const float4* A4 = (const float4*)Af + (size_t)row0 * 32;
        #pragma unroll
        for (int i = tid; i < 4096; i += 256) {
            int r = i >> 5, c4 = i & 31;
            float4 v = make_float4(0.f, 0.f, 0.f, 0.f);
            if (row0 + r < n) v = A4[i];
            __half2* dst = (__half2*)(sA + r * SKH + c4 * 4);
            dst[0] = __floats2half2_rn(v.x, v.y);
            dst[1] = __floats2half2_rn(v.z, v.w);
        }
    }
    __syncthreads();

    int warp = tid >> 5;
    int wr = warp & 3;
    int wc = warp >> 2;

    wmma::fragment<wmma::accumulator, 16, 16, 16, float> acc[2][4];
    #pragma unroll
    for (int i = 0; i < 2; i++)
        #pragma unroll
        for (int j = 0; j < 4; j++) wmma::fill_fragment(acc[i][j], 0.0f);

    #pragma unroll
    for (int ks = 0; ks < 8; ks++) {
        wmma::fragment<wmma::matrix_a, 16, 16, 16, __half, wmma::row_major> af[2];
        wmma::load_matrix_sync(af[0], sA + (wr * 32 +  0) * SKH + ks * 16, SKH);
        wmma::load_matrix_sync(af[1], sA + (wr * 32 + 16) * SKH + ks * 16, SKH);
        wmma::fragment<wmma::matrix_b, 16, 16, 16, __half, wmma::row_major> bf[4];
        #pragma unroll
        for (int j = 0; j < 4; j++)
            wmma::load_matrix_sync(bf[j], sB + (ks * 16) * SKH + wc * 64 + j * 16, SKH);
        #pragma unroll
        for (int i = 0; i < 2; i++)
            #pragma unroll
            for (int j = 0; j < 4; j++)
                wmma::mma_sync(acc[i][j], af[i], bf[j], acc[i][j]);
    }
    __syncthreads();

    #pragma unroll
    for (int i = 0; i < 2; i++)
        #pragma unroll
        for (int j = 0; j < 4; j++)
            wmma::store_matrix_sync(sC + (wr * 32 + i * 16) * SKH + wc * 64 + j * 16,
                                    acc[i][j], SKH, wmma::mem_row_major);
    __syncthreads();

    #pragma unroll
    for (int i = tid; i < 4096; i += 256) {
        int r = i >> 5, c4 = i & 31;
        if (row0 + r < n) {
            float4 v = *(const float4*)(sC + r * SKH + c4 * 4);
            uint2 o;
            __half2 hh;
            hh = __floats2half2_rn(v.x, v.y);
            o.x = *reinterpret_cast<unsigned*>(&hh);
            hh = __floats2half2_rn(v.z, v.w);
            o.y = *reinterpret_cast<unsigned*>(&hh);
            ((uint2*)(C + (size_t)(row0 + r) * D))[c4] = o;
        }
    }
}

// ---------------- tensor-core GEMM 128->40 (fp16 in + BN+ReLU, fp16 out) ---------
#define SB40 48
#define GEMM40_SMEM (128 * SKH * 2 + 128 * SB40 * 2)

__global__ void __launch_bounds__(256) gemm40t(const __half* __restrict__ A,
                                               const float* __restrict__ W,
                                               __half* __restrict__ C, int n) {
    extern __shared__ char smem[];
    __half* sA = (__half*)smem;              // [128][SKH]
    __half* sB = sA + 128 * SKH;             // [128][SB40]
    float*  sC = (float*)smem;               // [128][SB40] staging

    int tid = threadIdx.x;
    int row0 = blockIdx.x * 128;

    #pragma unroll
    for (int i = tid; i < 128 * SB40; i += 256) {
        int r = i / SB40, c = i % SB40;
        float v = (c < DOUT) ? W[r * DOUT + c] : 0.f;
        sB[r * SB40 + c] = __float2half_rn(v);
    }

    const uint2* A2 = (const uint2*)(A + (size_t)row0 * D);
    #pragma unroll
    for (int i = tid; i < 4096; i += 256) {
        int r = i >> 5, c4 = i & 31;
        float4 v = make_float4(0.f, 0.f, 0.f, 0.f);
        if (row0 + r < n) {
            uint2 rv = A2[i];
            float2 f0 = __half22float2(*reinterpret_cast<__half2*>(&rv.x));
            float2 f1 = __half22float2(*reinterpret_cast<__half2*>(&rv.y));
            v = bnrelu4(make_float4(f0.x, f0.y, f1.x, f1.y), c4);
        }
        __half2* dst = (__half2*)(sA + r * SKH + c4 * 4);
        dst[0] = __floats2half2_rn(v.x, v.y);
        dst[1] = __floats2half2_rn(v.z, v.w);
    }
    __syncthreads();

    int warp = tid >> 5;

    wmma::fragment<wmma::accumulator, 16, 16, 16, float> acc[3];
    #pragma unroll
    for (int j = 0; j < 3; j++) wmma::fill_fragment(acc[j], 0.0f);

    #pragma unroll
    for (int ks = 0; ks < 8; ks++) {
        wmma::fragment<wmma::matrix_a, 16, 16, 16, __half, wmma::row_major> af;
        wmma::load_matrix_sync(af, sA + (warp * 16) * SKH + ks * 16, SKH);
        #pragma unroll
        for (int j = 0; j < 3; j++) {
            wmma::fragment<wmma::matrix_b, 16, 16, 16, __half, wmma::row_major> bf;
            wmma::load_matrix_sync(bf, sB + (ks * 16) * SB40 + j * 16, SB40);
            wmma::mma_sync(acc[j], af, bf, acc[j]);
        }
    }
    __syncthreads();

    #pragma unroll
    for (int j = 0; j < 3; j++)
        wmma::store_matrix_sync(sC + (warp * 16) * SB40 + j * 16, acc[j],
                                SB40, wmma::mem_row_major);
    __syncthreads();

    #pragma unroll
    for (int i = tid; i < 128 * 20; i += 256) {
        int r = i / 20, cu = i % 20;
        if (row0 + r < n) {
            float2 v = *(const float2*)(sC + r * SB40 + cu * 2);
            __half2 hh = __floats2half2_rn(v.x, v.y);
            ((unsigned*)(C + (size_t)(row0 + r) * DOUT))[cu] =
                *reinterpret_cast<unsigned*>(&hh);
        }
    }
}

// ---------------- CSR gather + BN stats + fused finalize (last block) ------------
__global__ void gather128_bn(const __half* __restrict__ xw, const float* __restrict__ b,
                             __half* __restrict__ h, int n,
                             const float* __restrict__ g, const float* __restrict__ be,
                             float fn) {
    __shared__ float sbs[128], sbss[128];
    __shared__ int sIsLast;
    int tid = threadIdx.x;
    if (tid < 128) { sbs[tid] = 0.f; sbss[tid] = 0.f; }
    __syncthreads();

    int lane   = tid & 31;
    int warp   = (blockIdx.x * blockDim.x + tid) >> 5;
    int nwarps = (gridDim.x * blockDim.x) >> 5;

    float4 ps  = make_float4(0.f, 0.f, 0.f, 0.f);
    float4 pss = make_float4(0.f, 0.f, 0.f, 0.f);
    float4 bb  = ((const float4*)b)[lane];

    for (int v = warp; v < n; v += nwarps) {
        int beg = g_rowptr[v], end = g_rowptr[v + 1];
        float4 acc  = make_float4(0.f, 0.f, 0.f, 0.f);
        float4 acc2 = make_float4(0.f, 0.f, 0.f, 0.f);
        int i = beg;
        for (; i + 2 <= end; i += 2) {
            int2 e0 = g_edge[i], e1 = g_edge[i + 1];
            float w0 = __int_as_float(e0.y), w1 = __int_as_float(e1.y);
            uint2 r0 = ((const uint2*)(xw + (size_t)e0.x * D))[lane];
            uint2 r1 = ((const uint2*)(xw + (size_t)e1.x * D))[lane];
            float2 a0 = __half22float2(*reinterpret_cast<__half2*>(&r0.x));
            float2 a1 = __half22float2(*reinterpret_cast<__half2*>(&r0.y));
            float2 b0f = __half22float2(*reinterpret_cast<__half2*>(&r1.x));
            float2 b1f = __half22float2(*reinterpret_cast<__half2*>(&r1.y));
            acc.x  = fmaf(a0.x,  w0, acc.x);
            acc.y  = fmaf(a0.y,  w0, acc.y);
            acc.z  = fmaf(a1.x,  w0, acc.z);
            acc.w  = fmaf(a1.y,  w0, acc.w);
            acc2.x = fmaf(b0f.x, w1, acc2.x);
            acc2.y = fmaf(b0f.y, w1, acc2.y);
            acc2.z = fmaf(b1f.x, w1, acc2.z);
            acc2.w = fmaf(b1f.y, w1, acc2.w);
        }
        if (i < end) {
            int2 e0 = g_edge[i];
            float w0 = __int_as_float(e0.y);
            uint2 r0 = ((const uint2*)(xw + (size_t)e0.x * D))[lane];
            float2 a0 = __half22float2(*reinterpret_cast<__half2*>(&r0.x));
            float2 a1 = __half22float2(*reinterpret_cast<__half2*>(&r0.y));
            acc.x = fmaf(a0.x, w0, acc.x);
            acc.y = fmaf(a0.y, w0, acc.y);
            acc.z = fmaf(a1.x, w0, acc.z);
            acc.w = fmaf(a1.y, w0, acc.w);
        }
        acc.x += acc2.x; acc.y += acc2.y; acc.z += acc2.z; acc.w += acc2.w;

        float di  = g_dinv[v];
        float di2 = di * di;
        uint2 rv = ((const uint2*)(xw + (size_t)v * D))[lane];
        float2 f0 = __half22float2(*reinterpret_cast<__half2*>(&rv.x));
        float2 f1 = __half22float2(*reinterpret_cast<__half2*>(&rv.y));
        acc.x = fmaf(f0.x, di2, acc.x) + bb.x;
        acc.y = fmaf(f0.y, di2, acc.y) + bb.y;
        acc.z = fmaf(f1.x, di2, acc.z) + bb.z;
        acc.w = fmaf(f1.y, di2, acc.w) + bb.w;

        uint2 o;
        __half2 hh;
        hh = __floats2half2_rn(acc.x, acc.y);
        o.x = *reinterpret_cast<unsigned*>(&hh);
        hh = __floats2half2_rn(acc.z, acc.w);
        o.y = *reinterpret_cast<unsigned*>(&hh);
        ((uint2*)(h + (size_t)v * D))[lane] = o;

        ps.x += acc.x; ps.y += acc.y; ps.z += acc.z; ps.w += acc.w;
        pss.x = fmaf(acc.x, acc.x, pss.x);
        pss.y = fmaf(acc.y, acc.y, pss.y);
        pss.z = fmaf(acc.z, acc.z, pss.z);
        pss.w = fmaf(acc.w, acc.w, pss.w);
    }

    atomicAdd(&sbs[lane * 4 + 0], ps.x);
    atomicAdd(&sbs[lane * 4 + 1], ps.y);
    atomicAdd(&sbs[lane * 4 + 2], ps.z);
    atomicAdd(&sbs[lane * 4 + 3], ps.w);
    atomicAdd(&sbss[lane * 4 + 0], pss.x);
    atomicAdd(&sbss[lane * 4 + 1], pss.y);
    atomicAdd(&sbss[lane * 4 + 2], pss.z);
    atomicAdd(&sbss[lane * 4 + 3], pss.w);
    __syncthreads();
    if (tid < 128) {
        atomicAdd(&g_bnsum[tid],   sbs[tid]);
        atomicAdd(&g_bnsumsq[tid], sbss[tid]);
    }

    __threadfence();
    if (tid == 0) {
        int prev = atomicAdd(&g_done, 1);
        sIsLast = (prev == gridDim.x - 1);
    }
    __syncthreads();
    if (sIsLast && tid < 128) {
        float mean = g_bnsum[tid] / fn;
        float var  = g_bnsumsq[tid] / fn - mean * mean;
        float sc   = g[tid] * rsqrtf(var + 1e-5f);
        g_scale[tid] = sc;
        g_shift[tid] = be[tid] - mean * sc;
        g_bnsum[tid] = 0.f;
        g_bnsumsq[tid] = 0.f;
        if (tid == 0) g_done = 0;
    }
}

// ---------------- CSR gather (D=40, 16-lane groups, 2 nodes/warp) + log_softmax --
__global__ void gather40_softmax(const __half* __restrict__ xw2,
                                 const float* __restrict__ b2, float* __restrict__ out,
                                 int n) {
    int tid  = threadIdx.x;
    int l    = tid & 15;                 // lane within 16-group
    int grp  = (blockIdx.x * blockDim.x + tid) >> 4;
    int ngrp = (gridDim.x * blockDim.x) >> 4;
    unsigned mask = 0xFFFFu << ((tid & 16));   // 16-lane group mask within warp

    for (int v = grp; v < n; v += ngrp) {
        int beg = g_rowptr[v], end = g_rowptr[v + 1];
        float4 acc  = make_float4(0.f, 0.f, 0.f, 0.f);
        float4 acc2 = make_float4(0.f, 0.f, 0.f, 0.f);
        if (l < 10) {
            int i = beg;
            for (; i + 2 <= end; i += 2) {
                int2 e0 = g_edge[i], e1 = g_edge[i + 1];
                float w0 = __int_as_float(e0.y), w1 = __int_as_float(e1.y);
                uint2 r0 = ((const uint2*)(xw2 + (size_t)e0.x * DOUT))[l];
                uint2 r1 = ((const uint2*)(xw2 + (size_t)e1.x * DOUT))[l];
                float2 a0 = __half22float2(*reinterpret_cast<__half2*>(&r0.x));
                float2 a1 = __half22float2(*reinterpret_cast<__half2*>(&r0.y));
                float2 c0 = __half22float2(*reinterpret_cast<__half2*>(&r1.x));
                float2 c1 = __half22float2(*reinterpret_cast<__half2*>(&r1.y));
                acc.x  = fmaf(a0.x, w0, acc.x);
                acc.y  = fmaf(a0.y, w0, acc.y);
                acc.z  = fmaf(a1.x, w0, acc.z);
                acc.w  = fmaf(a1.y, w0, acc.w);
                acc2.x = fmaf(c0.x, w1, acc2.x);
                acc2.y = fmaf(c0.y, w1, acc2.y);
                acc2.z = fmaf(c1.x, w1, acc2.z);
                acc2.w = fmaf(c1.y, w1, acc2.w);
            }
            if (i < end) {
                int2 e0 = g_edge[i];
                float w0 = __int_as_float(e0.y);
                uint2 r0 = ((const uint2*)(xw2 + (size_t)e0.x * DOUT))[l];
                float2 a0 = __half22float2(*reinterpret_cast<__half2*>(&r0.x));
                float2 a1 = __half22float2(*reinterpret_cast<__half2*>(&r0.y));
                acc.x = fmaf(a0.x, w0, acc.x);
                acc.y = fmaf(a0.y, w0, acc.y);
                acc.z = fmaf(a1.x, w0, acc.z);
                acc.w = fmaf(a1.y, w0, acc.w);
            }
            acc.x += acc2.x; acc.y += acc2.y; acc.z += acc2.z; acc.w += acc2.w;

            float di  = g_dinv[v];
            float di2 = di * di;
            uint2 rv = ((const uint2*)(xw2 + (size_t)v * DOUT))[l];
            float2 f0 = __half22float2(*reinterpret_cast<__half2*>(&rv.x));
            float2 f1 = __half22float2(*reinterpret_cast<__half2*>(&rv.y));
            float4 bb = ((const float4*)b2)[l];
            acc.x = fmaf(f0.x, di2, acc.x) + bb.x;
            acc.y = fmaf(f0.y, di2, acc.y) + bb.y;
            acc.z = fmaf(f1.x, di2, acc.z) + bb.z;
            acc.w = fmaf(f1.y, di2, acc.w) + bb.w;
        }
        float m = (l < 10)
                ? fmaxf(fmaxf(acc.x, acc.y), fmaxf(acc.z, acc.w)) : -1e30f;
        #pragma unroll
        for (int o = 8; o; o >>= 1) m = fmaxf(m, __shfl_xor_sync(mask, m, o, 16));
        float s = (l < 10)
                ? (expf(acc.x - m) + expf(acc.y - m) + expf(acc.z - m) + expf(acc.w - m))
                : 0.f;
        #pragma unroll
        for (int o = 8; o; o >>= 1) s += __shfl_xor_sync(mask, s, o, 16);
        float lse = m + logf(s);
        if (l < 10)
            ((float4*)(out + (size_t)v * DOUT))[l] =
                make_float4(acc.x - lse, acc.y - lse, acc.z - lse, acc.w - lse);
    }
}

// ---------------- launch ----------------
extern "C" void kernel_launch(void* const* d_in, const int* in_sizes, int n_in,
                              void* d_out, int out_size) {
    const float* x   = (const float*)d_in[0];
    const void*  ei  = d_in[1];
    const float* ew  = (const float*)d_in[2];
    const float* W0  = (const float*)d_in[3];
    const float* b0  = (const float*)d_in[4];
    const float* g0  = (const float*)d_in[5];
    const float* be0 = (const float*)d_in[6];
    const float* W1  = (const float*)d_in[7];
    const float* b1  = (const float*)d_in[8];
    const float* g1  = (const float*)d_in[9];
    const float* be1 = (const float*)d_in[10];
    const float* W2  = (const float*)d_in[11];
    const float* b2  = (const float*)d_in[12];

    int n = in_sizes[0] / D;
    int E = in_sizes[2];
    int twoE = 2 * E;
    float fn = (float)n;

    cudaFuncSetAttribute(gemm128t<false>, cudaFuncAttributeMaxDynamicSharedMemorySize, GEMM_SMEM);
    cudaFuncSetAttribute(gemm128t<true>,  cudaFuncAttributeMaxDynamicSharedMemorySize, GEMM_SMEM);
    cudaFuncSetAttribute(gemm40t, cudaFuncAttributeMaxDynamicSharedMemorySize, GEMM40_SMEM);

    void *p_deg, *p_cnt, *p_fill, *p_bns, *p_bnss, *p_done, *p_sdone, *p_xw, *p_h, *p_xw2;
    cudaGetSymbolAddress(&p_deg,  g_deg);
    cudaGetSymbolAddress(&p_cnt,  g_cnt);
    cudaGetSymbolAddress(&p_fill, g_fill);
    cudaGetSymbolAddress(&p_bns,  g_bnsum);
    cudaGetSymbolAddress(&p_bnss, g_bnsumsq);
    cudaGetSymbolAddress(&p_done, g_done);
    cudaGetSymbolAddress(&p_sdone, g_scan_done);
    cudaGetSymbolAddress(&p_xw,   g_xw);
    cudaGetSymbolAddress(&p_h,    g_h);
    cudaGetSymbolAddress(&p_xw2,  g_xw2);
    __half* xw  = (__half*)p_xw;
    __half* h   = (__half*)p_h;
    __half* xw2 = (__half*)p_xw2;

    const int T = 256;
    int nb_scan = cdiv(n, 512);
    int gather_blocks = 1184;

    cudaStream_t s2;
    cudaEvent_t evF, evJ;
    cudaStreamCreateWithFlags(&s2, cudaStreamNonBlocking);
    cudaEventCreateWithFlags(&evF, cudaEventDisableTiming);
    cudaEventCreateWithFlags(&evJ, cudaEventDisableTiming);

    cudaEventRecord(evF, 0);
    cudaStreamWaitEvent(s2, evF, 0);

    // ---- branch A (s2): zero + convert + CSR build ----
    cudaMemsetAsync(p_deg,  0, (size_t)n * sizeof(float), s2);
    cudaMemsetAsync(p_cnt,  0, (size_t)n * sizeof(int), s2);
    cudaMemsetAsync(p_fill, 0, (size_t)n * sizeof(int), s2);
    cudaMemsetAsync(p_bns,  0, 128 * sizeof(float), s2);
    cudaMemsetAsync(p_bnss, 0, 128 * sizeof(float), s2);
    cudaMemsetAsync(p_done, 0, sizeof(int), s2);
    cudaMemsetAsync(p_sdone, 0, sizeof(int), s2);
    detect_kernel<<<1, 32, 0, s2>>>((const unsigned*)ei, twoE);
    convert_deg_kernel<<<cdiv(twoE, T), T, 0, s2>>>(ei, ew, E);
    scan1<<<nb_scan, 512, 0, s2>>>(n, nb_scan);
    scan3<<<cdiv(n, T), T, 0, s2>>>(n, E);
    fill_kernel<<<cdiv(E, T), T, 0, s2>>>(ew, E);
    cudaEventRecord(evJ, s2);

    // ---- branch B (stream 0): layer-0 GEMM (tensor cores) ----
    gemm128t<false><<<cdiv(n, 128), T, GEMM_SMEM>>>(x, (const __half*)0, W0, xw, n);

    cudaStreamWaitEvent(0, evJ, 0);

    // ---- layer 0 aggregate (BN finalize fused into last block) ----
    gather128_bn<<<gather_blocks, T>>>(xw, b0, h, n, g0, be0, fn);

    // ---- layer 1 ----
    gemm128t<true><<<cdiv(n, 128), T, GEMM_SMEM>>>((const float*)0, h, W1, xw, n);
    gather128_bn<<<gather_blocks, T>>>(xw, b1, h, n, g1, be1, fn);

    // ---- layer 2 + log_softmax ----
    gemm40t<<<cdiv(n, 128), T, GEMM40_SMEM>>>(h, W2, xw2, n);
    gather40_softmax<<<gather_blocks, T>>>(xw2, b2, (float*)d_out, n);

    cudaEventDestroy(evF);
    cudaEventDestroy(evJ);
    cudaStreamDestroy(s2);
}

// round 15
// speedup vs baseline: 1.7313x; 1.0252x over previous
#include <cuda_runtime.h>
#include <cuda_fp16.h>
#include <mma.h>
#include <math.h>

using namespace nvcuda;

#define D    128
#define DOUT 40
#define NMAX 100000
#define EMAX 1600000

typedef unsigned long long ull;

static inline int cdiv(int a, int b) { return (a + b - 1) / b; }

// ---------------- scratch (static device globals; no allocation) ----------------
__device__ __align__(16) __half g_xw [(size_t)NMAX * D];    // fp16 gather operand
__device__ __align__(16) __half g_h  [(size_t)NMAX * D];    // fp16 hidden activations
__device__ __align__(16) __half g_xw2[(size_t)NMAX * DOUT]; // fp16 final-layer operand
__device__ float g_deg [NMAX];
__device__ float g_dinv[NMAX];
__device__ int   g_idx [2 * EMAX];
__device__ int   g_is64;
// CSR
__device__ int   g_cnt [NMAX];
__device__ int   g_rowptr[NMAX + 1];
__device__ int   g_fill[NMAX];
__device__ int   g_bsum[256];
__device__ int   g_boff[256];
__device__ int   g_scan_done;
__device__ __align__(8) int2 g_edge[EMAX];   // (src, norm-bits) interleaved
// BN
__device__ __align__(16) float g_bnsum  [128];
__device__ __align__(16) float g_bnsumsq[128];
__device__ __align__(16) float g_scale  [128];
__device__ __align__(16) float g_shift  [128];
__device__ int g_done;

// ---------------- index dtype detect ----------------
__global__ void detect_kernel(const unsigned* __restrict__ w, int twoE) {
    if (threadIdx.x == 0 && blockIdx.x == 0) {
        int nchk = twoE < 256 ? twoE : 256;
        int is64 = 1;
        for (int i = 0; i < nchk; i++)
            if (w[2 * i + 1] != 0u) { is64 = 0; break; }
        g_is64 = is64;
    }
}

// ---------------- convert + degree/histogram (fused) ----------------
__global__ void convert_deg_kernel(const void* __restrict__ ei,
                                   const float* __restrict__ ew, int E) {
    int i = blockIdx.x * blockDim.x + threadIdx.x;
    int twoE = 2 * E;
    if (i < twoE) {
        int v;
        if (g_is64) v = (int)((const long long*)ei)[i];
        else        v = ((const int*)ei)[i];
        g_idx[i] = v;
        if (i >= E) {
            atomicAdd(&g_deg[v], ew[i - E]);
            atomicAdd(&g_cnt[v], 1);
        }
    }
}

// ---------------- scan1: per-block scan + last-block scans block sums -----------
__global__ void scan1(int n, int nb) {
    __shared__ int sm[512];
    __shared__ int sIsLast;
    int i = blockIdx.x * 512 + threadIdx.x;
    int v = (i < n) ? g_cnt[i] : 0;
    sm[threadIdx.x] = v;
    __syncthreads();
    #pragma unroll
    for (int o = 1; o < 512; o <<= 1) {
        int t = (threadIdx.x >= o) ? sm[threadIdx.x - o] : 0;
        __syncthreads();
        sm[threadIdx.x] += t;
        __syncthreads();
    }
    if (i < n) g_rowptr[i] = sm[threadIdx.x] - v;
    if (threadIdx.x == 511) g_bsum[blockIdx.x] = sm[511];

    __threadfence();
    if (threadIdx.x == 0) {
        int prev = atomicAdd(&g_scan_done, 1);
        sIsLast = (prev == gridDim.x - 1);
    }
    __syncthreads();
    if (sIsLast) {
        int bv = (threadIdx.x < nb) ? g_bsum[threadIdx.x] : 0;
        sm[threadIdx.x] = bv;
        __syncthreads();
        #pragma unroll
        for (int o = 1; o < 512; o <<= 1) {
            int t = (threadIdx.x >= o) ? sm[threadIdx.x - o] : 0;
            __syncthreads();
            sm[threadIdx.x] += t;
            __syncthreads();
        }
        if (threadIdx.x < nb) g_boff[threadIdx.x] = sm[threadIdx.x] - bv;
        if (threadIdx.x == 0) g_scan_done = 0;
    }
}

__global__ void scan3(int n, int E) {
    int i = blockIdx.x * blockDim.x + threadIdx.x;
    if (i < n) {
        g_rowptr[i] += g_boff[i >> 9];
        g_dinv[i] = rsqrtf(g_deg[i] + 1.0f);
    }
    if (i == 0) g_rowptr[n] = E;
}

// ---------------- CSR fill (interleaved src+norm) ----------------
__global__ void fill_kernel(const float* __restrict__ ew, int E) {
    int e = blockIdx.x * blockDim.x + threadIdx.x;
    if (e < E) {
        int s = g_idx[e];
        int d = g_idx[E + e];
        int pos = g_rowptr[d] + atomicAdd(&g_fill[d], 1);
        float nm = g_dinv[s] * ew[e] * g_dinv[d];
        g_edge[pos] = make_int2(s, __float_as_int(nm));
    }
}

// ---------------- fused BN+ReLU on load ----------------
__device__ __forceinline__ float4 bnrelu4(float4 v, int c4) {
    float4 sc = ((const float4*)g_scale)[c4];
    float4 sh = ((const float4*)g_shift)[c4];
    v.x = fmaxf(fmaf(v.x, sc.x, sh.x), 0.0f);
    v.y = fmaxf(fmaf(v.y, sc.y, sh.y), 0.0f);
    v.z = fmaxf(fmaf(v.z, sc.z, sh.z), 0.0f);
    v.w = fmaxf(fmaf(v.w, sc.w, sh.w), 0.0f);
    return v;
}

// ---------------- tensor-core GEMM 128x128 ----------------
#define SKH 136
#define GEMM_SMEM (128 * SKH * 4)   // 69632 B

template <bool FUSE_BN>
__global__ void __launch_bounds__(256) gemm128t(const float* __restrict__ Af,
                                                const __half* __restrict__ Ah,
                                                const float* __restrict__ W,
                                                __half* __restrict__ C, int n) {
    extern __shared__ char smem[];
    __half* sA = (__half*)smem;              // [128][SKH]
    __half* sB = sA + 128 * SKH;             // [128][SKH]
    float*  sC = (float*)smem;               // [128][SKH] (reused)

    int tid = threadIdx.x;
    int row0 = blockIdx.x * 128;

    // W load: independent of the producer kernel's output
    const float4* W4 = (const float4*)W;
    #pragma unroll
    for (int i = tid; i < 4096; i += 256) {
        int r = i >> 5, c4 = i & 31;
        float4 v = W4[i];
        __half2* dst = (__half2*)(sB + r * SKH + c4 * 4);
        dst[0] = __floats2half2_rn(v.x, v.y);
        dst[1] = __floats2half2_rn(v.z, v.w);
    }

    // PDL: wait for producer (gather writes Ah + g_scale/g_shift) before A-load
    cudaGridDependencySynchronize();

    if (FUSE_BN) {
        const uint2* A2 = (const uint2*)(Ah + (size_t)row0 * D);
        #pragma unroll
        for (int i = tid; i < 4096; i += 256) {
            int r = i >> 5, c4 = i & 31;
            float4 v = make_float4(0.f, 0.f, 0.f, 0.f);
            if (row0 + r < n) {
                uint2 rv = A2[i];
                float2 f0 = __half22float2(*reinterpret_cast<__half2*>(&rv.x));
                float2 f1 = __half22float2(*reinterpret_cast<__half2*>(&rv.y));
                v = bnrelu4(make_float4(f0.x, f0.y, f1.x, f1.y), c4);
            }
            __half2* dst = (__half2*)(sA + r * SKH + c4 * 4);
            dst[0] = __floats2half2_rn(v.x, v.y);
            dst[1] = __floats2half2_rn(v.z, v.w);
        }
    } else {
        const float4* A4 = (const float4*)Af + (size_t)row0 * 32;
        #pragma unroll
        for (int i = tid; i < 4096; i += 256) {
            int r = i >> 5, c4 = i & 31;
            float4 v = make_float4(0.f, 0.f, 0.f, 0.f);
            if (row0 + r < n) v = A4[i];
            __half2* dst = (__half2*)(sA + r * SKH + c4 * 4);
            dst[0] = __floats2half2_rn(v.x, v.y);
            dst[1] = __floats2half2_rn(v.z, v.w);
        }
    }
    __syncthreads();

    int warp = tid >> 5;
    int wr = warp & 3;
    int wc = warp >> 2;

    wmma::fragment<wmma::accumulator, 16, 16, 16, float> acc[2][4];
    #pragma unroll
    for (int i = 0; i < 2; i++)
        #pragma unroll
        for (int j = 0; j < 4; j++) wmma::fill_fragment(acc[i][j], 0.0f);

    #pragma unroll
    for (int ks = 0; ks < 8; ks++) {
        wmma::fragment<wmma::matrix_a, 16, 16, 16, __half, wmma::row_major> af[2];
        wmma::load_matrix_sync(af[0], sA + (wr * 32 +  0) * SKH + ks * 16, SKH);
        wmma::load_matrix_sync(af[1], sA + (wr * 32 + 16) * SKH + ks * 16, SKH);
        wmma::fragment<wmma::matrix_b, 16, 16, 16, __half, wmma::row_major> bf[4];
        #pragma unroll
        for (int j = 0; j < 4; j++)
            wmma::load_matrix_sync(bf[j], sB + (ks * 16) * SKH + wc * 64 + j * 16, SKH);
        #pragma unroll
        for (int i = 0; i < 2; i++)
            #pragma unroll
            for (int j = 0; j < 4; j++)
                wmma::mma_sync(acc[i][j], af[i], bf[j], acc[i][j]);
    }
    __syncthreads();

    #pragma unroll
    for (int i = 0; i < 2; i++)
        #pragma unroll
        for (int j = 0; j < 4; j++)
            wmma::store_matrix_sync(sC + (wr * 32 + i * 16) * SKH + wc * 64 + j * 16,
                                    acc[i][j], SKH, wmma::mem_row_major);
    __syncthreads();

    #pragma unroll
    for (int i = tid; i < 4096; i += 256) {
        int r = i >> 5, c4 = i & 31;
        if (row0 + r < n) {
            float4 v = *(const float4*)(sC + r * SKH + c4 * 4);
            uint2 o;
            __half2 hh;
            hh = __floats2half2_rn(v.x, v.y);
            o.x = *reinterpret_cast<unsigned*>(&hh);
            hh = __floats2half2_rn(v.z, v.w);
            o.y = *reinterpret_cast<unsigned*>(&hh);
            ((uint2*)(C + (size_t)(row0 + r) * D))[c4] = o;
        }
    }
}

// ---------------- tensor-core GEMM 128->40 (fp16 in + BN+ReLU, fp16 out) ---------
#define SB40 48
#define GEMM40_SMEM (128 * SKH * 2 + 128 * SB40 * 2)

__global__ void __launch_bounds__(256) gemm40t(const __half* __restrict__ A,
                                               const float* __restrict__ W,
                                               __half* __restrict__ C, int n) {
    extern __shared__ char smem[];
    __half* sA = (__half*)smem;              // [128][SKH]
    __half* sB = sA + 128 * SKH;             // [128][SB40]
    float*  sC = (float*)smem;               // [128][SB40] staging

    int tid = threadIdx.x;
    int row0 = blockIdx.x * 128;

    // W2 load: independent
    #pragma unroll
    for (int i = tid; i < 128 * SB40; i += 256) {
        int r = i / SB40, c = i % SB40;
        float v = (c < DOUT) ? W[r * DOUT + c] : 0.f;
        sB[r * SB40 + c] = __float2half_rn(v);
    }

    // PDL: wait for gather1 (A rows + g_scale/g_shift)
    cudaGridDependencySynchronize();

    const uint2* A2 = (const uint2*)(A + (size_t)row0 * D);
    #pragma unroll
    for (int i = tid; i < 4096; i += 256) {
        int r = i >> 5, c4 = i & 31;
        float4 v = make_float4(0.f, 0.f, 0.f, 0.f);
        if (row0 + r < n) {
            uint2 rv = A2[i];
            float2 f0 = __half22float2(*reinterpret_cast<__half2*>(&rv.x));
            float2 f1 = __half22float2(*reinterpret_cast<__half2*>(&rv.y));
            v = bnrelu4(make_float4(f0.x, f0.y, f1.x, f1.y), c4);
        }
        __half2* dst = (__half2*)(sA + r * SKH + c4 * 4);
        dst[0] = __floats2half2_rn(v.x, v.y);
        dst[1] = __floats2half2_rn(v.z, v.w);
    }
    __syncthreads();

    int warp = tid >> 5;

    wmma::fragment<wmma::accumulator, 16, 16, 16, float> acc[3];
    #pragma unroll
    for (int j = 0; j < 3; j++) wmma::fill_fragment(acc[j], 0.0f);

    #pragma unroll
    for (int ks = 0; ks < 8; ks++) {
        wmma::fragment<wmma::matrix_a, 16, 16, 16, __half, wmma::row_major> af;
        wmma::load_matrix_sync(af, sA + (warp * 16) * SKH + ks * 16, SKH);
        #pragma unroll
        for (int j = 0; j < 3; j++) {
            wmma::fragment<wmma::matrix_b, 16, 16, 16, __half, wmma::row_major> bf;
            wmma::load_matrix_sync(bf, sB + (ks * 16) * SB40 + j * 16, SB40);
            wmma::mma_sync(acc[j], af, bf, acc[j]);
        }
    }
    __syncthreads();

    #pragma unroll
    for (int j = 0; j < 3; j++)
        wmma::store_matrix_sync(sC + (warp * 16) * SB40 + j * 16, acc[j],
                                SB40, wmma::mem_row_major);
    __syncthreads();

    #pragma unroll
    for (int i = tid; i < 128 * 20; i += 256) {
        int r = i / 20, cu = i % 20;
        if (row0 + r < n) {
            float2 v = *(const float2*)(sC + r * SB40 + cu * 2);
            __half2 hh = __floats2half2_rn(v.x, v.y);
            ((unsigned*)(C + (size_t)(row0 + r) * DOUT))[cu] =
                *reinterpret_cast<unsigned*>(&hh);
        }
    }
}

// ---------------- CSR gather + BN stats + fused finalize (last block) ------------
__global__ void gather128_bn(const __half* __restrict__ xw, const float* __restrict__ b,
                             __half* __restrict__ h, int n,
                             const float* __restrict__ g, const float* __restrict__ be,
                             float fn) {
    __shared__ float sbs[128], sbss[128];
    __shared__ int sIsLast;
    int tid = threadIdx.x;
    if (tid < 128) { sbs[tid] = 0.f; sbss[tid] = 0.f; }

    // PDL: wait for producer GEMM before reading xw
    cudaGridDependencySynchronize();
    __syncthreads();

    int lane   = tid & 31;
    int warp   = (blockIdx.x * blockDim.x + tid) >> 5;
    int nwarps = (gridDim.x * blockDim.x) >> 5;

    float4 ps  = make_float4(0.f, 0.f, 0.f, 0.f);
    float4 pss = make_float4(0.f, 0.f, 0.f, 0.f);
    float4 bb  = ((const float4*)b)[lane];

    for (int v = warp; v < n; v += nwarps) {
        int beg = g_rowptr[v], end = g_rowptr[v + 1];
        float4 acc  = make_float4(0.f, 0.f, 0.f, 0.f);
        float4 acc2 = make_float4(0.f, 0.f, 0.f, 0.f);
        int i = beg;
        for (; i + 2 <= end; i += 2) {
            int2 e0 = g_edge[i], e1 = g_edge[i + 1];
            float w0 = __int_as_float(e0.y), w1 = __int_as_float(e1.y);
            uint2 r0 = ((const uint2*)(xw + (size_t)e0.x * D))[lane];
            uint2 r1 = ((const uint2*)(xw + (size_t)e1.x * D))[lane];
            float2 a0 = __half22float2(*reinterpret_cast<__half2*>(&r0.x));
            float2 a1 = __half22float2(*reinterpret_cast<__half2*>(&r0.y));
            float2 b0f = __half22float2(*reinterpret_cast<__half2*>(&r1.x));
            float2 b1f = __half22float2(*reinterpret_cast<__half2*>(&r1.y));
            acc.x  = fmaf(a0.x,  w0, acc.x);
            acc.y  = fmaf(a0.y,  w0, acc.y);
            acc.z  = fmaf(a1.x,  w0, acc.z);
            acc.w  = fmaf(a1.y,  w0, acc.w);
            acc2.x = fmaf(b0f.x, w1, acc2.x);
            acc2.y = fmaf(b0f.y, w1, acc2.y);
            acc2.z = fmaf(b1f.x, w1, acc2.z);
            acc2.w = fmaf(b1f.y, w1, acc2.w);
        }
        if (i < end) {
            int2 e0 = g_edge[i];
            float w0 = __int_as_float(e0.y);
            uint2 r0 = ((const uint2*)(xw + (size_t)e0.x * D))[lane];
            float2 a0 = __half22float2(*reinterpret_cast<__half2*>(&r0.x));
            float2 a1 = __half22float2(*reinterpret_cast<__half2*>(&r0.y));
            acc.x = fmaf(a0.x, w0, acc.x);
            acc.y = fmaf(a0.y, w0, acc.y);
            acc.z = fmaf(a1.x, w0, acc.z);
            acc.w = fmaf(a1.y, w0, acc.w);
        }
        acc.x += acc2.x; acc.y += acc2.y; acc.z += acc2.z; acc.w += acc2.w;

        float di  = g_dinv[v];
        float di2 = di * di;
        uint2 rv = ((const uint2*)(xw + (size_t)v * D))[lane];
        float2 f0 = __half22float2(*reinterpret_cast<__half2*>(&rv.x));
        float2 f1 = __half22float2(*reinterpret_cast<__half2*>(&rv.y));
        acc.x = fmaf(f0.x, di2, acc.x) + bb.x;
        acc.y = fmaf(f0.y, di2, acc.y) + bb.y;
        acc.z = fmaf(f1.x, di2, acc.z) + bb.z;
        acc.w = fmaf(f1.y, di2, acc.w) + bb.w;

        uint2 o;
        __half2 hh;
        hh = __floats2half2_rn(acc.x, acc.y);
        o.x = *reinterpret_cast<unsigned*>(&hh);
        hh = __floats2half2_rn(acc.z, acc.w);
        o.y = *reinterpret_cast<unsigned*>(&hh);
        ((uint2*)(h + (size_t)v * D))[lane] = o;

        ps.x += acc.x; ps.y += acc.y; ps.z += acc.z; ps.w += acc.w;
        pss.x = fmaf(acc.x, acc.x, pss.x);
        pss.y = fmaf(acc.y, acc.y, pss.y);
        pss.z = fmaf(acc.z, acc.z, pss.z);
        pss.w = fmaf(acc.w, acc.w, pss.w);
    }

    atomicAdd(&sbs[lane * 4 + 0], ps.x);
    atomicAdd(&sbs[lane * 4 + 1], ps.y);
    atomicAdd(&sbs[lane * 4 + 2], ps.z);
    atomicAdd(&sbs[lane * 4 + 3], ps.w);
    atomicAdd(&sbss[lane * 4 + 0], pss.x);
    atomicAdd(&sbss[lane * 4 + 1], pss.y);
    atomicAdd(&sbss[lane * 4 + 2], pss.z);
    atomicAdd(&sbss[lane * 4 + 3], pss.w);
    __syncthreads();
    if (tid < 128) {
        atomicAdd(&g_bnsum[tid],   sbs[tid]);
        atomicAdd(&g_bnsumsq[tid], sbss[tid]);
    }

    __threadfence();
    if (tid == 0) {
        int prev = atomicAdd(&g_done, 1);
        sIsLast = (prev == gridDim.x - 1);
    }
    __syncthreads();
    if (sIsLast && tid < 128) {
        float mean = g_bnsum[tid] / fn;
        float var  = g_bnsumsq[tid] / fn - mean * mean;
        float sc   = g[tid] * rsqrtf(var + 1e-5f);
        g_scale[tid] = sc;
        g_shift[tid] = be[tid] - mean * sc;
        g_bnsum[tid] = 0.f;
        g_bnsumsq[tid] = 0.f;
        if (tid == 0) g_done = 0;
    }
}

// ---------------- CSR gather (D=40, 16-lane groups, 2 nodes/warp) + log_softmax --
__global__ void gather40_softmax(const __half* __restrict__ xw2,
                                 const float* __restrict__ b2, float* __restrict__ out,
                                 int n) {
    // PDL: wait for gemm40t before reading xw2
    cudaGridDependencySynchronize();

    int tid  = threadIdx.x;
    int l    = tid & 15;
    int grp  = (blockIdx.x * blockDim.x + tid) >> 4;
    int ngrp = (gridDim.x * blockDim.x) >> 4;
    unsigned mask = 0xFFFFu << ((tid & 16));

    for (int v = grp; v < n; v += ngrp) {
        int beg = g_rowptr[v], end = g_rowptr[v + 1];
        float4 acc  = make_float4(0.f, 0.f, 0.f, 0.f);
        float4 acc2 = make_float4(0.f, 0.f, 0.f, 0.f);
        if (l < 10) {
            int i = beg;
            for (; i + 2 <= end; i += 2) {
                int2 e0 = g_edge[i], e1 = g_edge[i + 1];
                float w0 = __int_as_float(e0.y), w1 = __int_as_float(e1.y);
                uint2 r0 = ((const uint2*)(xw2 + (size_t)e0.x * DOUT))[l];
                uint2 r1 = ((const uint2*)(xw2 + (size_t)e1.x * DOUT))[l];
                float2 a0 = __half22float2(*reinterpret_cast<__half2*>(&r0.x));
                float2 a1 = __half22float2(*reinterpret_cast<__half2*>(&r0.y));
                float2 c0 = __half22float2(*reinterpret_cast<__half2*>(&r1.x));
                float2 c1 = __half22float2(*reinterpret_cast<__half2*>(&r1.y));
                acc.x  = fmaf(a0.x, w0, acc.x);
                acc.y  = fmaf(a0.y, w0, acc.y);
                acc.z  = fmaf(a1.x, w0, acc.z);
                acc.w  = fmaf(a1.y, w0, acc.w);
                acc2.x = fmaf(c0.x, w1, acc2.x);
                acc2.y = fmaf(c0.y, w1, acc2.y);
                acc2.z = fmaf(c1.x, w1, acc2.z);
                acc2.w = fmaf(c1.y, w1, acc2.w);
            }
            if (i < end) {
                int2 e0 = g_edge[i];
                float w0 = __int_as_float(e0.y);
                uint2 r0 = ((const uint2*)(xw2 + (size_t)e0.x * DOUT))[l];
                float2 a0 = __half22float2(*reinterpret_cast<__half2*>(&r0.x));
                float2 a1 = __half22float2(*reinterpret_cast<__half2*>(&r0.y));
                acc.x = fmaf(a0.x, w0, acc.x);
                acc.y = fmaf(a0.y, w0, acc.y);
                acc.z = fmaf(a1.x, w0, acc.z);
                acc.w = fmaf(a1.y, w0, acc.w);
            }
            acc.x += acc2.x; acc.y += acc2.y; acc.z += acc2.z; acc.w += acc2.w;

            float di  = g_dinv[v];
            float di2 = di * di;
            uint2 rv = ((const uint2*)(xw2 + (size_t)v * DOUT))[l];
            float2 f0 = __half22float2(*reinterpret_cast<__half2*>(&rv.x));
            float2 f1 = __half22float2(*reinterpret_cast<__half2*>(&rv.y));
            float4 bb = ((const float4*)b2)[l];
            acc.x = fmaf(f0.x, di2, acc.x) + bb.x;
            acc.y = fmaf(f0.y, di2, acc.y) + bb.y;
            acc.z = fmaf(f1.x, di2, acc.z) + bb.z;
            acc.w = fmaf(f1.y, di2, acc.w) + bb.w;
        }
        float m = (l < 10)
                ? fmaxf(fmaxf(acc.x, acc.y), fmaxf(acc.z, acc.w)) : -1e30f;
        #pragma unroll
        for (int o = 8; o; o >>= 1) m = fmaxf(m, __shfl_xor_sync(mask, m, o, 16));
        float s = (l < 10)
                ? (expf(acc.x - m) + expf(acc.y - m) + expf(acc.z - m) + expf(acc.w - m))
                : 0.f;
        #pragma unroll
        for (int o = 8; o; o >>= 1) s += __shfl_xor_sync(mask, s, o, 16);
        float lse = m + logf(s);
        if (l < 10)
            ((float4*)(out + (size_t)v * DOUT))[l] =
                make_float4(acc.x - lse, acc.y - lse, acc.z - lse, acc.w - lse);
    }
}

// ---------------- launch ----------------
extern "C" void kernel_launch(void* const* d_in, const int* in_sizes, int n_in,
                              void* d_out, int out_size) {
    const float* x   = (const float*)d_in[0];
    const void*  ei  = d_in[1];
    const float* ew  = (const float*)d_in[2];
    const float* W0  = (const float*)d_in[3];
    const float* b0  = (const float*)d_in[4];
    const float* g0  = (const float*)d_in[5];
    const float* be0 = (const float*)d_in[6];
    const float* W1  = (const float*)d_in[7];
    const float* b1  = (const float*)d_in[8];
    const float* g1  = (const float*)d_in[9];
    const float* be1 = (const float*)d_in[10];
    const float* W2  = (const float*)d_in[11];
    const float* b2  = (const float*)d_in[12];

    int n = in_sizes[0] / D;
    int E = in_sizes[2];
    int twoE = 2 * E;
    float fn = (float)n;

    cudaFuncSetAttribute(gemm128t<false>, cudaFuncAttributeMaxDynamicSharedMemorySize, GEMM_SMEM);
    cudaFuncSetAttribute(gemm128t<true>,  cudaFuncAttributeMaxDynamicSharedMemorySize, GEMM_SMEM);
    cudaFuncSetAttribute(gemm40t, cudaFuncAttributeMaxDynamicSharedMemorySize, GEMM40_SMEM);

    void *p_deg, *p_cnt, *p_fill, *p_bns, *p_bnss, *p_done, *p_sdone, *p_xw, *p_h, *p_xw2;
    cudaGetSymbolAddress(&p_deg,  g_deg);
    cudaGetSymbolAddress(&p_cnt,  g_cnt);
    cudaGetSymbolAddress(&p_fill, g_fill);
    cudaGetSymbolAddress(&p_bns,  g_bnsum);
    cudaGetSymbolAddress(&p_bnss, g_bnsumsq);
    cudaGetSymbolAddress(&p_done, g_done);
    cudaGetSymbolAddress(&p_sdone, g_scan_done);
    cudaGetSymbolAddress(&p_xw,   g_xw);
    cudaGetSymbolAddress(&p_h,    g_h);
    cudaGetSymbolAddress(&p_xw2,  g_xw2);
    __half* xw  = (__half*)p_xw;
    __half* h   = (__half*)p_h;
    __half* xw2 = (__half*)p_xw2;

    const int T = 256;
    int nb_scan = cdiv(n, 512);
    int gather_blocks = 1184;

    cudaStream_t s2;
    cudaEvent_t evF, evJ;
    cudaStreamCreateWithFlags(&s2, cudaStreamNonBlocking);
    cudaEventCreateWithFlags(&evF, cudaEventDisableTiming);
    cudaEventCreateWithFlags(&evJ, cudaEventDisableTiming);

    cudaEventRecord(evF, 0);
    cudaStreamWaitEvent(s2, evF, 0);

    // ---- branch A (s2): zero + convert + CSR build ----
    cudaMemsetAsync(p_deg,  0, (size_t)n * sizeof(float), s2);
    cudaMemsetAsync(p_cnt,  0, (size_t)n * sizeof(int), s2);
    cudaMemsetAsync(p_fill, 0, (size_t)n * sizeof(int), s2);
    cudaMemsetAsync(p_bns,  0, 128 * sizeof(float), s2);
    cudaMemsetAsync(p_bnss, 0, 128 * sizeof(float), s2);
    cudaMemsetAsync(p_done, 0, sizeof(int), s2);
    cudaMemsetAsync(p_sdone, 0, sizeof(int), s2);
    detect_kernel<<<1, 32, 0, s2>>>((const unsigned*)ei, twoE);
    convert_deg_kernel<<<cdiv(twoE, T), T, 0, s2>>>(ei, ew, E);
    scan1<<<nb_scan, 512, 0, s2>>>(n, nb_scan);
    scan3<<<cdiv(n, T), T, 0, s2>>>(n, E);
    fill_kernel<<<cdiv(E, T), T, 0, s2>>>(ew, E);
    cudaEventRecord(evJ, s2);

    // ---- branch B (stream 0): layer-0 GEMM (tensor cores) ----
    gemm128t<false><<<cdiv(n, 128), T, GEMM_SMEM>>>(x, (const __half*)0, W0, xw, n);

    cudaStreamWaitEvent(0, evJ, 0);

    // ---- layer 0 aggregate (plain launch; follows cross-stream join) ----
    gather128_bn<<<gather_blocks, T>>>(xw, b0, h, n, g0, be0, fn);

    // PDL config for the serial chain
    cudaLaunchAttribute pdlAttr[1];
    pdlAttr[0].id = cudaLaunchAttributeProgrammaticStreamSerialization;
    pdlAttr[0].val.programmaticStreamSerializationAllowed = 1;

    // ---- layer 1 (PDL) ----
    {
        cudaLaunchConfig_t cfg = {};
        cfg.gridDim = dim3(cdiv(n, 128));
        cfg.blockDim = dim3(T);
        cfg.dynamicSmemBytes = GEMM_SMEM;
        cfg.stream = 0;
        cfg.attrs = pdlAttr;
        cfg.numAttrs = 1;
        cudaLaunchKernelEx(&cfg, gemm128t<true>,
                           (const float*)0, (const __half*)h, W1, xw, n);
    }
    {
        cudaLaunchConfig_t cfg = {};
        cfg.gridDim = dim3(gather_blocks);
        cfg.blockDim = dim3(T);
        cfg.dynamicSmemBytes = 0;
        cfg.stream = 0;
        cfg.attrs = pdlAttr;
        cfg.numAttrs = 1;
        cudaLaunchKernelEx(&cfg, gather128_bn,
                           (const __half*)xw, b1, h, n, g1, be1, fn);
    }

    // ---- layer 2 + log_softmax (PDL) ----
    {
        cudaLaunchConfig_t cfg = {};
        cfg.gridDim = dim3(cdiv(n, 128));
        cfg.blockDim = dim3(T);
        cfg.dynamicSmemBytes = GEMM40_SMEM;
        cfg.stream = 0;
        cfg.attrs = pdlAttr;
        cfg.numAttrs = 1;
        cudaLaunchKernelEx(&cfg, gemm40t, (const __half*)h, W2, xw2, n);
    }
    {
        cudaLaunchConfig_t cfg = {};
        cfg.gridDim = dim3(gather_blocks);
        cfg.blockDim = dim3(T);
        cfg.dynamicSmemBytes = 0;
        cfg.stream = 0;
        cfg.attrs = pdlAttr;
        cfg.numAttrs = 1;
        cudaLaunchKernelEx(&cfg, gather40_softmax,
                           (const __half*)xw2, b2, (float*)d_out, n);
    }

    cudaEventDestroy(evF);
    cudaEventDestroy(evJ);
    cudaStreamDestroy(s2);
}

// round 16
// speedup vs baseline: 1.8774x; 1.0844x over previous
#include <cuda_runtime.h>
#include <cuda_fp16.h>
#include <mma.h>
#include <math.h>

using namespace nvcuda;

#define D    128
#define DOUT 40
#define NMAX 100000
#define EMAX 1600000

typedef unsigned long long ull;

static inline int cdiv(int a, int b) { return (a + b - 1) / b; }

// ---------------- scratch (static device globals; no allocation) ----------------
__device__ __align__(16) __half g_xw [(size_t)NMAX * D];    // fp16 gather operand
__device__ __align__(16) __half g_h  [(size_t)NMAX * D];    // fp16 hidden activations
__device__ __align__(16) __half g_xw2[(size_t)NMAX * DOUT]; // fp16 final-layer operand
__device__ float g_dinv[NMAX];
__device__ int   g_is64;
// per-launch-zeroed block (one memset covers all three)
struct NZ { float deg[NMAX]; int cnt[NMAX]; int fill[NMAX]; };
__device__ NZ g_nz;
// CSR
__device__ int   g_rowptr[NMAX + 1];
__device__ int   g_bsum[256];
__device__ int   g_boff[256];
__device__ int   g_scan_done;            // zero-init; self-resetting
__device__ __align__(8) int2 g_edge[EMAX];   // (src, norm-bits) interleaved
// BN (zero-init; self-resetting via gather last block)
__device__ __align__(16) float g_bnsum  [128];
__device__ __align__(16) float g_bnsumsq[128];
__device__ __align__(16) float g_scale  [128];
__device__ __align__(16) float g_shift  [128];
__device__ int g_done;                   // zero-init; self-resetting

// ---------------- index dtype detect ----------------
__global__ void detect_kernel(const unsigned* __restrict__ w, int twoE) {
    if (threadIdx.x == 0 && blockIdx.x == 0) {
        int nchk = twoE < 256 ? twoE : 256;
        int is64 = 1;
        for (int i = 0; i < nchk; i++)
            if (w[2 * i + 1] != 0u) { is64 = 0; break; }
        g_is64 = is64;
    }
}

// ---------------- degree/histogram from dst half (no index copy) ----------------
__global__ void deg_kernel(const void* __restrict__ ei,
                           const float* __restrict__ ew, int E) {
    cudaGridDependencySynchronize();
    int e = blockIdx.x * blockDim.x + threadIdx.x;
    if (e < E) {
        int d;
        if (g_is64) d = (int)((const long long*)ei)[E + e];
        else        d = ((const int*)ei)[E + e];
        atomicAdd(&g_nz.deg[d], ew[e]);
        atomicAdd(&g_nz.cnt[d], 1);
    }
}

// ---------------- scan1: per-block scan + last-block scans block sums -----------
__global__ void scan1(int n, int nb) {
    cudaGridDependencySynchronize();
    __shared__ int sm[512];
    __shared__ int sIsLast;
    int i = blockIdx.x * 512 + threadIdx.x;
    int v = (i < n) ? g_nz.cnt[i] : 0;
    sm[threadIdx.x] = v;
    __syncthreads();
    #pragma unroll
    for (int o = 1; o < 512; o <<= 1) {
        int t = (threadIdx.x >= o) ? sm[threadIdx.x - o] : 0;
        __syncthreads();
        sm[threadIdx.x] += t;
        __syncthreads();
    }
    if (i < n) g_rowptr[i] = sm[threadIdx.x] - v;
    if (threadIdx.x == 511) g_bsum[blockIdx.x] = sm[511];

    __threadfence();
    if (threadIdx.x == 0) {
        int prev = atomicAdd(&g_scan_done, 1);
        sIsLast = (prev == gridDim.x - 1);
    }
    __syncthreads();
    if (sIsLast) {
        int bv = (threadIdx.x < nb) ? g_bsum[threadIdx.x] : 0;
        sm[threadIdx.x] = bv;
        __syncthreads();
        #pragma unroll
        for (int o = 1; o < 512; o <<= 1) {
            int t = (threadIdx.x >= o) ? sm[threadIdx.x - o] : 0;
            __syncthreads();
            sm[threadIdx.x] += t;
            __syncthreads();
        }
        if (threadIdx.x < nb) g_boff[threadIdx.x] = sm[threadIdx.x] - bv;
        if (threadIdx.x == 0) g_scan_done = 0;
    }
}

__global__ void scan3(int n, int E) {
    cudaGridDependencySynchronize();
    int i = blockIdx.x * blockDim.x + threadIdx.x;
    if (i < n) {
        g_rowptr[i] += g_boff[i >> 9];
        g_dinv[i] = rsqrtf(g_nz.deg[i] + 1.0f);
    }
    if (i == 0) g_rowptr[n] = E;
}

// ---------------- CSR fill (inline index convert, interleaved src+norm) ----------
__global__ void fill_kernel(const void* __restrict__ ei,
                            const float* __restrict__ ew, int E) {
    cudaGridDependencySynchronize();
    int e = blockIdx.x * blockDim.x + threadIdx.x;
    if (e < E) {
        int s, d;
        if (g_is64) {
            s = (int)((const long long*)ei)[e];
            d = (int)((const long long*)ei)[E + e];
        } else {
            s = ((const int*)ei)[e];
            d = ((const int*)ei)[E + e];
        }
        int pos = g_rowptr[d] + atomicAdd(&g_nz.fill[d], 1);
        float nm = g_dinv[s] * ew[e] * g_dinv[d];
        g_edge[pos] = make_int2(s, __float_as_int(nm));
    }
}

// ---------------- fused BN+ReLU on load ----------------
__device__ __forceinline__ float4 bnrelu4(float4 v, int c4) {
    float4 sc = ((const float4*)g_scale)[c4];
    float4 sh = ((const float4*)g_shift)[c4];
    v.x = fmaxf(fmaf(v.x, sc.x, sh.x), 0.0f);
    v.y = fmaxf(fmaf(v.y, sc.y, sh.y), 0.0f);
    v.z = fmaxf(fmaf(v.z, sc.z, sh.z), 0.0f);
    v.w = fmaxf(fmaf(v.w, sc.w, sh.w), 0.0f);
    return v;
}

// ---------------- tensor-core GEMM 128x128 ----------------
#define SKH 136
#define GEMM_SMEM (128 * SKH * 4)   // 69632 B

template <bool FUSE_BN>
__global__ void __launch_bounds__(256) gemm128t(const float* __restrict__ Af,
                                                const __half* __restrict__ Ah,
                                                const float* __restrict__ W,
                                                __half* __restrict__ C, int n) {
    extern __shared__ char smem[];
    __half* sA = (__half*)smem;              // [128][SKH]
    __half* sB = sA + 128 * SKH;             // [128][SKH]
    float*  sC = (float*)smem;               // [128][SKH] (reused)

    int tid = threadIdx.x;
    int row0 = blockIdx.x * 128;

    // W load: independent of producer output
    const float4* W4 = (const float4*)W;
    #pragma unroll
    for (int i = tid; i < 4096; i += 256) {
        int r = i >> 5, c4 = i & 31;
        float4 v = W4[i];
        __half2* dst = (__half2*)(sB + r * SKH + c4 * 4);
        dst[0] = __floats2half2_rn(v.x, v.y);
        dst[1] = __floats2half2_rn(v.z, v.w);
    }

    cudaGridDependencySynchronize();

    if (FUSE_BN) {
        const uint2* A2 = (const uint2*)(Ah + (size_t)row0 * D);
        #pragma unroll
        for (int i = tid; i < 4096; i += 256) {
            int r = i >> 5, c4 = i & 31;
            float4 v = make_float4(0.f, 0.f, 0.f, 0.f);
            if (row0 + r < n) {
                uint2 rv = A2[i];
                float2 f0 = __half22float2(*reinterpret_cast<__half2*>(&rv.x));
                float2 f1 = __half22float2(*reinterpret_cast<__half2*>(&rv.y));
                v = bnrelu4(make_float4(f0.x, f0.y, f1.x, f1.y), c4);
            }
            __half2* dst = (__half2*)(sA + r * SKH + c4 * 4);
            dst[0] = __floats2half2_rn(v.x, v.y);
            dst[1] = __floats2half2_rn(v.z, v.w);
        }
    } else {
        const float4* A4 = (const float4*)Af + (size_t)row0 * 32;
        #pragma unroll
        for (int i = tid; i < 4096; i += 256) {
            int r = i >> 5, c4 = i & 31;
            float4 v = make_float4(0.f, 0.f, 0.f, 0.f);
            if (row0 + r < n) v = A4[i];
            __half2* dst = (__half2*)(sA + r * SKH + c4 * 4);
            dst[0] = __floats2half2_rn(v.x, v.y);
            dst[1] = __floats2half2_rn(v.z, v.w);
        }
    }
    __syncthreads();

    int warp = tid >> 5;
    int wr = warp & 3;
    int wc = warp >> 2;

    wmma::fragment<wmma::accumulator, 16, 16, 16, float> acc[2][4];
    #pragma unroll
    for (int i = 0; i < 2; i++)
        #pragma unroll
        for (int j = 0; j < 4; j++) wmma::fill_fragment(acc[i][j], 0.0f);

    #pragma unroll
    for (int ks = 0; ks < 8; ks++) {
        wmma::fragment<wmma::matrix_a, 16, 16, 16, __half, wmma::row_major> af[2];
        wmma::load_matrix_sync(af[0], sA + (wr * 32 +  0) * SKH + ks * 16, SKH);
        wmma::load_matrix_sync(af[1], sA + (wr * 32 + 16) * SKH + ks * 16, SKH);
        wmma::fragment<wmma::matrix_b, 16, 16, 16, __half, wmma::row_major> bf[4];
        #pragma unroll
        for (int j = 0; j < 4; j++)
            wmma::load_matrix_sync(bf[j], sB + (ks * 16) * SKH + wc * 64 + j * 16, SKH);
        #pragma unroll
        for (int i = 0; i < 2; i++)
            #pragma unroll
            for (int j = 0; j < 4; j++)
                wmma::mma_sync(acc[i][j], af[i], bf[j], acc[i][j]);
    }
    __syncthreads();

    #pragma unroll
    for (int i = 0; i < 2; i++)
        #pragma unroll
        for (int j = 0; j < 4; j++)
            wmma::store_matrix_sync(sC + (wr * 32 + i * 16) * SKH + wc * 64 + j * 16,
                                    acc[i][j], SKH, wmma::mem_row_major);
    __syncthreads();

    #pragma unroll
    for (int i = tid; i < 4096; i += 256) {
        int r = i >> 5, c4 = i & 31;
        if (row0 + r < n) {
            float4 v = *(const float4*)(sC + r * SKH + c4 * 4);
            uint2 o;
            __half2 hh;
            hh = __floats2half2_rn(v.x, v.y);
            o.x = *reinterpret_cast<unsigned*>(&hh);
            hh = __floats2half2_rn(v.z, v.w);
            o.y = *reinterpret_cast<unsigned*>(&hh);
            ((uint2*)(C + (size_t)(row0 + r) * D))[c4] = o;
        }
    }
}

// ---------------- tensor-core GEMM 128->40 (fp16 in + BN+ReLU, fp16 out) ---------
#define SB40 48
#define GEMM40_SMEM (128 * SKH * 2 + 128 * SB40 * 2)

__global__ void __launch_bounds__(256) gemm40t(const __half* __restrict__ A,
                                               const float* __restrict__ W,
                                               __half* __restrict__ C, int n) {
    extern __shared__ char smem[];
    __half* sA = (__half*)smem;              // [128][SKH]
    __half* sB = sA + 128 * SKH;             // [128][SB40]
    float*  sC = (float*)smem;               // [128][SB40] staging

    int tid = threadIdx.x;
    int row0 = blockIdx.x * 128;

    #pragma unroll
    for (int i = tid; i < 128 * SB40; i += 256) {
        int r = i / SB40, c = i % SB40;
        float v = (c < DOUT) ? W[r * DOUT + c] : 0.f;
        sB[r * SB40 + c] = __float2half_rn(v);
    }

    cudaGridDependencySynchronize();

    const uint2* A2 = (const uint2*)(A + (size_t)row0 * D);
    #pragma unroll
    for (int i = tid; i < 4096; i += 256) {
        int r = i >> 5, c4 = i & 31;
        float4 v = make_float4(0.f, 0.f, 0.f, 0.f);
        if (row0 + r < n) {
            uint2 rv = A2[i];
            float2 f0 = __half22float2(*reinterpret_cast<__half2*>(&rv.x));
            float2 f1 = __half22float2(*reinterpret_cast<__half2*>(&rv.y));
            v = bnrelu4(make_float4(f0.x, f0.y, f1.x, f1.y), c4);
        }
        __half2* dst = (__half2*)(sA + r * SKH + c4 * 4);
        dst[0] = __floats2half2_rn(v.x, v.y);
        dst[1] = __floats2half2_rn(v.z, v.w);
    }
    __syncthreads();

    int warp = tid >> 5;

    wmma::fragment<wmma::accumulator, 16, 16, 16, float> acc[3];
    #pragma unroll
    for (int j = 0; j < 3; j++) wmma::fill_fragment(acc[j], 0.0f);

    #pragma unroll
    for (int ks = 0; ks < 8; ks++) {
        wmma::fragment<wmma::matrix_a, 16, 16, 16, __half, wmma::row_major> af;
        wmma::load_matrix_sync(af, sA + (warp * 16) * SKH + ks * 16, SKH);
        #pragma unroll
        for (int j = 0; j < 3; j++) {
            wmma::fragment<wmma::matrix_b, 16, 16, 16, __half, wmma::row_major> bf;
            wmma::load_matrix_sync(bf, sB + (ks * 16) * SB40 + j * 16, SB40);
            wmma::mma_sync(acc[j], af, bf, acc[j]);
        }
    }
    __syncthreads();

    #pragma unroll
    for (int j = 0; j < 3; j++)
        wmma::store_matrix_sync(sC + (warp * 16) * SB40 + j * 16, acc[j],
                                SB40, wmma::mem_row_major);
    __syncthreads();

    #pragma unroll
    for (int i = tid; i < 128 * 20; i += 256) {
        int r = i / 20, cu = i % 20;
        if (row0 + r < n) {
            float2 v = *(const float2*)(sC + r * SB40 + cu * 2);
            __half2 hh = __floats2half2_rn(v.x, v.y);
            ((unsigned*)(C + (size_t)(row0 + r) * DOUT))[cu] =
                *reinterpret_cast<unsigned*>(&hh);
        }
    }
}

// ---------------- CSR gather + BN stats + fused finalize (last block) ------------
__global__ void gather128_bn(const __half* __restrict__ xw, const float* __restrict__ b,
                             __half* __restrict__ h, int n,
                             const float* __restrict__ g, const float* __restrict__ be,
                             float fn) {
    __shared__ float sbs[128], sbss[128];
    __shared__ int sIsLast;
    int tid = threadIdx.x;
    if (tid < 128) { sbs[tid] = 0.f; sbss[tid] = 0.f; }

    cudaGridDependencySynchronize();
    __syncthreads();

    int lane   = tid & 31;
    int warp   = (blockIdx.x * blockDim.x + tid) >> 5;
    int nwarps = (gridDim.x * blockDim.x) >> 5;

    float4 ps  = make_float4(0.f, 0.f, 0.f, 0.f);
    float4 pss = make_float4(0.f, 0.f, 0.f, 0.f);
    float4 bb  = ((const float4*)b)[lane];

    for (int v = warp; v < n; v += nwarps) {
        int beg = g_rowptr[v], end = g_rowptr[v + 1];
        float4 acc  = make_float4(0.f, 0.f, 0.f, 0.f);
        float4 acc2 = make_float4(0.f, 0.f, 0.f, 0.f);
        int i = beg;
        for (; i + 2 <= end; i += 2) {
            int2 e0 = g_edge[i], e1 = g_edge[i + 1];
            float w0 = __int_as_float(e0.y), w1 = __int_as_float(e1.y);
            uint2 r0 = ((const uint2*)(xw + (size_t)e0.x * D))[lane];
            uint2 r1 = ((const uint2*)(xw + (size_t)e1.x * D))[lane];
            float2 a0 = __half22float2(*reinterpret_cast<__half2*>(&r0.x));
            float2 a1 = __half22float2(*reinterpret_cast<__half2*>(&r0.y));
            float2 b0f = __half22float2(*reinterpret_cast<__half2*>(&r1.x));
            float2 b1f = __half22float2(*reinterpret_cast<__half2*>(&r1.y));
            acc.x  = fmaf(a0.x,  w0, acc.x);
            acc.y  = fmaf(a0.y,  w0, acc.y);
            acc.z  = fmaf(a1.x,  w0, acc.z);
            acc.w  = fmaf(a1.y,  w0, acc.w);
            acc2.x = fmaf(b0f.x, w1, acc2.x);
            acc2.y = fmaf(b0f.y, w1, acc2.y);
            acc2.z = fmaf(b1f.x, w1, acc2.z);
            acc2.w = fmaf(b1f.y, w1, acc2.w);
        }
        if (i < end) {
            int2 e0 = g_edge[i];
            float w0 = __int_as_float(e0.y);
            uint2 r0 = ((const uint2*)(xw + (size_t)e0.x * D))[lane];
            float2 a0 = __half22float2(*reinterpret_cast<__half2*>(&r0.x));
            float2 a1 = __half22float2(*reinterpret_cast<__half2*>(&r0.y));
            acc.x = fmaf(a0.x, w0, acc.x);
            acc.y = fmaf(a0.y, w0, acc.y);
            acc.z = fmaf(a1.x, w0, acc.z);
            acc.w = fmaf(a1.y, w0, acc.w);
        }
        acc.x += acc2.x; acc.y += acc2.y; acc.z += acc2.z; acc.w += acc2.w;

        float di  = g_dinv[v];
        float di2 = di * di;
        uint2 rv = ((const uint2*)(xw + (size_t)v * D))[lane];
        float2 f0 = __half22float2(*reinterpret_cast<__half2*>(&rv.x));
        float2 f1 = __half22float2(*reinterpret_cast<__half2*>(&rv.y));
        acc.x = fmaf(f0.x, di2, acc.x) + bb.x;
        acc.y = fmaf(f0.y, di2, acc.y) + bb.y;
        acc.z = fmaf(f1.x, di2, acc.z) + bb.z;
        acc.w = fmaf(f1.y, di2, acc.w) + bb.w;

        uint2 o;
        __half2 hh;
        hh = __floats2half2_rn(acc.x, acc.y);
        o.x = *reinterpret_cast<unsigned*>(&hh);
        hh = __floats2half2_rn(acc.z, acc.w);
        o.y = *reinterpret_cast<unsigned*>(&hh);
        ((uint2*)(h + (size_t)v * D))[lane] = o;

        ps.x += acc.x; ps.y += acc.y; ps.z += acc.z; ps.w += acc.w;
        pss.x = fmaf(acc.x, acc.x, pss.x);
        pss.y = fmaf(acc.y, acc.y, pss.y);
        pss.z = fmaf(acc.z, acc.z, pss.z);
        pss.w = fmaf(acc.w, acc.w, pss.w);
    }

    atomicAdd(&sbs[lane * 4 + 0], ps.x);
    atomicAdd(&sbs[lane * 4 + 1], ps.y);
    atomicAdd(&sbs[lane * 4 + 2], ps.z);
    atomicAdd(&sbs[lane * 4 + 3], ps.w);
    atomicAdd(&sbss[lane * 4 + 0], pss.x);
    atomicAdd(&sbss[lane * 4 + 1], pss.y);
    atomicAdd(&sbss[lane * 4 + 2], pss.z);
    atomicAdd(&sbss[lane * 4 + 3], pss.w);
    __syncthreads();
    if (tid < 128) {
        atomicAdd(&g_bnsum[tid],   sbs[tid]);
        atomicAdd(&g_bnsumsq[tid], sbss[tid]);
    }

    __threadfence();
    if (tid == 0) {
        int prev = atomicAdd(&g_done, 1);
        sIsLast = (prev == gridDim.x - 1);
    }
    __syncthreads();
    if (sIsLast && tid < 128) {
        float mean = g_bnsum[tid] / fn;
        float var  = g_bnsumsq[tid] / fn - mean * mean;
        float sc   = g[tid] * rsqrtf(var + 1e-5f);
        g_scale[tid] = sc;
        g_shift[tid] = be[tid] - mean * sc;
        g_bnsum[tid] = 0.f;
        g_bnsumsq[tid] = 0.f;
        if (tid == 0) g_done = 0;
    }
}

// ---------------- CSR gather (D=40, 16-lane groups, 2 nodes/warp) + log_softmax --
__global__ void gather40_softmax(const __half* __restrict__ xw2,
                                 const float* __restrict__ b2, float* __restrict__ out,
                                 int n) {
    cudaGridDependencySynchronize();

    int tid  = threadIdx.x;
    int l    = tid & 15;
    int grp  = (blockIdx.x * blockDim.x + tid) >> 4;
    int ngrp = (gridDim.x * blockDim.x) >> 4;
    unsigned mask = 0xFFFFu << ((tid & 16));

    for (int v = grp; v < n; v += ngrp) {
        int beg = g_rowptr[v], end = g_rowptr[v + 1];
        float4 acc  = make_float4(0.f, 0.f, 0.f, 0.f);
        float4 acc2 = make_float4(0.f, 0.f, 0.f, 0.f);
        if (l < 10) {
            int i = beg;
            for (; i + 2 <= end; i += 2) {
                int2 e0 = g_edge[i], e1 = g_edge[i + 1];
                float w0 = __int_as_float(e0.y), w1 = __int_as_float(e1.y);
                uint2 r0 = ((const uint2*)(xw2 + (size_t)e0.x * DOUT))[l];
                uint2 r1 = ((const uint2*)(xw2 + (size_t)e1.x * DOUT))[l];
                float2 a0 = __half22float2(*reinterpret_cast<__half2*>(&r0.x));
                float2 a1 = __half22float2(*reinterpret_cast<__half2*>(&r0.y));
                float2 c0 = __half22float2(*reinterpret_cast<__half2*>(&r1.x));
                float2 c1 = __half22float2(*reinterpret_cast<__half2*>(&r1.y));
                acc.x  = fmaf(a0.x, w0, acc.x);
                acc.y  = fmaf(a0.y, w0, acc.y);
                acc.z  = fmaf(a1.x, w0, acc.z);
                acc.w  = fmaf(a1.y, w0, acc.w);
                acc2.x = fmaf(c0.x, w1, acc2.x);
                acc2.y = fmaf(c0.y, w1, acc2.y);
                acc2.z = fmaf(c1.x, w1, acc2.z);
                acc2.w = fmaf(c1.y, w1, acc2.w);
            }
            if (i < end) {
                int2 e0 = g_edge[i];
                float w0 = __int_as_float(e0.y);
                uint2 r0 = ((const uint2*)(xw2 + (size_t)e0.x * DOUT))[l];
                float2 a0 = __half22float2(*reinterpret_cast<__half2*>(&r0.x));
                float2 a1 = __half22float2(*reinterpret_cast<__half2*>(&r0.y));
                acc.x = fmaf(a0.x, w0, acc.x);
                acc.y = fmaf(a0.y, w0, acc.y);
                acc.z = fmaf(a1.x, w0, acc.z);
                acc.w = fmaf(a1.y, w0, acc.w);
            }
            acc.x += acc2.x; acc.y += acc2.y; acc.z += acc2.z; acc.w += acc2.w;

            float di  = g_dinv[v];
            float di2 = di * di;
            uint2 rv = ((const uint2*)(xw2 + (size_t)v * DOUT))[l];
            float2 f0 = __half22float2(*reinterpret_cast<__half2*>(&rv.x));
            float2 f1 = __half22float2(*reinterpret_cast<__half2*>(&rv.y));
            float4 bb = ((const float4*)b2)[l];
            acc.x = fmaf(f0.x, di2, acc.x) + bb.x;
            acc.y = fmaf(f0.y, di2, acc.y) + bb.y;
            acc.z = fmaf(f1.x, di2, acc.z) + bb.z;
            acc.w = fmaf(f1.y, di2, acc.w) + bb.w;
        }
        float m = (l < 10)
                ? fmaxf(fmaxf(acc.x, acc.y), fmaxf(acc.z, acc.w)) : -1e30f;
        #pragma unroll
        for (int o = 8; o; o >>= 1) m = fmaxf(m, __shfl_xor_sync(mask, m, o, 16));
        float s = (l < 10)
                ? (expf(acc.x - m) + expf(acc.y - m) + expf(acc.z - m) + expf(acc.w - m))
                : 0.f;
        #pragma unroll
        for (int o = 8; o; o >>= 1) s += __shfl_xor_sync(mask, s, o, 16);
        float lse = m + logf(s);
        if (l < 10)
            ((float4*)(out + (size_t)v * DOUT))[l] =
                make_float4(acc.x - lse, acc.y - lse, acc.z - lse, acc.w - lse);
    }
}

// ---------------- launch ----------------
extern "C" void kernel_launch(void* const* d_in, const int* in_sizes, int n_in,
                              void* d_out, int out_size) {
    const float* x   = (const float*)d_in[0];
    const void*  ei  = d_in[1];
    const float* ew  = (const float*)d_in[2];
    const float* W0  = (const float*)d_in[3];
    const float* b0  = (const float*)d_in[4];
    const float* g0  = (const float*)d_in[5];
    const float* be0 = (const float*)d_in[6];
    const float* W1  = (const float*)d_in[7];
    const float* b1  = (const float*)d_in[8];
    const float* g1  = (const float*)d_in[9];
    const float* be1 = (const float*)d_in[10];
    const float* W2  = (const float*)d_in[11];
    const float* b2  = (const float*)d_in[12];

    int n = in_sizes[0] / D;
    int E = in_sizes[2];
    int twoE = 2 * E;
    float fn = (float)n;

    cudaFuncSetAttribute(gemm128t<false>, cudaFuncAttributeMaxDynamicSharedMemorySize, GEMM_SMEM);
    cudaFuncSetAttribute(gemm128t<true>,  cudaFuncAttributeMaxDynamicSharedMemorySize, GEMM_SMEM);
    cudaFuncSetAttribute(gemm40t, cudaFuncAttributeMaxDynamicSharedMemorySize, GEMM40_SMEM);

    void *p_nz, *p_xw, *p_h, *p_xw2;
    cudaGetSymbolAddress(&p_nz, g_nz);
    cudaGetSymbolAddress(&p_xw, g_xw);
    cudaGetSymbolAddress(&p_h,  g_h);
    cudaGetSymbolAddress(&p_xw2, g_xw2);
    __half* xw  = (__half*)p_xw;
    __half* h   = (__half*)p_h;
    __half* xw2 = (__half*)p_xw2;

    const int T = 256;
    int nb_scan = cdiv(n, 512);
    int gather_blocks = 1184;

    cudaLaunchAttribute pdlAttr[1];
    pdlAttr[0].id = cudaLaunchAttributeProgrammaticStreamSerialization;
    pdlAttr[0].val.programmaticStreamSerializationAllowed = 1;

    cudaStream_t s2;
    cudaEvent_t evF, evJ;
    cudaStreamCreateWithFlags(&s2, cudaStreamNonBlocking);
    cudaEventCreateWithFlags(&evF, cudaEventDisableTiming);
    cudaEventCreateWithFlags(&evJ, cudaEventDisableTiming);

    cudaEventRecord(evF, 0);
    cudaStreamWaitEvent(s2, evF, 0);

    // ---- branch A (s2): one memset + detect + CSR build (PDL chained) ----
    cudaMemsetAsync(p_nz, 0, sizeof(NZ), s2);
    detect_kernel<<<1, 32, 0, s2>>>((const unsigned*)ei, twoE);
    {
        cudaLaunchConfig_t cfg = {};
        cfg.gridDim = dim3(cdiv(E, T)); cfg.blockDim = dim3(T);
        cfg.stream = s2; cfg.attrs = pdlAttr; cfg.numAttrs = 1;
        cudaLaunchKernelEx(&cfg, deg_kernel, (const void*)ei, ew, E);
    }
    {
        cudaLaunchConfig_t cfg = {};
        cfg.gridDim = dim3(nb_scan); cfg.blockDim = dim3(512);
        cfg.stream = s2; cfg.attrs = pdlAttr; cfg.numAttrs = 1;
        cudaLaunchKernelEx(&cfg, scan1, n, nb_scan);
    }
    {
        cudaLaunchConfig_t cfg = {};
        cfg.gridDim = dim3(cdiv(n, T)); cfg.blockDim = dim3(T);
        cfg.stream = s2; cfg.attrs = pdlAttr; cfg.numAttrs = 1;
        cudaLaunchKernelEx(&cfg, scan3, n, E);
    }
    {
        cudaLaunchConfig_t cfg = {};
        cfg.gridDim = dim3(cdiv(E, T)); cfg.blockDim = dim3(T);
        cfg.stream = s2; cfg.attrs = pdlAttr; cfg.numAttrs = 1;
        cudaLaunchKernelEx(&cfg, fill_kernel, (const void*)ei, ew, E);
    }
    cudaEventRecord(evJ, s2);

    // ---- branch B (stream 0): layer-0 GEMM (tensor cores) ----
    gemm128t<false><<<cdiv(n, 128), T, GEMM_SMEM>>>(x, (const __half*)0, W0, xw, n);

    cudaStreamWaitEvent(0, evJ, 0);

    // ---- layer 0 aggregate (plain launch; follows cross-stream join) ----
    gather128_bn<<<gather_blocks, T>>>(xw, b0, h, n, g0, be0, fn);

    // ---- layer 1 (PDL) ----
    {
        cudaLaunchConfig_t cfg = {};
        cfg.gridDim = dim3(cdiv(n, 128)); cfg.blockDim = dim3(T);
        cfg.dynamicSmemBytes = GEMM_SMEM;
        cfg.stream = 0; cfg.attrs = pdlAttr; cfg.numAttrs = 1;
        cudaLaunchKernelEx(&cfg, gemm128t<true>,
                           (const float*)0, (const __half*)h, W1, xw, n);
    }
    {
        cudaLaunchConfig_t cfg = {};
        cfg.gridDim = dim3(gather_blocks); cfg.blockDim = dim3(T);
        cfg.stream = 0; cfg.attrs = pdlAttr; cfg.numAttrs = 1;
        cudaLaunchKernelEx(&cfg, gather128_bn,
                           (const __half*)xw, b1, h, n, g1, be1, fn);
    }

    // ---- layer 2 + log_softmax (PDL) ----
    {
        cudaLaunchConfig_t cfg = {};
        cfg.gridDim = dim3(cdiv(n, 128)); cfg.blockDim = dim3(T);
        cfg.dynamicSmemBytes = GEMM40_SMEM;
        cfg.stream = 0; cfg.attrs = pdlAttr; cfg.numAttrs = 1;
        cudaLaunchKernelEx(&cfg, gemm40t, (const __half*)h, W2, xw2, n);
    }
    {
        cudaLaunchConfig_t cfg = {};
        cfg.gridDim = dim3(gather_blocks); cfg.blockDim = dim3(T);
        cfg.stream = 0; cfg.attrs = pdlAttr; cfg.numAttrs = 1;
        cudaLaunchKernelEx(&cfg, gather40_softmax,
                           (const __half*)xw2, b2, (float*)d_out, n);
    }

    cudaEventDestroy(evF);
    cudaEventDestroy(evJ);
    cudaStreamDestroy(s2);
}